// round 8
// baseline (speedup 1.0000x reference)
#include <cuda_runtime.h>
#include <math.h>
#include <stdint.h>

// Problem constants
#define BB 4
#define LL 2048
#define DM 1024
#define NH 16
#define DH 64
#define MM (BB*LL)          // 8192 rows
#define ELEMS (MM*DM)       // 8388608 floats per tensor
#define WELEMS (DM*DM)      // 1048576

// Scratch: xn,q,k,v,attn (5x) + 4 tf32 transposed weights + rope table
__device__ float g_scratch[5 * (size_t)ELEMS + 4 * (size_t)WELEMS + 131072];

#define CVT_TF32(u, f) asm("cvt.rna.tf32.f32 %0, %1;" : "=r"(u) : "f"(f))
__device__ __forceinline__ uint32_t fau(float f) { return __float_as_uint(f); }
__device__ __forceinline__ float uaf(uint32_t u) { return __uint_as_float(u); }

__device__ __forceinline__ void mma_tf32(float c[4],
                                         const uint32_t a[4],
                                         const uint32_t b[2]) {
    asm volatile(
        "mma.sync.aligned.m16n8k8.row.col.f32.tf32.tf32.f32 "
        "{%0,%1,%2,%3}, {%4,%5,%6,%7}, {%8,%9}, {%0,%1,%2,%3};\n"
        : "+f"(c[0]), "+f"(c[1]), "+f"(c[2]), "+f"(c[3])
        : "r"(a[0]), "r"(a[1]), "r"(a[2]), "r"(a[3]),
          "r"(b[0]), "r"(b[1]));
}

__device__ __forceinline__ void ldmx4(uint32_t& r0, uint32_t& r1,
                                      uint32_t& r2, uint32_t& r3,
                                      uint32_t addr) {
    asm volatile("ldmatrix.sync.aligned.m8n8.x4.shared.b16 {%0,%1,%2,%3}, [%4];"
                 : "=r"(r0), "=r"(r1), "=r"(r2), "=r"(r3) : "r"(addr));
}

#define CP_ASYNC16(dst, src) \
    asm volatile("cp.async.cg.shared.global [%0], [%1], 16;\n" \
                 :: "r"(dst), "l"(src) : "memory")
#define CP_COMMIT() asm volatile("cp.async.commit_group;\n" ::: "memory")
#define CP_WAIT1()  asm volatile("cp.async.wait_group 1;\n" ::: "memory")

// ---------------------------------------------------------------------------
// Weight prep: fp32 -> tf32 round + transpose (Wt[n][k] = round(W[k][n]))
// ---------------------------------------------------------------------------
__global__ __launch_bounds__(256) void cvtwt_kernel(const float* __restrict__ src,
                                                    float* __restrict__ dst) {
    __shared__ float tile[32][33];
    const int tx = threadIdx.x, ty = threadIdx.y;
    const int bx = blockIdx.x, by = blockIdx.y;
#pragma unroll
    for (int i = 0; i < 4; i++) {
        const int k = by * 32 + ty + i * 8;
        float v = src[(size_t)k * DM + bx * 32 + tx];
        uint32_t u; CVT_TF32(u, v);
        tile[ty + i * 8][tx] = uaf(u);
    }
    __syncthreads();
#pragma unroll
    for (int i = 0; i < 4; i++) {
        const int n = bx * 32 + ty + i * 8;
        dst[(size_t)n * DM + by * 32 + tx] = tile[tx][ty + i * 8];
    }
}

// ---------------------------------------------------------------------------
// RoPE cos/sin table
// ---------------------------------------------------------------------------
__global__ __launch_bounds__(256) void rope_table_kernel(float2* __restrict__ t) {
    const int idx = blockIdx.x * 256 + threadIdx.x;   // 65536
    const int l = idx >> 5, p = idx & 31;
    const float inv = exp2f((float)p * (-2.0f / 64.0f) * 13.2877123795494f);
    float s, c;
    sincosf((float)l * inv, &s, &c);
    t[idx] = make_float2(c, s);
}

// ---------------------------------------------------------------------------
// LayerNorm -> tf32-rounded output
// ---------------------------------------------------------------------------
__global__ __launch_bounds__(256) void ln_kernel(const float* __restrict__ x,
                                                 const float* __restrict__ gamma,
                                                 const float* __restrict__ beta,
                                                 float* __restrict__ xn) {
    const int row = blockIdx.x;
    const int t = threadIdx.x;
    const float4 v = ((const float4*)(x + (size_t)row * DM))[t];
    __shared__ float red[8];

    float s = v.x + v.y + v.z + v.w;
#pragma unroll
    for (int o = 16; o > 0; o >>= 1) s += __shfl_xor_sync(0xffffffffu, s, o);
    if ((t & 31) == 0) red[t >> 5] = s;
    __syncthreads();
    float mean = (red[0]+red[1]+red[2]+red[3]+red[4]+red[5]+red[6]+red[7]) * (1.0f/DM);

    float dx = v.x-mean, dy = v.y-mean, dz = v.z-mean, dw = v.w-mean;
    float q = dx*dx + dy*dy + dz*dz + dw*dw;
#pragma unroll
    for (int o = 16; o > 0; o >>= 1) q += __shfl_xor_sync(0xffffffffu, q, o);
    __syncthreads();
    if ((t & 31) == 0) red[t >> 5] = q;
    __syncthreads();
    float var = (red[0]+red[1]+red[2]+red[3]+red[4]+red[5]+red[6]+red[7]) * (1.0f/DM);
    float rs = rsqrtf(var + 1e-5f);

    const float4 g4 = ((const float4*)gamma)[t];
    const float4 b4 = ((const float4*)beta)[t];
    uint32_t u0, u1, u2, u3;
    CVT_TF32(u0, dx*rs*g4.x + b4.x);
    CVT_TF32(u1, dy*rs*g4.y + b4.y);
    CVT_TF32(u2, dz*rs*g4.z + b4.z);
    CVT_TF32(u3, dw*rs*g4.w + b4.w);
    ((float4*)(xn + (size_t)row * DM))[t] =
        make_float4(uaf(u0), uaf(u1), uaf(u2), uaf(u3));
}

// ---------------------------------------------------------------------------
// TF32 GEMM: 128x128x16 block, 4 warps (2Mx2N), 64x64 warp tile.
// cp.async 3-stage + ldmatrix. A[m][k], Wt[n][k] both tf32-rounded.
// Smem: As[3][128][20], Bs[3][128][20]
// ---------------------------------------------------------------------------
#define AS_STG 2560          // 128*20 floats
#define BS_BASE (3*AS_STG)
#define GSMEM (6*AS_STG*4)   // 61440 bytes

template <bool RESID, bool ROPE, bool CVTOUT>
__global__ __launch_bounds__(128) void tgemm3(const float* __restrict__ A,
                                              const float* __restrict__ Wt,
                                              const float* __restrict__ bias,
                                              const float* __restrict__ resid,
                                              const float2* __restrict__ rtab,
                                              float oscale,
                                              float* __restrict__ C) {
    constexpr int NK = 64;   // 1024/16
    extern __shared__ float sm2[];

    const int tid   = threadIdx.x;
    const int lane  = tid & 31;
    const int warp  = tid >> 5;
    const int warpM = warp >> 1;     // 0..1
    const int warpN = warp & 1;      // 0..1
    const int g  = lane >> 2;
    const int l4 = lane & 3;
    const int brow = blockIdx.y;
    const int bcol = blockIdx.x;

    const float* Ab = A  + (size_t)brow * 128 * 1024;
    const float* Bb = Wt + (size_t)bcol * 128 * 1024;

    const uint32_t smbase = (uint32_t)__cvta_generic_to_shared(sm2);

    // async copy: each thread owns one row (A and B), 4 x 16B chunks each
    auto issue = [&](int stage, int k0) {
        const uint32_t da = smbase + (stage * AS_STG + tid * 20) * 4;
        const float* sa = Ab + (size_t)tid * 1024 + k0;
        const uint32_t db = smbase + ((BS_BASE + stage * AS_STG) + tid * 20) * 4;
        const float* sb = Bb + (size_t)tid * 1024 + k0;
#pragma unroll
        for (int c = 0; c < 4; c++) {
            CP_ASYNC16(da + c * 16, sa + c * 4);
            CP_ASYNC16(db + c * 16, sb + c * 4);
        }
    };

    float acc[4][8][4];
#pragma unroll
    for (int i = 0; i < 4; i++)
#pragma unroll
        for (int j = 0; j < 8; j++)
#pragma unroll
            for (int q = 0; q < 4; q++) acc[i][j][q] = 0.f;

    const uint32_t aoff = ((warpM * 64 + (lane & 15)) * 20) * 4 + (lane >> 4) * 16;
    const uint32_t boff = ((warpN * 64 + (lane & 15)) * 20) * 4 + (lane >> 4) * 16;

    auto compute = [&](int stage) {
        const uint32_t abase = smbase + stage * AS_STG * 4 + aoff;
        const uint32_t bbase = smbase + (BS_BASE + stage * AS_STG) * 4 + boff;
#pragma unroll
        for (int k8 = 0; k8 < 16; k8 += 8) {
            uint32_t af[4][4];
            uint32_t bf[8][2];
#pragma unroll
            for (int i = 0; i < 4; i++)
                ldmx4(af[i][0], af[i][1], af[i][2], af[i][3],
                      abase + i * (16 * 20 * 4) + k8 * 4);
#pragma unroll
            for (int jj = 0; jj < 4; jj++)
                ldmx4(bf[2*jj][0], bf[2*jj+1][0], bf[2*jj][1], bf[2*jj+1][1],
                      bbase + jj * (16 * 20 * 4) + k8 * 4);
#pragma unroll
            for (int i = 0; i < 4; i++)
#pragma unroll
                for (int j = 0; j < 8; j++)
                    mma_tf32(acc[i][j], af[i], bf[j]);
        }
    };

    issue(0, 0);  CP_COMMIT();
    issue(1, 16); CP_COMMIT();

    for (int kt = 0; kt < NK; kt++) {
        CP_WAIT1();
        __syncthreads();
        if (kt + 2 < NK) issue((kt + 2) % 3, (kt + 2) * 16);
        CP_COMMIT();
        compute(kt % 3);
    }

    // ---- epilogue ----
#pragma unroll
    for (int i = 0; i < 4; i++) {
        const int r0 = brow * 128 + warpM * 64 + i * 16 + g;
#pragma unroll
        for (int j = 0; j < 8; j++) {
            const int cc = bcol * 128 + warpN * 64 + j * 8 + (l4 << 1);
            const float bx = bias[cc], by = bias[cc + 1];
            float v0x = acc[i][j][0] + bx;
            float v0y = acc[i][j][1] + by;
            float v1x = acc[i][j][2] + bx;
            float v1y = acc[i][j][3] + by;
            if (ROPE) {
                const int p  = (cc & 63) >> 1;
                const int l0 = r0 & (LL - 1);
                const float2 cs0 = rtab[l0 * 32 + p];
                const float2 cs1 = rtab[(l0 + 8) * 32 + p];
                float t;
                t   = v0x * cs0.x - v0y * cs0.y;
                v0y = v0x * cs0.y + v0y * cs0.x;
                v0x = t;
                t   = v1x * cs1.x - v1y * cs1.y;
                v1y = v1x * cs1.y + v1y * cs1.x;
                v1x = t;
            }
            if (RESID) {
                const float2 r0v = *(const float2*)(resid + (size_t)r0 * 1024 + cc);
                const float2 r1v = *(const float2*)(resid + (size_t)(r0 + 8) * 1024 + cc);
                v0x += r0v.x; v0y += r0v.y;
                v1x += r1v.x; v1y += r1v.y;
            }
            if (CVTOUT) {
                uint32_t u0, u1, u2, u3;
                CVT_TF32(u0, v0x * oscale);
                CVT_TF32(u1, v0y * oscale);
                CVT_TF32(u2, v1x * oscale);
                CVT_TF32(u3, v1y * oscale);
                v0x = uaf(u0); v0y = uaf(u1); v1x = uaf(u2); v1y = uaf(u3);
            }
            *(float2*)(C + (size_t)r0 * 1024 + cc)       = make_float2(v0x, v0y);
            *(float2*)(C + (size_t)(r0 + 8) * 1024 + cc) = make_float2(v1x, v1y);
        }
    }
}

// ---------------------------------------------------------------------------
// Tensor-core flash attention (causal, TF32 mma).
// Inputs q (pre-scaled, tf32), k, v (tf32): plain LDG+STS staging.
// ---------------------------------------------------------------------------
#define AST 68

__global__ __launch_bounds__(128) void attn_tc_kernel(const float* __restrict__ qg,
                                                      const float* __restrict__ kg,
                                                      const float* __restrict__ vg,
                                                      float* __restrict__ og) {
    extern __shared__ float sm[];
    float* Qs = sm;
    float* Ks = sm + 128 * AST;
    float* Vs = Ks + 64 * AST;

    const int bh = blockIdx.y;
    const int b = bh >> 4, h = bh & 15;
    const int qt = (int)gridDim.x - 1 - (int)blockIdx.x;
    const int qbase = qt * 128;
    const int tid  = threadIdx.x;
    const int lane = tid & 31;
    const int warp = tid >> 5;
    const int g  = lane >> 2;
    const int l4 = lane & 3;

    // ---- Q tile: 128 rows x 64 d ----
    for (int i = tid; i < 128 * 16; i += 128) {
        const int row = i >> 4, c4 = i & 15;
        float4 v = *(const float4*)(qg + (size_t)(b * LL + qbase + row) * 1024 + h * 64 + c4 * 4);
        *(float4*)(Qs + row * AST + c4 * 4) = v;
    }

    float s[2][8][4];
    float o[2][8][4];
#pragma unroll
    for (int mt = 0; mt < 2; mt++)
#pragma unroll
        for (int n = 0; n < 8; n++)
#pragma unroll
            for (int i = 0; i < 4; i++) o[mt][n][i] = 0.f;
    float mrow[4] = {-1e30f, -1e30f, -1e30f, -1e30f};
    float lrow[4] = {0.f, 0.f, 0.f, 0.f};

    const int ntiles = 2 * qt + 2;
    for (int t64 = 0; t64 < ntiles; t64++) {
        const int j0 = t64 * 64;
        __syncthreads();
        for (int i = tid; i < 64 * 16; i += 128) {
            const int row = i >> 4, c4 = i & 15;
            const size_t gsrc = (size_t)(b * LL + j0 + row) * 1024 + h * 64 + c4 * 4;
            *(float4*)(Ks + row * AST + c4 * 4) = *(const float4*)(kg + gsrc);
            *(float4*)(Vs + row * AST + c4 * 4) = *(const float4*)(vg + gsrc);
        }
        __syncthreads();

        // ---- S = Q @ K^T ----
#pragma unroll
        for (int mt = 0; mt < 2; mt++)
#pragma unroll
            for (int n = 0; n < 8; n++)
#pragma unroll
                for (int i = 0; i < 4; i++) s[mt][n][i] = 0.f;

#pragma unroll
        for (int kk = 0; kk < 8; kk++) {
            uint32_t qa[2][4];
#pragma unroll
            for (int mt = 0; mt < 2; mt++) {
                const float* qp = Qs + (warp * 32 + mt * 16 + g) * AST + kk * 8 + l4;
                qa[mt][0] = fau(qp[0]);
                qa[mt][2] = fau(qp[4]);
                qa[mt][1] = fau(qp[8 * AST]);
                qa[mt][3] = fau(qp[8 * AST + 4]);
            }
#pragma unroll
            for (int n = 0; n < 8; n++) {
                uint32_t kb[2];
                const float* kp = Ks + (n * 8 + g) * AST + kk * 8 + l4;
                kb[0] = fau(kp[0]);
                kb[1] = fau(kp[4]);
                mma_tf32(s[0][n], qa[0], kb);
                mma_tf32(s[1][n], qa[1], kb);
            }
        }

        if (t64 >= 2 * qt) {
#pragma unroll
            for (int mt = 0; mt < 2; mt++) {
                const int rg = qbase + warp * 32 + mt * 16 + g;
#pragma unroll
                for (int n = 0; n < 8; n++) {
                    const int c0 = j0 + n * 8 + 2 * l4;
                    if (c0     > rg)     s[mt][n][0] = -1e30f;
                    if (c0 + 1 > rg)     s[mt][n][1] = -1e30f;
                    if (c0     > rg + 8) s[mt][n][2] = -1e30f;
                    if (c0 + 1 > rg + 8) s[mt][n][3] = -1e30f;
                }
            }
        }

#pragma unroll
        for (int mt = 0; mt < 2; mt++) {
            float r0 = -1e30f, r1 = -1e30f;
#pragma unroll
            for (int n = 0; n < 8; n++) {
                r0 = fmaxf(r0, fmaxf(s[mt][n][0], s[mt][n][1]));
                r1 = fmaxf(r1, fmaxf(s[mt][n][2], s[mt][n][3]));
            }
            r0 = fmaxf(r0, __shfl_xor_sync(0xffffffffu, r0, 1));
            r0 = fmaxf(r0, __shfl_xor_sync(0xffffffffu, r0, 2));
            r1 = fmaxf(r1, __shfl_xor_sync(0xffffffffu, r1, 1));
            r1 = fmaxf(r1, __shfl_xor_sync(0xffffffffu, r1, 2));
            const float m0 = fmaxf(mrow[2*mt],   r0);
            const float m1 = fmaxf(mrow[2*mt+1], r1);
            const float c0 = __expf(mrow[2*mt]   - m0);
            const float c1 = __expf(mrow[2*mt+1] - m1);
            mrow[2*mt] = m0; mrow[2*mt+1] = m1;
            float ps0 = 0.f, ps1 = 0.f;
#pragma unroll
            for (int n = 0; n < 8; n++) {
                float e0 = __expf(s[mt][n][0] - m0);
                float e1 = __expf(s[mt][n][1] - m0);
                float e2 = __expf(s[mt][n][2] - m1);
                float e3 = __expf(s[mt][n][3] - m1);
                ps0 += e0 + e1; ps1 += e2 + e3;
                uint32_t t0, t1, t2, t3;
                CVT_TF32(t0, e0); CVT_TF32(t1, e1);
                CVT_TF32(t2, e2); CVT_TF32(t3, e3);
                s[mt][n][0] = uaf(t0); s[mt][n][1] = uaf(t1);
                s[mt][n][2] = uaf(t2); s[mt][n][3] = uaf(t3);
                o[mt][n][0] *= c0; o[mt][n][1] *= c0;
                o[mt][n][2] *= c1; o[mt][n][3] *= c1;
            }
            lrow[2*mt]   = lrow[2*mt]   * c0 + ps0;
            lrow[2*mt+1] = lrow[2*mt+1] * c1 + ps1;
        }

        const int srcA = (lane & ~3) | (l4 >> 1);
        const int srcB = srcA + 2;
#pragma unroll
        for (int kk = 0; kk < 8; kk++) {
            uint32_t pa[2][4];
#pragma unroll
            for (int mt = 0; mt < 2; mt++) {
                float c0 = s[mt][kk][0], c1 = s[mt][kk][1];
                float c2 = s[mt][kk][2], c3 = s[mt][kk][3];
                float x0 = __shfl_sync(0xffffffffu, c0, srcA);
                float x1 = __shfl_sync(0xffffffffu, c1, srcA);
                float y0 = __shfl_sync(0xffffffffu, c0, srcB);
                float y1 = __shfl_sync(0xffffffffu, c1, srcB);
                pa[mt][0] = fau((l4 & 1) ? x1 : x0);
                pa[mt][2] = fau((l4 & 1) ? y1 : y0);
                x0 = __shfl_sync(0xffffffffu, c2, srcA);
                x1 = __shfl_sync(0xffffffffu, c3, srcA);
                y0 = __shfl_sync(0xffffffffu, c2, srcB);
                y1 = __shfl_sync(0xffffffffu, c3, srcB);
                pa[mt][1] = fau((l4 & 1) ? x1 : x0);
                pa[mt][3] = fau((l4 & 1) ? y1 : y0);
            }
#pragma unroll
            for (int n = 0; n < 8; n++) {
                uint32_t vb[2];
                const float* vp = Vs + (kk * 8 + l4) * AST + n * 8 + g;
                vb[0] = fau(vp[0]);
                vb[1] = fau(vp[4 * AST]);
                mma_tf32(o[0][n], pa[0], vb);
                mma_tf32(o[1][n], pa[1], vb);
            }
        }
    }

#pragma unroll
    for (int i = 0; i < 4; i++) {
        lrow[i] += __shfl_xor_sync(0xffffffffu, lrow[i], 1);
        lrow[i] += __shfl_xor_sync(0xffffffffu, lrow[i], 2);
        lrow[i] = 1.0f / lrow[i];
    }
#pragma unroll
    for (int mt = 0; mt < 2; mt++) {
        const int rg = b * LL + qbase + warp * 32 + mt * 16 + g;
#pragma unroll
        for (int n = 0; n < 8; n++) {
            const size_t a0 = (size_t)rg * 1024 + h * 64 + n * 8 + 2 * l4;
            uint32_t u0, u1, u2, u3;
            CVT_TF32(u0, o[mt][n][0] * lrow[2*mt]);
            CVT_TF32(u1, o[mt][n][1] * lrow[2*mt]);
            CVT_TF32(u2, o[mt][n][2] * lrow[2*mt+1]);
            CVT_TF32(u3, o[mt][n][3] * lrow[2*mt+1]);
            *(float2*)(og + a0)            = make_float2(uaf(u0), uaf(u1));
            *(float2*)(og + a0 + 8 * 1024) = make_float2(uaf(u2), uaf(u3));
        }
    }
}

// ---------------------------------------------------------------------------
// Launch
// ---------------------------------------------------------------------------
extern "C" void kernel_launch(void* const* d_in, const int* in_sizes, int n_in,
                              void* d_out, int out_size) {
    const float* x     = (const float*)d_in[0];
    const float* gamma = (const float*)d_in[1];
    const float* beta  = (const float*)d_in[2];
    const float* Wq    = (const float*)d_in[3];
    const float* bq    = (const float*)d_in[4];
    const float* Wk    = (const float*)d_in[5];
    const float* bk    = (const float*)d_in[6];
    const float* Wv    = (const float*)d_in[7];
    const float* bv    = (const float*)d_in[8];
    const float* Wo    = (const float*)d_in[9];
    const float* bo    = (const float*)d_in[10];
    float* out = (float*)d_out;

    float* sc = nullptr;
    cudaGetSymbolAddress((void**)&sc, g_scratch);
    float* xn   = sc;
    float* qb   = sc + 1 * (size_t)ELEMS;
    float* kb   = sc + 2 * (size_t)ELEMS;
    float* vb   = sc + 3 * (size_t)ELEMS;
    float* attn = sc + 4 * (size_t)ELEMS;
    float* Wqt  = sc + 5 * (size_t)ELEMS;
    float* Wkt  = Wqt + (size_t)WELEMS;
    float* Wvt  = Wkt + (size_t)WELEMS;
    float* Wot  = Wvt + (size_t)WELEMS;
    float2* rtab = (float2*)(Wot + (size_t)WELEMS);

    const int attn_smem = (128 + 64 + 64) * AST * sizeof(float);
    cudaFuncSetAttribute(attn_tc_kernel,
                         cudaFuncAttributeMaxDynamicSharedMemorySize, attn_smem);
    cudaFuncSetAttribute(tgemm3<false, true,  true>,
                         cudaFuncAttributeMaxDynamicSharedMemorySize, GSMEM);
    cudaFuncSetAttribute(tgemm3<false, false, true>,
                         cudaFuncAttributeMaxDynamicSharedMemorySize, GSMEM);
    cudaFuncSetAttribute(tgemm3<true,  false, false>,
                         cudaFuncAttributeMaxDynamicSharedMemorySize, GSMEM);

    rope_table_kernel<<<65536 / 256, 256>>>(rtab);
    dim3 tgrid(32, 32), tblk(32, 8);
    cvtwt_kernel<<<tgrid, tblk>>>(Wq, Wqt);
    cvtwt_kernel<<<tgrid, tblk>>>(Wk, Wkt);
    cvtwt_kernel<<<tgrid, tblk>>>(Wv, Wvt);
    cvtwt_kernel<<<tgrid, tblk>>>(Wo, Wot);

    ln_kernel<<<MM, 256>>>(x, gamma, beta, xn);

    dim3 ggrid(8, 64);
    tgemm3<false, true,  true ><<<ggrid, 128, GSMEM>>>(xn, Wqt, bq, nullptr, rtab, 0.125f, qb);
    tgemm3<false, true,  true ><<<ggrid, 128, GSMEM>>>(xn, Wkt, bk, nullptr, rtab, 1.0f,   kb);
    tgemm3<false, false, true ><<<ggrid, 128, GSMEM>>>(xn, Wvt, bv, nullptr, rtab, 1.0f,   vb);

    dim3 agrid(LL / 128, BB * NH);
    attn_tc_kernel<<<agrid, 128, attn_smem>>>(qb, kb, vb, attn);

    tgemm3<true, false, false><<<ggrid, 128, GSMEM>>>(attn, Wot, bo, x, rtab, 1.0f, out);
}

// round 9
// speedup vs baseline: 1.1932x; 1.1932x over previous
#include <cuda_runtime.h>
#include <math.h>
#include <stdint.h>

// Problem constants
#define BB 4
#define LL 2048
#define DM 1024
#define NH 16
#define DH 64
#define MM (BB*LL)          // 8192 rows
#define ELEMS (MM*DM)       // 8388608 floats per tensor
#define WELEMS (DM*DM)      // 1048576

// Scratch: xn,q,k,v,attn (5x) + 4 tf32 weights + rope table (131072 floats)
__device__ float g_scratch[5 * (size_t)ELEMS + 4 * (size_t)WELEMS + 131072];

#define CVT_TF32(u, f) asm("cvt.rna.tf32.f32 %0, %1;" : "=r"(u) : "f"(f))
__device__ __forceinline__ uint32_t fau(float f) { return __float_as_uint(f); }
__device__ __forceinline__ float uaf(uint32_t u) { return __uint_as_float(u); }

__device__ __forceinline__ void mma_tf32(float c[4],
                                         const uint32_t a[4],
                                         const uint32_t b[2]) {
    asm volatile(
        "mma.sync.aligned.m16n8k8.row.col.f32.tf32.tf32.f32 "
        "{%0,%1,%2,%3}, {%4,%5,%6,%7}, {%8,%9}, {%0,%1,%2,%3};\n"
        : "+f"(c[0]), "+f"(c[1]), "+f"(c[2]), "+f"(c[3])
        : "r"(a[0]), "r"(a[1]), "r"(a[2]), "r"(a[3]),
          "r"(b[0]), "r"(b[1]));
}

#define CP_ASYNC16(dst, src) \
    asm volatile("cp.async.cg.shared.global [%0], [%1], 16;\n" \
                 :: "r"(dst), "l"(src) : "memory")
#define CP_COMMIT() asm volatile("cp.async.commit_group;\n" ::: "memory")
#define CP_WAIT1()  asm volatile("cp.async.wait_group 1;\n" ::: "memory")

// ---------------------------------------------------------------------------
// Elementwise fp32 -> tf32 rounding (for weight matrices), float4
// ---------------------------------------------------------------------------
__global__ __launch_bounds__(256) void cvtw_kernel(const float* __restrict__ src,
                                                   float* __restrict__ dst) {
    const int i = blockIdx.x * 256 + threadIdx.x;
    float4 v = ((const float4*)src)[i];
    uint32_t u0, u1, u2, u3;
    CVT_TF32(u0, v.x); CVT_TF32(u1, v.y);
    CVT_TF32(u2, v.z); CVT_TF32(u3, v.w);
    ((float4*)dst)[i] = make_float4(uaf(u0), uaf(u1), uaf(u2), uaf(u3));
}

// ---------------------------------------------------------------------------
// RoPE cos/sin table: t[l*32+p] = {cos(l*invfreq(p)), sin(...)}
// ---------------------------------------------------------------------------
__global__ __launch_bounds__(256) void rope_table_kernel(float2* __restrict__ t) {
    const int idx = blockIdx.x * 256 + threadIdx.x;   // 65536
    const int l = idx >> 5, p = idx & 31;
    const float inv = exp2f((float)p * (-2.0f / 64.0f) * 13.2877123795494f);
    float s, c;
    sincosf((float)l * inv, &s, &c);
    t[idx] = make_float2(c, s);
}

// ---------------------------------------------------------------------------
// LayerNorm -> tf32-rounded output
// ---------------------------------------------------------------------------
__global__ __launch_bounds__(256) void ln_kernel(const float* __restrict__ x,
                                                 const float* __restrict__ gamma,
                                                 const float* __restrict__ beta,
                                                 float* __restrict__ xn) {
    const int row = blockIdx.x;
    const int t = threadIdx.x;
    const float4 v = ((const float4*)(x + (size_t)row * DM))[t];
    __shared__ float red[8];

    float s = v.x + v.y + v.z + v.w;
#pragma unroll
    for (int o = 16; o > 0; o >>= 1) s += __shfl_xor_sync(0xffffffffu, s, o);
    if ((t & 31) == 0) red[t >> 5] = s;
    __syncthreads();
    float mean = (red[0]+red[1]+red[2]+red[3]+red[4]+red[5]+red[6]+red[7]) * (1.0f/DM);

    float dx = v.x-mean, dy = v.y-mean, dz = v.z-mean, dw = v.w-mean;
    float q = dx*dx + dy*dy + dz*dz + dw*dw;
#pragma unroll
    for (int o = 16; o > 0; o >>= 1) q += __shfl_xor_sync(0xffffffffu, q, o);
    __syncthreads();
    if ((t & 31) == 0) red[t >> 5] = q;
    __syncthreads();
    float var = (red[0]+red[1]+red[2]+red[3]+red[4]+red[5]+red[6]+red[7]) * (1.0f/DM);
    float rs = rsqrtf(var + 1e-5f);

    const float4 g4 = ((const float4*)gamma)[t];
    const float4 b4 = ((const float4*)beta)[t];
    uint32_t u0, u1, u2, u3;
    CVT_TF32(u0, dx*rs*g4.x + b4.x);
    CVT_TF32(u1, dy*rs*g4.y + b4.y);
    CVT_TF32(u2, dz*rs*g4.z + b4.z);
    CVT_TF32(u3, dw*rs*g4.w + b4.w);
    ((float4*)(xn + (size_t)row * DM))[t] =
        make_float4(uaf(u0), uaf(u1), uaf(u2), uaf(u3));
}

// ---------------------------------------------------------------------------
// TF32 GEMM, cp.async 3-stage: C[M,1024] = A@W + bias (+rope)(+resid)(+cvt)
// A, W already tf32-rounded. 128x128x16 tile, 8 warps (2Mx4N), 64x32 warp.
// Smem: As[3][128][20], Bs[3][16][136]   (exact round-6 configuration)
// ---------------------------------------------------------------------------
#define AS_STG 2560          // 128*20
#define BS_STG 2176          // 16*136
#define BS_BASE (3*AS_STG)   // 7680
#define GSMEM ((3*AS_STG + 3*BS_STG) * 4)  // 56832 bytes

template <bool RESID, bool ROPE, bool CVTOUT>
__global__ __launch_bounds__(256) void tgemm2(const float* __restrict__ A,
                                              const float* __restrict__ W,
                                              const float* __restrict__ bias,
                                              const float* __restrict__ resid,
                                              const float2* __restrict__ rtab,
                                              float oscale,
                                              float* __restrict__ C) {
    constexpr int NK = 64;   // 1024/16
    extern __shared__ float sm2[];

    const int tid   = threadIdx.x;
    const int lane  = tid & 31;
    const int warp  = tid >> 5;
    const int warpM = warp >> 2;
    const int warpN = warp & 3;
    const int g  = lane >> 2;
    const int l4 = lane & 3;
    const int brow = blockIdx.y;
    const int bcol = blockIdx.x;

    const float* Ab = A + (size_t)brow * 128 * 1024;
    const float* Wb = W + (size_t)bcol * 128;

    const uint32_t smbase = (uint32_t)__cvta_generic_to_shared(sm2);

    // async-copy assignments
    const int arow = tid >> 1;               // 0..127
    const int akc  = (tid & 1) << 3;         // 0 or 8
    const int brow2 = tid >> 4;              // 0..15
    const int bnc   = ((2 * tid) & 31) << 2; // 0..124 step 8

    auto issue = [&](int stage, int k0) {
        const uint32_t da = smbase + (stage * AS_STG + arow * 20 + akc) * 4;
        const float* sa = Ab + (size_t)arow * 1024 + k0 + akc;
        CP_ASYNC16(da, sa);
        CP_ASYNC16(da + 16, sa + 4);
        const uint32_t db = smbase + (BS_BASE + stage * BS_STG + brow2 * 136 + bnc) * 4;
        const float* sb = Wb + (size_t)(k0 + brow2) * 1024 + bnc;
        CP_ASYNC16(db, sb);
        CP_ASYNC16(db + 16, sb + 4);
    };

    float acc[16][4];
#pragma unroll
    for (int i = 0; i < 16; i++)
#pragma unroll
        for (int j = 0; j < 4; j++) acc[i][j] = 0.f;

    auto compute = [&](int stage) {
        const float* Ast = sm2 + stage * AS_STG;
        const float* Bst = sm2 + BS_BASE + stage * BS_STG;
#pragma unroll
        for (int k8 = 0; k8 < 16; k8 += 8) {
            uint32_t af[4][4];
            uint32_t bf[4][2];
#pragma unroll
            for (int i = 0; i < 4; i++) {
                const float* p = Ast + (warpM * 64 + i * 16 + g) * 20 + k8 + l4;
                af[i][0] = fau(p[0]);
                af[i][1] = fau(p[8 * 20]);
                af[i][2] = fau(p[4]);
                af[i][3] = fau(p[8 * 20 + 4]);
            }
#pragma unroll
            for (int j = 0; j < 4; j++) {
                const float* p = Bst + (k8 + l4) * 136 + warpN * 32 + j * 8 + g;
                bf[j][0] = fau(p[0]);
                bf[j][1] = fau(p[4 * 136]);
            }
#pragma unroll
            for (int i = 0; i < 4; i++)
#pragma unroll
                for (int j = 0; j < 4; j++)
                    mma_tf32(acc[i * 4 + j], af[i], bf[j]);
        }
    };

    // prologue
    issue(0, 0);  CP_COMMIT();
    issue(1, 16); CP_COMMIT();

    for (int kt = 0; kt < NK; kt++) {
        CP_WAIT1();
        __syncthreads();
        if (kt + 2 < NK) issue((kt + 2) % 3, (kt + 2) * 16);
        CP_COMMIT();
        compute(kt % 3);
    }

    // ---- epilogue ----
#pragma unroll
    for (int i = 0; i < 4; i++) {
        const int r0 = brow * 128 + warpM * 64 + i * 16 + g;
#pragma unroll
        for (int j = 0; j < 4; j++) {
            const int cc = bcol * 128 + warpN * 32 + j * 8 + (l4 << 1);
            const float bx = bias[cc], by = bias[cc + 1];
            float v0x = acc[i * 4 + j][0] + bx;
            float v0y = acc[i * 4 + j][1] + by;
            float v1x = acc[i * 4 + j][2] + bx;
            float v1y = acc[i * 4 + j][3] + by;
            if (ROPE) {
                const int p  = (cc & 63) >> 1;
                const int l0 = r0 & (LL - 1);
                const float2 cs0 = rtab[l0 * 32 + p];
                const float2 cs1 = rtab[(l0 + 8) * 32 + p];
                float t;
                t   = v0x * cs0.x - v0y * cs0.y;
                v0y = v0x * cs0.y + v0y * cs0.x;
                v0x = t;
                t   = v1x * cs1.x - v1y * cs1.y;
                v1y = v1x * cs1.y + v1y * cs1.x;
                v1x = t;
            }
            if (RESID) {
                const float2 r0v = *(const float2*)(resid + (size_t)r0 * 1024 + cc);
                const float2 r1v = *(const float2*)(resid + (size_t)(r0 + 8) * 1024 + cc);
                v0x += r0v.x; v0y += r0v.y;
                v1x += r1v.x; v1y += r1v.y;
            }
            if (CVTOUT) {
                uint32_t u0, u1, u2, u3;
                CVT_TF32(u0, v0x * oscale);
                CVT_TF32(u1, v0y * oscale);
                CVT_TF32(u2, v1x * oscale);
                CVT_TF32(u3, v1y * oscale);
                v0x = uaf(u0); v0y = uaf(u1); v1x = uaf(u2); v1y = uaf(u3);
            }
            *(float2*)(C + (size_t)r0 * 1024 + cc)       = make_float2(v0x, v0y);
            *(float2*)(C + (size_t)(r0 + 8) * 1024 + cc) = make_float2(v1x, v1y);
        }
    }
}

// ---------------------------------------------------------------------------
// Tensor-core flash attention (causal, TF32 mma).
// Inputs q (pre-scaled, tf32), k, v (tf32): plain LDG float4 + STS staging.
// ---------------------------------------------------------------------------
#define AST 68

__global__ __launch_bounds__(128) void attn_tc_kernel(const float* __restrict__ qg,
                                                      const float* __restrict__ kg,
                                                      const float* __restrict__ vg,
                                                      float* __restrict__ og) {
    extern __shared__ float sm[];
    float* Qs = sm;
    float* Ks = sm + 128 * AST;
    float* Vs = Ks + 64 * AST;

    const int bh = blockIdx.y;
    const int b = bh >> 4, h = bh & 15;
    const int qt = (int)gridDim.x - 1 - (int)blockIdx.x;
    const int qbase = qt * 128;
    const int tid  = threadIdx.x;
    const int lane = tid & 31;
    const int warp = tid >> 5;
    const int g  = lane >> 2;
    const int l4 = lane & 3;

    // ---- Q tile: 128 rows x 64 d (already scaled+rounded) ----
    for (int i = tid; i < 128 * 16; i += 128) {
        const int row = i >> 4, c4 = i & 15;
        *(float4*)(Qs + row * AST + c4 * 4) =
            *(const float4*)(qg + (size_t)(b * LL + qbase + row) * 1024 + h * 64 + c4 * 4);
    }

    float s[2][8][4];
    float o[2][8][4];
#pragma unroll
    for (int mt = 0; mt < 2; mt++)
#pragma unroll
        for (int n = 0; n < 8; n++)
#pragma unroll
            for (int i = 0; i < 4; i++) o[mt][n][i] = 0.f;
    float mrow[4] = {-1e30f, -1e30f, -1e30f, -1e30f};
    float lrow[4] = {0.f, 0.f, 0.f, 0.f};

    const int ntiles = 2 * qt + 2;
    for (int t64 = 0; t64 < ntiles; t64++) {
        const int j0 = t64 * 64;
        __syncthreads();
        for (int i = tid; i < 64 * 16; i += 128) {
            const int row = i >> 4, c4 = i & 15;
            const size_t gsrc = (size_t)(b * LL + j0 + row) * 1024 + h * 64 + c4 * 4;
            *(float4*)(Ks + row * AST + c4 * 4) = *(const float4*)(kg + gsrc);
            *(float4*)(Vs + row * AST + c4 * 4) = *(const float4*)(vg + gsrc);
        }
        __syncthreads();

        // ---- S = Q @ K^T ----
#pragma unroll
        for (int mt = 0; mt < 2; mt++)
#pragma unroll
            for (int n = 0; n < 8; n++)
#pragma unroll
                for (int i = 0; i < 4; i++) s[mt][n][i] = 0.f;

#pragma unroll
        for (int kk = 0; kk < 8; kk++) {
            uint32_t qa[2][4];
#pragma unroll
            for (int mt = 0; mt < 2; mt++) {
                const float* qp = Qs + (warp * 32 + mt * 16 + g) * AST + kk * 8 + l4;
                qa[mt][0] = fau(qp[0]);
                qa[mt][2] = fau(qp[4]);
                qa[mt][1] = fau(qp[8 * AST]);
                qa[mt][3] = fau(qp[8 * AST + 4]);
            }
#pragma unroll
            for (int n = 0; n < 8; n++) {
                uint32_t kb[2];
                const float* kp = Ks + (n * 8 + g) * AST + kk * 8 + l4;
                kb[0] = fau(kp[0]);
                kb[1] = fau(kp[4]);
                mma_tf32(s[0][n], qa[0], kb);
                mma_tf32(s[1][n], qa[1], kb);
            }
        }

        if (t64 >= 2 * qt) {
#pragma unroll
            for (int mt = 0; mt < 2; mt++) {
                const int rg = qbase + warp * 32 + mt * 16 + g;
#pragma unroll
                for (int n = 0; n < 8; n++) {
                    const int c0 = j0 + n * 8 + 2 * l4;
                    if (c0     > rg)     s[mt][n][0] = -1e30f;
                    if (c0 + 1 > rg)     s[mt][n][1] = -1e30f;
                    if (c0     > rg + 8) s[mt][n][2] = -1e30f;
                    if (c0 + 1 > rg + 8) s[mt][n][3] = -1e30f;
                }
            }
        }

#pragma unroll
        for (int mt = 0; mt < 2; mt++) {
            float r0 = -1e30f, r1 = -1e30f;
#pragma unroll
            for (int n = 0; n < 8; n++) {
                r0 = fmaxf(r0, fmaxf(s[mt][n][0], s[mt][n][1]));
                r1 = fmaxf(r1, fmaxf(s[mt][n][2], s[mt][n][3]));
            }
            r0 = fmaxf(r0, __shfl_xor_sync(0xffffffffu, r0, 1));
            r0 = fmaxf(r0, __shfl_xor_sync(0xffffffffu, r0, 2));
            r1 = fmaxf(r1, __shfl_xor_sync(0xffffffffu, r1, 1));
            r1 = fmaxf(r1, __shfl_xor_sync(0xffffffffu, r1, 2));
            const float m0 = fmaxf(mrow[2*mt],   r0);
            const float m1 = fmaxf(mrow[2*mt+1], r1);
            const float c0 = __expf(mrow[2*mt]   - m0);
            const float c1 = __expf(mrow[2*mt+1] - m1);
            mrow[2*mt] = m0; mrow[2*mt+1] = m1;
            float ps0 = 0.f, ps1 = 0.f;
#pragma unroll
            for (int n = 0; n < 8; n++) {
                float e0 = __expf(s[mt][n][0] - m0);
                float e1 = __expf(s[mt][n][1] - m0);
                float e2 = __expf(s[mt][n][2] - m1);
                float e3 = __expf(s[mt][n][3] - m1);
                ps0 += e0 + e1; ps1 += e2 + e3;
                uint32_t t0, t1, t2, t3;
                CVT_TF32(t0, e0); CVT_TF32(t1, e1);
                CVT_TF32(t2, e2); CVT_TF32(t3, e3);
                s[mt][n][0] = uaf(t0); s[mt][n][1] = uaf(t1);
                s[mt][n][2] = uaf(t2); s[mt][n][3] = uaf(t3);
                o[mt][n][0] *= c0; o[mt][n][1] *= c0;
                o[mt][n][2] *= c1; o[mt][n][3] *= c1;
            }
            lrow[2*mt]   = lrow[2*mt]   * c0 + ps0;
            lrow[2*mt+1] = lrow[2*mt+1] * c1 + ps1;
        }

        const int srcA = (lane & ~3) | (l4 >> 1);
        const int srcB = srcA + 2;
#pragma unroll
        for (int kk = 0; kk < 8; kk++) {
            uint32_t pa[2][4];
#pragma unroll
            for (int mt = 0; mt < 2; mt++) {
                float c0 = s[mt][kk][0], c1 = s[mt][kk][1];
                float c2 = s[mt][kk][2], c3 = s[mt][kk][3];
                float x0 = __shfl_sync(0xffffffffu, c0, srcA);
                float x1 = __shfl_sync(0xffffffffu, c1, srcA);
                float y0 = __shfl_sync(0xffffffffu, c0, srcB);
                float y1 = __shfl_sync(0xffffffffu, c1, srcB);
                pa[mt][0] = fau((l4 & 1) ? x1 : x0);
                pa[mt][2] = fau((l4 & 1) ? y1 : y0);
                x0 = __shfl_sync(0xffffffffu, c2, srcA);
                x1 = __shfl_sync(0xffffffffu, c3, srcA);
                y0 = __shfl_sync(0xffffffffu, c2, srcB);
                y1 = __shfl_sync(0xffffffffu, c3, srcB);
                pa[mt][1] = fau((l4 & 1) ? x1 : x0);
                pa[mt][3] = fau((l4 & 1) ? y1 : y0);
            }
#pragma unroll
            for (int n = 0; n < 8; n++) {
                uint32_t vb[2];
                const float* vp = Vs + (kk * 8 + l4) * AST + n * 8 + g;
                vb[0] = fau(vp[0]);
                vb[1] = fau(vp[4 * AST]);
                mma_tf32(o[0][n], pa[0], vb);
                mma_tf32(o[1][n], pa[1], vb);
            }
        }
    }

#pragma unroll
    for (int i = 0; i < 4; i++) {
        lrow[i] += __shfl_xor_sync(0xffffffffu, lrow[i], 1);
        lrow[i] += __shfl_xor_sync(0xffffffffu, lrow[i], 2);
        lrow[i] = 1.0f / lrow[i];
    }
#pragma unroll
    for (int mt = 0; mt < 2; mt++) {
        const int rg = b * LL + qbase + warp * 32 + mt * 16 + g;
#pragma unroll
        for (int n = 0; n < 8; n++) {
            const size_t a0 = (size_t)rg * 1024 + h * 64 + n * 8 + 2 * l4;
            uint32_t u0, u1, u2, u3;
            CVT_TF32(u0, o[mt][n][0] * lrow[2*mt]);
            CVT_TF32(u1, o[mt][n][1] * lrow[2*mt]);
            CVT_TF32(u2, o[mt][n][2] * lrow[2*mt+1]);
            CVT_TF32(u3, o[mt][n][3] * lrow[2*mt+1]);
            *(float2*)(og + a0)            = make_float2(uaf(u0), uaf(u1));
            *(float2*)(og + a0 + 8 * 1024) = make_float2(uaf(u2), uaf(u3));
        }
    }
}

// ---------------------------------------------------------------------------
// Launch
// ---------------------------------------------------------------------------
extern "C" void kernel_launch(void* const* d_in, const int* in_sizes, int n_in,
                              void* d_out, int out_size) {
    const float* x     = (const float*)d_in[0];
    const float* gamma = (const float*)d_in[1];
    const float* beta  = (const float*)d_in[2];
    const float* Wq    = (const float*)d_in[3];
    const float* bq    = (const float*)d_in[4];
    const float* Wk    = (const float*)d_in[5];
    const float* bk    = (const float*)d_in[6];
    const float* Wv    = (const float*)d_in[7];
    const float* bv    = (const float*)d_in[8];
    const float* Wo    = (const float*)d_in[9];
    const float* bo    = (const float*)d_in[10];
    float* out = (float*)d_out;

    float* sc = nullptr;
    cudaGetSymbolAddress((void**)&sc, g_scratch);
    float* xn   = sc;
    float* qb   = sc + 1 * (size_t)ELEMS;
    float* kb   = sc + 2 * (size_t)ELEMS;
    float* vb   = sc + 3 * (size_t)ELEMS;
    float* attn = sc + 4 * (size_t)ELEMS;
    float* Wqt  = sc + 5 * (size_t)ELEMS;
    float* Wkt  = Wqt + (size_t)WELEMS;
    float* Wvt  = Wkt + (size_t)WELEMS;
    float* Wot  = Wvt + (size_t)WELEMS;
    float2* rtab = (float2*)(Wot + (size_t)WELEMS);

    const int attn_smem = (128 + 64 + 64) * AST * sizeof(float);
    cudaFuncSetAttribute(attn_tc_kernel,
                         cudaFuncAttributeMaxDynamicSharedMemorySize, attn_smem);
    cudaFuncSetAttribute(tgemm2<false, true,  true>,
                         cudaFuncAttributeMaxDynamicSharedMemorySize, GSMEM);
    cudaFuncSetAttribute(tgemm2<false, false, true>,
                         cudaFuncAttributeMaxDynamicSharedMemorySize, GSMEM);
    cudaFuncSetAttribute(tgemm2<true,  false, false>,
                         cudaFuncAttributeMaxDynamicSharedMemorySize, GSMEM);

    rope_table_kernel<<<65536 / 256, 256>>>(rtab);
    cvtw_kernel<<<WELEMS / 1024, 256>>>(Wq, Wqt);
    cvtw_kernel<<<WELEMS / 1024, 256>>>(Wk, Wkt);
    cvtw_kernel<<<WELEMS / 1024, 256>>>(Wv, Wvt);
    cvtw_kernel<<<WELEMS / 1024, 256>>>(Wo, Wot);

    ln_kernel<<<MM, 256>>>(x, gamma, beta, xn);

    dim3 ggrid(8, 64);
    tgemm2<false, true,  true ><<<ggrid, 256, GSMEM>>>(xn, Wqt, bq, nullptr, rtab, 0.125f, qb);
    tgemm2<false, true,  true ><<<ggrid, 256, GSMEM>>>(xn, Wkt, bk, nullptr, rtab, 1.0f,   kb);
    tgemm2<false, false, true ><<<ggrid, 256, GSMEM>>>(xn, Wvt, bv, nullptr, rtab, 1.0f,   vb);

    dim3 agrid(LL / 128, BB * NH);
    attn_tc_kernel<<<agrid, 128, attn_smem>>>(qb, kb, vb, attn);

    tgemm2<true, false, false><<<ggrid, 256, GSMEM>>>(attn, Wot, bo, x, rtab, 1.0f, out);
}

// round 10
// speedup vs baseline: 1.3227x; 1.1085x over previous
#include <cuda_runtime.h>
#include <math.h>
#include <stdint.h>

// Problem constants
#define BB 4
#define LL 2048
#define DM 1024
#define NH 16
#define DH 64
#define MM (BB*LL)          // 8192 rows
#define ELEMS (MM*DM)       // 8388608 floats per tensor
#define WELEMS (DM*DM)      // 1048576

// Scratch: xn,q,k,v,attn (5x) + 4 tf32 weights (contig) + rope table
__device__ float g_scratch[5 * (size_t)ELEMS + 4 * (size_t)WELEMS + 131072];

#define CVT_TF32(u, f) asm("cvt.rna.tf32.f32 %0, %1;" : "=r"(u) : "f"(f))
__device__ __forceinline__ uint32_t fau(float f) { return __float_as_uint(f); }
__device__ __forceinline__ float uaf(uint32_t u) { return __uint_as_float(u); }

__device__ __forceinline__ void mma_tf32(float c[4],
                                         const uint32_t a[4],
                                         const uint32_t b[2]) {
    asm volatile(
        "mma.sync.aligned.m16n8k8.row.col.f32.tf32.tf32.f32 "
        "{%0,%1,%2,%3}, {%4,%5,%6,%7}, {%8,%9}, {%0,%1,%2,%3};\n"
        : "+f"(c[0]), "+f"(c[1]), "+f"(c[2]), "+f"(c[3])
        : "r"(a[0]), "r"(a[1]), "r"(a[2]), "r"(a[3]),
          "r"(b[0]), "r"(b[1]));
}

#define CP_ASYNC16(dst, src) \
    asm volatile("cp.async.cg.shared.global [%0], [%1], 16;\n" \
                 :: "r"(dst), "l"(src) : "memory")
#define CP_ASYNC16_CA(dst, src) \
    asm volatile("cp.async.ca.shared.global [%0], [%1], 16;\n" \
                 :: "r"(dst), "l"(src) : "memory")
#define CP_COMMIT() asm volatile("cp.async.commit_group;\n" ::: "memory")
#define CP_WAIT1()  asm volatile("cp.async.wait_group 1;\n" ::: "memory")
#define CP_WAIT0()  asm volatile("cp.async.wait_group 0;\n" ::: "memory")

// ---------------------------------------------------------------------------
// Elementwise fp32 -> tf32 rounding (weights), float4
// ---------------------------------------------------------------------------
__global__ __launch_bounds__(256) void cvtw_kernel(const float* __restrict__ src,
                                                   float* __restrict__ dst) {
    const int i = blockIdx.x * 256 + threadIdx.x;
    float4 v = ((const float4*)src)[i];
    uint32_t u0, u1, u2, u3;
    CVT_TF32(u0, v.x); CVT_TF32(u1, v.y);
    CVT_TF32(u2, v.z); CVT_TF32(u3, v.w);
    ((float4*)dst)[i] = make_float4(uaf(u0), uaf(u1), uaf(u2), uaf(u3));
}

// ---------------------------------------------------------------------------
// RoPE cos/sin table
// ---------------------------------------------------------------------------
__global__ __launch_bounds__(256) void rope_table_kernel(float2* __restrict__ t) {
    const int idx = blockIdx.x * 256 + threadIdx.x;   // 65536
    const int l = idx >> 5, p = idx & 31;
    const float inv = exp2f((float)p * (-2.0f / 64.0f) * 13.2877123795494f);
    float s, c;
    sincosf((float)l * inv, &s, &c);
    t[idx] = make_float2(c, s);
}

// ---------------------------------------------------------------------------
// LayerNorm -> tf32-rounded output
// ---------------------------------------------------------------------------
__global__ __launch_bounds__(256) void ln_kernel(const float* __restrict__ x,
                                                 const float* __restrict__ gamma,
                                                 const float* __restrict__ beta,
                                                 float* __restrict__ xn) {
    const int row = blockIdx.x;
    const int t = threadIdx.x;
    const float4 v = ((const float4*)(x + (size_t)row * DM))[t];
    __shared__ float red[8];

    float s = v.x + v.y + v.z + v.w;
#pragma unroll
    for (int o = 16; o > 0; o >>= 1) s += __shfl_xor_sync(0xffffffffu, s, o);
    if ((t & 31) == 0) red[t >> 5] = s;
    __syncthreads();
    float mean = (red[0]+red[1]+red[2]+red[3]+red[4]+red[5]+red[6]+red[7]) * (1.0f/DM);

    float dx = v.x-mean, dy = v.y-mean, dz = v.z-mean, dw = v.w-mean;
    float q = dx*dx + dy*dy + dz*dz + dw*dw;
#pragma unroll
    for (int o = 16; o > 0; o >>= 1) q += __shfl_xor_sync(0xffffffffu, q, o);
    __syncthreads();
    if ((t & 31) == 0) red[t >> 5] = q;
    __syncthreads();
    float var = (red[0]+red[1]+red[2]+red[3]+red[4]+red[5]+red[6]+red[7]) * (1.0f/DM);
    float rs = rsqrtf(var + 1e-5f);

    const float4 g4 = ((const float4*)gamma)[t];
    const float4 b4 = ((const float4*)beta)[t];
    uint32_t u0, u1, u2, u3;
    CVT_TF32(u0, dx*rs*g4.x + b4.x);
    CVT_TF32(u1, dy*rs*g4.y + b4.y);
    CVT_TF32(u2, dz*rs*g4.z + b4.z);
    CVT_TF32(u3, dw*rs*g4.w + b4.w);
    ((float4*)(xn + (size_t)row * DM))[t] =
        make_float4(uaf(u0), uaf(u1), uaf(u2), uaf(u3));
}

// ---------------------------------------------------------------------------
// GEMM core (R6 config): 128x128x16 tile, 8 warps (2Mx4N), cp.async 3-stage.
// Smem: As[3][128][20], Bs[3][16][136]
// ---------------------------------------------------------------------------
#define AS_STG 2560          // 128*20
#define BS_STG 2176          // 16*136
#define BS_BASE (3*AS_STG)   // 7680
#define GSMEM ((3*AS_STG + 3*BS_STG) * 4)  // 56832 bytes

struct GemmCore {
    int tid, lane, warp, warpM, warpN, g, l4;
    uint32_t smbase;
    float* sm2;
    const float* Ab;
    const float* Wb;
    int arow, akc, brow2, bnc;
    float acc[16][4];

    __device__ __forceinline__ void init(float* sm, const float* A_, const float* W_) {
        sm2 = sm;
        tid = threadIdx.x; lane = tid & 31; warp = tid >> 5;
        warpM = warp >> 2; warpN = warp & 3;
        g = lane >> 2; l4 = lane & 3;
        smbase = (uint32_t)__cvta_generic_to_shared(sm2);
        Ab = A_; Wb = W_;
        arow = tid >> 1; akc = (tid & 1) << 3;
        brow2 = tid >> 4; bnc = ((2 * tid) & 31) << 2;
#pragma unroll
        for (int i = 0; i < 16; i++)
#pragma unroll
            for (int j = 0; j < 4; j++) acc[i][j] = 0.f;
    }

    __device__ __forceinline__ void issue(int stage, int k0) {
        const uint32_t da = smbase + (stage * AS_STG + arow * 20 + akc) * 4;
        const float* sa = Ab + (size_t)arow * 1024 + k0 + akc;
        CP_ASYNC16(da, sa);
        CP_ASYNC16(da + 16, sa + 4);
        const uint32_t db = smbase + (BS_BASE + stage * BS_STG + brow2 * 136 + bnc) * 4;
        const float* sb = Wb + (size_t)(k0 + brow2) * 1024 + bnc;
        CP_ASYNC16(db, sb);
        CP_ASYNC16(db + 16, sb + 4);
    }

    __device__ __forceinline__ void compute(int stage) {
        const float* Ast = sm2 + stage * AS_STG;
        const float* Bst = sm2 + BS_BASE + stage * BS_STG;
#pragma unroll
        for (int k8 = 0; k8 < 16; k8 += 8) {
            uint32_t af[4][4];
            uint32_t bf[4][2];
#pragma unroll
            for (int i = 0; i < 4; i++) {
                const float* p = Ast + (warpM * 64 + i * 16 + g) * 20 + k8 + l4;
                af[i][0] = fau(p[0]);
                af[i][1] = fau(p[8 * 20]);
                af[i][2] = fau(p[4]);
                af[i][3] = fau(p[8 * 20 + 4]);
            }
#pragma unroll
            for (int j = 0; j < 4; j++) {
                const float* p = Bst + (k8 + l4) * 136 + warpN * 32 + j * 8 + g;
                bf[j][0] = fau(p[0]);
                bf[j][1] = fau(p[4 * 136]);
            }
#pragma unroll
            for (int i = 0; i < 4; i++)
#pragma unroll
                for (int j = 0; j < 4; j++)
                    mma_tf32(acc[i * 4 + j], af[i], bf[j]);
        }
    }

    __device__ __forceinline__ void mainloop() {
        issue(0, 0);  CP_COMMIT();
        issue(1, 16); CP_COMMIT();
        for (int kt = 0; kt < 64; kt++) {
            CP_WAIT1();
            __syncthreads();
            if (kt + 2 < 64) issue((kt + 2) % 3, (kt + 2) * 16);
            CP_COMMIT();
            compute(kt % 3);
        }
    }
};

// ---------------------------------------------------------------------------
// Merged QKV GEMM: grid (24, 64). bcol>>3 selects tensor (q,k,v).
// q: rope + 0.125 scale + cvt; k: rope + cvt; v: cvt.
// ---------------------------------------------------------------------------
__global__ __launch_bounds__(256) void qkv_gemm(const float* __restrict__ xn,
                                                const float* __restrict__ Wcat,
                                                const float* __restrict__ bq,
                                                const float* __restrict__ bk,
                                                const float* __restrict__ bv,
                                                const float2* __restrict__ rtab,
                                                float* __restrict__ qkv) {
    extern __shared__ float sm2[];
    const int brow = blockIdx.y;
    const int bcol = blockIdx.x;
    const int tsel = bcol >> 3;          // 0=q 1=k 2=v
    const int bcl  = bcol & 7;

    GemmCore core;
    core.init(sm2,
              xn + (size_t)brow * 128 * 1024,
              Wcat + (size_t)tsel * WELEMS + bcl * 128);
    core.mainloop();

    const float* bias = (tsel == 0) ? bq : (tsel == 1) ? bk : bv;
    const bool rope = (tsel < 2);
    const float oscale = (tsel == 0) ? 0.125f : 1.0f;
    float* C = qkv + (size_t)tsel * ELEMS;

#pragma unroll
    for (int i = 0; i < 4; i++) {
        const int r0 = brow * 128 + core.warpM * 64 + i * 16 + core.g;
#pragma unroll
        for (int j = 0; j < 4; j++) {
            const int cc = bcl * 128 + core.warpN * 32 + j * 8 + (core.l4 << 1);
            const float bx = bias[cc], by = bias[cc + 1];
            float v0x = core.acc[i * 4 + j][0] + bx;
            float v0y = core.acc[i * 4 + j][1] + by;
            float v1x = core.acc[i * 4 + j][2] + bx;
            float v1y = core.acc[i * 4 + j][3] + by;
            if (rope) {
                const int p  = (cc & 63) >> 1;
                const int l0 = r0 & (LL - 1);
                const float2 cs0 = rtab[l0 * 32 + p];
                const float2 cs1 = rtab[(l0 + 8) * 32 + p];
                float t;
                t   = v0x * cs0.x - v0y * cs0.y;
                v0y = v0x * cs0.y + v0y * cs0.x;
                v0x = t;
                t   = v1x * cs1.x - v1y * cs1.y;
                v1y = v1x * cs1.y + v1y * cs1.x;
                v1x = t;
            }
            uint32_t u0, u1, u2, u3;
            CVT_TF32(u0, v0x * oscale);
            CVT_TF32(u1, v0y * oscale);
            CVT_TF32(u2, v1x * oscale);
            CVT_TF32(u3, v1y * oscale);
            *(float2*)(C + (size_t)r0 * 1024 + cc)       = make_float2(uaf(u0), uaf(u1));
            *(float2*)(C + (size_t)(r0 + 8) * 1024 + cc) = make_float2(uaf(u2), uaf(u3));
        }
    }
}

// ---------------------------------------------------------------------------
// Output projection GEMM: C = attn @ Wo + bo + x   (residual)
// ---------------------------------------------------------------------------
__global__ __launch_bounds__(256) void o_gemm(const float* __restrict__ A,
                                              const float* __restrict__ W,
                                              const float* __restrict__ bias,
                                              const float* __restrict__ resid,
                                              float* __restrict__ C) {
    extern __shared__ float sm2[];
    const int brow = blockIdx.y;
    const int bcol = blockIdx.x;

    GemmCore core;
    core.init(sm2, A + (size_t)brow * 128 * 1024, W + (size_t)bcol * 128);
    core.mainloop();

#pragma unroll
    for (int i = 0; i < 4; i++) {
        const int r0 = brow * 128 + core.warpM * 64 + i * 16 + core.g;
#pragma unroll
        for (int j = 0; j < 4; j++) {
            const int cc = bcol * 128 + core.warpN * 32 + j * 8 + (core.l4 << 1);
            const float bx = bias[cc], by = bias[cc + 1];
            const float2 r0v = *(const float2*)(resid + (size_t)r0 * 1024 + cc);
            const float2 r1v = *(const float2*)(resid + (size_t)(r0 + 8) * 1024 + cc);
            *(float2*)(C + (size_t)r0 * 1024 + cc) =
                make_float2(core.acc[i*4+j][0] + bx + r0v.x,
                            core.acc[i*4+j][1] + by + r0v.y);
            *(float2*)(C + (size_t)(r0 + 8) * 1024 + cc) =
                make_float2(core.acc[i*4+j][2] + bx + r1v.x,
                            core.acc[i*4+j][3] + by + r1v.y);
        }
    }
}

// ---------------------------------------------------------------------------
// Tensor-core flash attention (causal, TF32 mma).
// Double-buffered K/V prefetch via cp.async.ca (L1-cached, overlapped).
// ---------------------------------------------------------------------------
#define AST 68
#define KVST (64 * AST)   // floats per K (or V) stage

__global__ __launch_bounds__(128) void attn_tc_kernel(const float* __restrict__ qg,
                                                      const float* __restrict__ kg,
                                                      const float* __restrict__ vg,
                                                      float* __restrict__ og) {
    extern __shared__ float sm[];
    float* Qs = sm;                        // 128*AST
    float* Ks = sm + 128 * AST;            // 2 stages x 64*AST
    float* Vs = Ks + 2 * KVST;             // 2 stages x 64*AST

    const int bh = blockIdx.y;
    const int b = bh >> 4, h = bh & 15;
    const int qt = (int)gridDim.x - 1 - (int)blockIdx.x;
    const int qbase = qt * 128;
    const int tid  = threadIdx.x;
    const int lane = tid & 31;
    const int warp = tid >> 5;
    const int g  = lane >> 2;
    const int l4 = lane & 3;

    const uint32_t smk = (uint32_t)__cvta_generic_to_shared(Ks);
    const uint32_t smv = (uint32_t)__cvta_generic_to_shared(Vs);

    // ---- Q tile (once) ----
    for (int i = tid; i < 128 * 16; i += 128) {
        const int row = i >> 4, c4 = i & 15;
        *(float4*)(Qs + row * AST + c4 * 4) =
            *(const float4*)(qg + (size_t)(b * LL + qbase + row) * 1024 + h * 64 + c4 * 4);
    }

    auto issueKV = [&](int t64, int st) {
#pragma unroll
        for (int it = 0; it < 8; it++) {
            const int i = tid + it * 128;
            const int row = i >> 4, c4 = i & 15;
            const size_t gsrc = (size_t)(b * LL + t64 * 64 + row) * 1024 + h * 64 + c4 * 4;
            const uint32_t soff = (st * KVST + row * AST + c4 * 4) * 4;
            CP_ASYNC16_CA(smk + soff, kg + gsrc);
            CP_ASYNC16_CA(smv + soff, vg + gsrc);
        }
    };

    float s[2][8][4];
    float o[2][8][4];
#pragma unroll
    for (int mt = 0; mt < 2; mt++)
#pragma unroll
        for (int n = 0; n < 8; n++)
#pragma unroll
            for (int i = 0; i < 4; i++) o[mt][n][i] = 0.f;
    float mrow[4] = {-1e30f, -1e30f, -1e30f, -1e30f};
    float lrow[4] = {0.f, 0.f, 0.f, 0.f};

    const int ntiles = 2 * qt + 2;
    issueKV(0, 0);
    CP_COMMIT();

    for (int t64 = 0; t64 < ntiles; t64++) {
        const int st = t64 & 1;
        __syncthreads();   // stage st^1 free (prev-prev compute done)
        if (t64 + 1 < ntiles) {
            issueKV(t64 + 1, st ^ 1);
            CP_COMMIT();
            CP_WAIT1();    // stage st data complete
        } else {
            CP_WAIT0();
        }
        __syncthreads();

        const float* Kst = Ks + st * KVST;
        const float* Vst = Vs + st * KVST;
        const int j0 = t64 * 64;

        // ---- S = Q @ K^T ----
#pragma unroll
        for (int mt = 0; mt < 2; mt++)
#pragma unroll
            for (int n = 0; n < 8; n++)
#pragma unroll
                for (int i = 0; i < 4; i++) s[mt][n][i] = 0.f;

#pragma unroll
        for (int kk = 0; kk < 8; kk++) {
            uint32_t qa[2][4];
#pragma unroll
            for (int mt = 0; mt < 2; mt++) {
                const float* qp = Qs + (warp * 32 + mt * 16 + g) * AST + kk * 8 + l4;
                qa[mt][0] = fau(qp[0]);
                qa[mt][2] = fau(qp[4]);
                qa[mt][1] = fau(qp[8 * AST]);
                qa[mt][3] = fau(qp[8 * AST + 4]);
            }
#pragma unroll
            for (int n = 0; n < 8; n++) {
                uint32_t kb[2];
                const float* kp = Kst + (n * 8 + g) * AST + kk * 8 + l4;
                kb[0] = fau(kp[0]);
                kb[1] = fau(kp[4]);
                mma_tf32(s[0][n], qa[0], kb);
                mma_tf32(s[1][n], qa[1], kb);
            }
        }

        if (t64 >= 2 * qt) {
#pragma unroll
            for (int mt = 0; mt < 2; mt++) {
                const int rg = qbase + warp * 32 + mt * 16 + g;
#pragma unroll
                for (int n = 0; n < 8; n++) {
                    const int c0 = j0 + n * 8 + 2 * l4;
                    if (c0     > rg)     s[mt][n][0] = -1e30f;
                    if (c0 + 1 > rg)     s[mt][n][1] = -1e30f;
                    if (c0     > rg + 8) s[mt][n][2] = -1e30f;
                    if (c0 + 1 > rg + 8) s[mt][n][3] = -1e30f;
                }
            }
        }

#pragma unroll
        for (int mt = 0; mt < 2; mt++) {
            float r0 = -1e30f, r1 = -1e30f;
#pragma unroll
            for (int n = 0; n < 8; n++) {
                r0 = fmaxf(r0, fmaxf(s[mt][n][0], s[mt][n][1]));
                r1 = fmaxf(r1, fmaxf(s[mt][n][2], s[mt][n][3]));
            }
            r0 = fmaxf(r0, __shfl_xor_sync(0xffffffffu, r0, 1));
            r0 = fmaxf(r0, __shfl_xor_sync(0xffffffffu, r0, 2));
            r1 = fmaxf(r1, __shfl_xor_sync(0xffffffffu, r1, 1));
            r1 = fmaxf(r1, __shfl_xor_sync(0xffffffffu, r1, 2));
            const float m0 = fmaxf(mrow[2*mt],   r0);
            const float m1 = fmaxf(mrow[2*mt+1], r1);
            const float c0 = __expf(mrow[2*mt]   - m0);
            const float c1 = __expf(mrow[2*mt+1] - m1);
            mrow[2*mt] = m0; mrow[2*mt+1] = m1;
            float ps0 = 0.f, ps1 = 0.f;
#pragma unroll
            for (int n = 0; n < 8; n++) {
                float e0 = __expf(s[mt][n][0] - m0);
                float e1 = __expf(s[mt][n][1] - m0);
                float e2 = __expf(s[mt][n][2] - m1);
                float e3 = __expf(s[mt][n][3] - m1);
                ps0 += e0 + e1; ps1 += e2 + e3;
                uint32_t t0, t1, t2, t3;
                CVT_TF32(t0, e0); CVT_TF32(t1, e1);
                CVT_TF32(t2, e2); CVT_TF32(t3, e3);
                s[mt][n][0] = uaf(t0); s[mt][n][1] = uaf(t1);
                s[mt][n][2] = uaf(t2); s[mt][n][3] = uaf(t3);
                o[mt][n][0] *= c0; o[mt][n][1] *= c0;
                o[mt][n][2] *= c1; o[mt][n][3] *= c1;
            }
            lrow[2*mt]   = lrow[2*mt]   * c0 + ps0;
            lrow[2*mt+1] = lrow[2*mt+1] * c1 + ps1;
        }

        const int srcA = (lane & ~3) | (l4 >> 1);
        const int srcB = srcA + 2;
#pragma unroll
        for (int kk = 0; kk < 8; kk++) {
            uint32_t pa[2][4];
#pragma unroll
            for (int mt = 0; mt < 2; mt++) {
                float c0 = s[mt][kk][0], c1 = s[mt][kk][1];
                float c2 = s[mt][kk][2], c3 = s[mt][kk][3];
                float x0 = __shfl_sync(0xffffffffu, c0, srcA);
                float x1 = __shfl_sync(0xffffffffu, c1, srcA);
                float y0 = __shfl_sync(0xffffffffu, c0, srcB);
                float y1 = __shfl_sync(0xffffffffu, c1, srcB);
                pa[mt][0] = fau((l4 & 1) ? x1 : x0);
                pa[mt][2] = fau((l4 & 1) ? y1 : y0);
                x0 = __shfl_sync(0xffffffffu, c2, srcA);
                x1 = __shfl_sync(0xffffffffu, c3, srcA);
                y0 = __shfl_sync(0xffffffffu, c2, srcB);
                y1 = __shfl_sync(0xffffffffu, c3, srcB);
                pa[mt][1] = fau((l4 & 1) ? x1 : x0);
                pa[mt][3] = fau((l4 & 1) ? y1 : y0);
            }
#pragma unroll
            for (int n = 0; n < 8; n++) {
                uint32_t vb[2];
                const float* vp = Vst + (kk * 8 + l4) * AST + n * 8 + g;
                vb[0] = fau(vp[0]);
                vb[1] = fau(vp[4 * AST]);
                mma_tf32(o[0][n], pa[0], vb);
                mma_tf32(o[1][n], pa[1], vb);
            }
        }
    }

#pragma unroll
    for (int i = 0; i < 4; i++) {
        lrow[i] += __shfl_xor_sync(0xffffffffu, lrow[i], 1);
        lrow[i] += __shfl_xor_sync(0xffffffffu, lrow[i], 2);
        lrow[i] = 1.0f / lrow[i];
    }
#pragma unroll
    for (int mt = 0; mt < 2; mt++) {
        const int rg = b * LL + qbase + warp * 32 + mt * 16 + g;
#pragma unroll
        for (int n = 0; n < 8; n++) {
            const size_t a0 = (size_t)rg * 1024 + h * 64 + n * 8 + 2 * l4;
            uint32_t u0, u1, u2, u3;
            CVT_TF32(u0, o[mt][n][0] * lrow[2*mt]);
            CVT_TF32(u1, o[mt][n][1] * lrow[2*mt]);
            CVT_TF32(u2, o[mt][n][2] * lrow[2*mt+1]);
            CVT_TF32(u3, o[mt][n][3] * lrow[2*mt+1]);
            *(float2*)(og + a0)            = make_float2(uaf(u0), uaf(u1));
            *(float2*)(og + a0 + 8 * 1024) = make_float2(uaf(u2), uaf(u3));
        }
    }
}

// ---------------------------------------------------------------------------
// Launch
// ---------------------------------------------------------------------------
extern "C" void kernel_launch(void* const* d_in, const int* in_sizes, int n_in,
                              void* d_out, int out_size) {
    const float* x     = (const float*)d_in[0];
    const float* gamma = (const float*)d_in[1];
    const float* beta  = (const float*)d_in[2];
    const float* Wq    = (const float*)d_in[3];
    const float* bq    = (const float*)d_in[4];
    const float* Wk    = (const float*)d_in[5];
    const float* bk    = (const float*)d_in[6];
    const float* Wv    = (const float*)d_in[7];
    const float* bv    = (const float*)d_in[8];
    const float* Wo    = (const float*)d_in[9];
    const float* bo    = (const float*)d_in[10];
    float* out = (float*)d_out;

    float* sc = nullptr;
    cudaGetSymbolAddress((void**)&sc, g_scratch);
    float* xn   = sc;
    float* qb   = sc + 1 * (size_t)ELEMS;
    float* kb   = sc + 2 * (size_t)ELEMS;
    float* vb   = sc + 3 * (size_t)ELEMS;
    float* attn = sc + 4 * (size_t)ELEMS;
    float* Wqt  = sc + 5 * (size_t)ELEMS;   // Wqt|Wkt|Wvt contiguous = Wcat
    float* Wkt  = Wqt + (size_t)WELEMS;
    float* Wvt  = Wkt + (size_t)WELEMS;
    float* Wot  = Wvt + (size_t)WELEMS;
    float2* rtab = (float2*)(Wot + (size_t)WELEMS);

    const int attn_smem = (128 + 4 * 64) * AST * sizeof(float);  // 104448
    cudaFuncSetAttribute(attn_tc_kernel,
                         cudaFuncAttributeMaxDynamicSharedMemorySize, attn_smem);
    cudaFuncSetAttribute(qkv_gemm,
                         cudaFuncAttributeMaxDynamicSharedMemorySize, GSMEM);
    cudaFuncSetAttribute(o_gemm,
                         cudaFuncAttributeMaxDynamicSharedMemorySize, GSMEM);

    rope_table_kernel<<<65536 / 256, 256>>>(rtab);
    cvtw_kernel<<<WELEMS / 1024, 256>>>(Wq, Wqt);
    cvtw_kernel<<<WELEMS / 1024, 256>>>(Wk, Wkt);
    cvtw_kernel<<<WELEMS / 1024, 256>>>(Wv, Wvt);
    cvtw_kernel<<<WELEMS / 1024, 256>>>(Wo, Wot);

    ln_kernel<<<MM, 256>>>(x, gamma, beta, xn);

    dim3 qkvgrid(24, 64);
    qkv_gemm<<<qkvgrid, 256, GSMEM>>>(xn, Wqt, bq, bk, bv, rtab, qb);

    dim3 agrid(LL / 128, BB * NH);
    attn_tc_kernel<<<agrid, 128, attn_smem>>>(qb, kb, vb, attn);

    dim3 ogrid(8, 64);
    o_gemm<<<ogrid, 256, GSMEM>>>(attn, Wot, bo, x, out);
}

// round 12
// speedup vs baseline: 1.7715x; 1.3394x over previous
#include <cuda_runtime.h>
#include <cuda_bf16.h>
#include <math.h>
#include <stdint.h>

// Problem constants
#define BB 4
#define LL 2048
#define DM 1024
#define NH 16
#define DH 64
#define MM (BB*LL)          // 8192 rows
#define ELEMS (MM*DM)       // 8388608
#define WELEMS (DM*DM)      // 1048576

// Scratch layout (float units):
// [0)        xn   (bf16, 16MB)
// [1..3)     q,k,v (fp32)
// [4)        attn (bf16, 16MB)
// [5*ELEMS)  4 x Wt bf16 (2*WELEMS floats total), then rope table
__device__ float g_scratch[5 * (size_t)ELEMS + 4 * (size_t)WELEMS + 131072];

#define CVT_TF32(u, f) asm("cvt.rna.tf32.f32 %0, %1;" : "=r"(u) : "f"(f))
#define PACK_BF16X2(r, lo, hi) \
    asm("cvt.rn.bf16x2.f32 %0, %1, %2;" : "=r"(r) : "f"(hi), "f"(lo))
__device__ __forceinline__ uint32_t fau(float f) { return __float_as_uint(f); }
__device__ __forceinline__ float uaf(uint32_t u) { return __uint_as_float(u); }

__device__ __forceinline__ void mma_tf32(float c[4],
                                         const uint32_t a[4],
                                         const uint32_t b[2]) {
    asm volatile(
        "mma.sync.aligned.m16n8k8.row.col.f32.tf32.tf32.f32 "
        "{%0,%1,%2,%3}, {%4,%5,%6,%7}, {%8,%9}, {%0,%1,%2,%3};\n"
        : "+f"(c[0]), "+f"(c[1]), "+f"(c[2]), "+f"(c[3])
        : "r"(a[0]), "r"(a[1]), "r"(a[2]), "r"(a[3]),
          "r"(b[0]), "r"(b[1]));
}

__device__ __forceinline__ void mma_bf16(float c[4],
                                         const uint32_t a[4],
                                         const uint32_t b[2]) {
    asm volatile(
        "mma.sync.aligned.m16n8k16.row.col.f32.bf16.bf16.f32 "
        "{%0,%1,%2,%3}, {%4,%5,%6,%7}, {%8,%9}, {%0,%1,%2,%3};\n"
        : "+f"(c[0]), "+f"(c[1]), "+f"(c[2]), "+f"(c[3])
        : "r"(a[0]), "r"(a[1]), "r"(a[2]), "r"(a[3]),
          "r"(b[0]), "r"(b[1]));
}

#define CP_ASYNC16(dst, src) \
    asm volatile("cp.async.cg.shared.global [%0], [%1], 16;\n" \
                 :: "r"(dst), "l"(src) : "memory")
#define CP_ASYNC16_CA(dst, src) \
    asm volatile("cp.async.ca.shared.global [%0], [%1], 16;\n" \
                 :: "r"(dst), "l"(src) : "memory")
#define CP_COMMIT() asm volatile("cp.async.commit_group;\n" ::: "memory")
#define CP_WAIT1()  asm volatile("cp.async.wait_group 1;\n" ::: "memory")
#define CP_WAIT0()  asm volatile("cp.async.wait_group 0;\n" ::: "memory")

// ---------------------------------------------------------------------------
// Weight prep: fp32 [k][n] -> bf16 transposed [n][k]
// ---------------------------------------------------------------------------
__global__ __launch_bounds__(256) void cvtwt_kernel(const float* __restrict__ src,
                                                    __nv_bfloat16* __restrict__ dst) {
    __shared__ float tile[32][33];
    const int tx = threadIdx.x, ty = threadIdx.y;
    const int bx = blockIdx.x, by = blockIdx.y;
#pragma unroll
    for (int i = 0; i < 4; i++) {
        const int k = by * 32 + ty + i * 8;
        tile[ty + i * 8][tx] = src[(size_t)k * DM + bx * 32 + tx];
    }
    __syncthreads();
#pragma unroll
    for (int i = 0; i < 4; i++) {
        const int n = bx * 32 + ty + i * 8;
        dst[(size_t)n * DM + by * 32 + tx] = __float2bfloat16_rn(tile[tx][ty + i * 8]);
    }
}

// ---------------------------------------------------------------------------
// RoPE cos/sin table
// ---------------------------------------------------------------------------
__global__ __launch_bounds__(256) void rope_table_kernel(float2* __restrict__ t) {
    const int idx = blockIdx.x * 256 + threadIdx.x;   // 65536
    const int l = idx >> 5, p = idx & 31;
    const float inv = exp2f((float)p * (-2.0f / 64.0f) * 13.2877123795494f);
    float s, c;
    sincosf((float)l * inv, &s, &c);
    t[idx] = make_float2(c, s);
}

// ---------------------------------------------------------------------------
// LayerNorm -> bf16 output
// ---------------------------------------------------------------------------
__global__ __launch_bounds__(256) void ln_kernel(const float* __restrict__ x,
                                                 const float* __restrict__ gamma,
                                                 const float* __restrict__ beta,
                                                 __nv_bfloat16* __restrict__ xn) {
    const int row = blockIdx.x;
    const int t = threadIdx.x;
    const float4 v = ((const float4*)(x + (size_t)row * DM))[t];
    __shared__ float red[8];

    float s = v.x + v.y + v.z + v.w;
#pragma unroll
    for (int o = 16; o > 0; o >>= 1) s += __shfl_xor_sync(0xffffffffu, s, o);
    if ((t & 31) == 0) red[t >> 5] = s;
    __syncthreads();
    float mean = (red[0]+red[1]+red[2]+red[3]+red[4]+red[5]+red[6]+red[7]) * (1.0f/DM);

    float dx = v.x-mean, dy = v.y-mean, dz = v.z-mean, dw = v.w-mean;
    float q = dx*dx + dy*dy + dz*dz + dw*dw;
#pragma unroll
    for (int o = 16; o > 0; o >>= 1) q += __shfl_xor_sync(0xffffffffu, q, o);
    __syncthreads();
    if ((t & 31) == 0) red[t >> 5] = q;
    __syncthreads();
    float var = (red[0]+red[1]+red[2]+red[3]+red[4]+red[5]+red[6]+red[7]) * (1.0f/DM);
    float rs = rsqrtf(var + 1e-5f);

    const float4 g4 = ((const float4*)gamma)[t];
    const float4 b4 = ((const float4*)beta)[t];
    uint32_t p0, p1;
    PACK_BF16X2(p0, dx*rs*g4.x + b4.x, dy*rs*g4.y + b4.y);
    PACK_BF16X2(p1, dz*rs*g4.z + b4.z, dw*rs*g4.w + b4.w);
    *(uint2*)((char*)xn + ((size_t)row * DM + 4 * t) * 2) = make_uint2(p0, p1);
}

// ---------------------------------------------------------------------------
// bf16 GEMM core: 128x128x16 tile, 8 warps (2Mx4N), cp.async 3-stage.
// Smem: A/B tiles [128 rows][16 k] bf16, 48B row stride (conflict-free).
// A stage 6144B x3 at 0; B x3 at 18432. Total 36864B.
// ---------------------------------------------------------------------------
#define GSTG 6144
#define GB_BASE 18432
#define GSMEM 36864

struct GemmCore {
    int tid, lane, warp, warpM, warpN, g, l4;
    uint32_t smbase;
    char* smc;
    const __nv_bfloat16* Ab;
    const __nv_bfloat16* Bb;
    float acc[16][4];

    __device__ __forceinline__ void init(char* sm, const __nv_bfloat16* A_,
                                         const __nv_bfloat16* B_) {
        smc = sm;
        tid = threadIdx.x; lane = tid & 31; warp = tid >> 5;
        warpM = warp >> 2; warpN = warp & 3;
        g = lane >> 2; l4 = lane & 3;
        smbase = (uint32_t)__cvta_generic_to_shared(sm);
        Ab = A_; Bb = B_;
#pragma unroll
        for (int i = 0; i < 16; i++)
#pragma unroll
            for (int j = 0; j < 4; j++) acc[i][j] = 0.f;
    }

    __device__ __forceinline__ void issue(int stage, int k0) {
        const int row = tid >> 1, half = tid & 1;
        const uint32_t d0 = smbase + stage * GSTG + row * 48 + half * 16;
        CP_ASYNC16(d0, Ab + (size_t)row * 1024 + k0 + half * 8);
        const uint32_t d1 = smbase + GB_BASE + stage * GSTG + row * 48 + half * 16;
        CP_ASYNC16(d1, Bb + (size_t)row * 1024 + k0 + half * 8);
    }

    __device__ __forceinline__ void compute(int stage) {
        const char* Ast = smc + stage * GSTG;
        const char* Bst = smc + GB_BASE + stage * GSTG;
        uint32_t af[4][4];
        uint32_t bf[4][2];
#pragma unroll
        for (int i = 0; i < 4; i++) {
            const int m = warpM * 64 + i * 16 + g;
            af[i][0] = *(const uint32_t*)(Ast + m * 48 + l4 * 4);
            af[i][1] = *(const uint32_t*)(Ast + (m + 8) * 48 + l4 * 4);
            af[i][2] = *(const uint32_t*)(Ast + m * 48 + 16 + l4 * 4);
            af[i][3] = *(const uint32_t*)(Ast + (m + 8) * 48 + 16 + l4 * 4);
        }
#pragma unroll
        for (int j = 0; j < 4; j++) {
            const int n = warpN * 32 + j * 8 + g;
            bf[j][0] = *(const uint32_t*)(Bst + n * 48 + l4 * 4);
            bf[j][1] = *(const uint32_t*)(Bst + n * 48 + 16 + l4 * 4);
        }
#pragma unroll
        for (int i = 0; i < 4; i++)
#pragma unroll
            for (int j = 0; j < 4; j++)
                mma_bf16(acc[i * 4 + j], af[i], bf[j]);
    }

    __device__ __forceinline__ void mainloop() {
        issue(0, 0);  CP_COMMIT();
        issue(1, 16); CP_COMMIT();
        for (int kt = 0; kt < 64; kt++) {
            CP_WAIT1();
            __syncthreads();
            if (kt + 2 < 64) issue((kt + 2) % 3, (kt + 2) * 16);
            CP_COMMIT();
            compute(kt % 3);
        }
    }
};

// ---------------------------------------------------------------------------
// Merged QKV GEMM: grid (24, 64). Outputs fp32 (tf32-rounded) q/k/v.
// ---------------------------------------------------------------------------
__global__ __launch_bounds__(256) void qkv_gemm(const __nv_bfloat16* __restrict__ xn,
                                                const __nv_bfloat16* __restrict__ Wcat,
                                                const float* __restrict__ bq,
                                                const float* __restrict__ bk,
                                                const float* __restrict__ bv,
                                                const float2* __restrict__ rtab,
                                                float* __restrict__ qkv) {
    extern __shared__ char sm[];
    const int brow = blockIdx.y;
    const int bcol = blockIdx.x;
    const int tsel = bcol >> 3;          // 0=q 1=k 2=v
    const int bcl  = bcol & 7;

    GemmCore core;
    core.init(sm,
              xn + (size_t)brow * 128 * 1024,
              Wcat + (size_t)tsel * WELEMS + (size_t)bcl * 128 * 1024);
    core.mainloop();

    const float* bias = (tsel == 0) ? bq : (tsel == 1) ? bk : bv;
    const bool rope = (tsel < 2);
    const float oscale = (tsel == 0) ? 0.125f : 1.0f;
    float* C = qkv + (size_t)tsel * ELEMS;

#pragma unroll
    for (int i = 0; i < 4; i++) {
        const int r0 = brow * 128 + core.warpM * 64 + i * 16 + core.g;
        const int l0 = r0 & (LL - 1);
#pragma unroll
        for (int j = 0; j < 4; j++) {
            const int cc = bcl * 128 + core.warpN * 32 + j * 8 + (core.l4 << 1);
            const float bx = bias[cc], by = bias[cc + 1];
            float v0x = core.acc[i * 4 + j][0] + bx;
            float v0y = core.acc[i * 4 + j][1] + by;
            float v1x = core.acc[i * 4 + j][2] + bx;
            float v1y = core.acc[i * 4 + j][3] + by;
            if (rope) {
                const int p = (cc & 63) >> 1;
                const float2 cs0 = rtab[l0 * 32 + p];
                const float2 cs1 = rtab[(l0 + 8) * 32 + p];
                float t;
                t   = v0x * cs0.x - v0y * cs0.y;
                v0y = v0x * cs0.y + v0y * cs0.x;
                v0x = t;
                t   = v1x * cs1.x - v1y * cs1.y;
                v1y = v1x * cs1.y + v1y * cs1.x;
                v1x = t;
            }
            uint32_t u0, u1, u2, u3;
            CVT_TF32(u0, v0x * oscale);
            CVT_TF32(u1, v0y * oscale);
            CVT_TF32(u2, v1x * oscale);
            CVT_TF32(u3, v1y * oscale);
            *(float2*)(C + (size_t)r0 * 1024 + cc)       = make_float2(uaf(u0), uaf(u1));
            *(float2*)(C + (size_t)(r0 + 8) * 1024 + cc) = make_float2(uaf(u2), uaf(u3));
        }
    }
}

// ---------------------------------------------------------------------------
// Output projection GEMM: out = attn(bf16) @ Wot^T + bo + x   (fp32 out)
// ---------------------------------------------------------------------------
__global__ __launch_bounds__(256) void o_gemm(const __nv_bfloat16* __restrict__ A,
                                              const __nv_bfloat16* __restrict__ Wt,
                                              const float* __restrict__ bias,
                                              const float* __restrict__ resid,
                                              float* __restrict__ C) {
    extern __shared__ char sm[];
    const int brow = blockIdx.y;
    const int bcol = blockIdx.x;

    GemmCore core;
    core.init(sm, A + (size_t)brow * 128 * 1024, Wt + (size_t)bcol * 128 * 1024);
    core.mainloop();

#pragma unroll
    for (int i = 0; i < 4; i++) {
        const int r0 = brow * 128 + core.warpM * 64 + i * 16 + core.g;
#pragma unroll
        for (int j = 0; j < 4; j++) {
            const int cc = bcol * 128 + core.warpN * 32 + j * 8 + (core.l4 << 1);
            const float bx = bias[cc], by = bias[cc + 1];
            const float2 r0v = *(const float2*)(resid + (size_t)r0 * 1024 + cc);
            const float2 r1v = *(const float2*)(resid + (size_t)(r0 + 8) * 1024 + cc);
            *(float2*)(C + (size_t)r0 * 1024 + cc) =
                make_float2(core.acc[i*4+j][0] + bx + r0v.x,
                            core.acc[i*4+j][1] + by + r0v.y);
            *(float2*)(C + (size_t)(r0 + 8) * 1024 + cc) =
                make_float2(core.acc[i*4+j][2] + bx + r1v.x,
                            core.acc[i*4+j][3] + by + r1v.y);
        }
    }
}

// ---------------------------------------------------------------------------
// Tensor-core flash attention (causal, TF32 mma) — R10 kernel; bf16 output.
// ---------------------------------------------------------------------------
#define AST 68
#define KVST (64 * AST)

__global__ __launch_bounds__(128) void attn_tc_kernel(const float* __restrict__ qg,
                                                      const float* __restrict__ kg,
                                                      const float* __restrict__ vg,
                                                      __nv_bfloat16* __restrict__ og) {
    extern __shared__ float smf[];
    float* Qs = smf;
    float* Ks = smf + 128 * AST;
    float* Vs = Ks + 2 * KVST;

    const int bh = blockIdx.y;
    const int b = bh >> 4, h = bh & 15;
    const int qt = (int)gridDim.x - 1 - (int)blockIdx.x;
    const int qbase = qt * 128;
    const int tid  = threadIdx.x;
    const int lane = tid & 31;
    const int warp = tid >> 5;
    const int g  = lane >> 2;
    const int l4 = lane & 3;

    const uint32_t smk = (uint32_t)__cvta_generic_to_shared(Ks);
    const uint32_t smv = (uint32_t)__cvta_generic_to_shared(Vs);

    for (int i = tid; i < 128 * 16; i += 128) {
        const int row = i >> 4, c4 = i & 15;
        *(float4*)(Qs + row * AST + c4 * 4) =
            *(const float4*)(qg + (size_t)(b * LL + qbase + row) * 1024 + h * 64 + c4 * 4);
    }

    auto issueKV = [&](int t64, int st) {
#pragma unroll
        for (int it = 0; it < 8; it++) {
            const int i = tid + it * 128;
            const int row = i >> 4, c4 = i & 15;
            const size_t gsrc = (size_t)(b * LL + t64 * 64 + row) * 1024 + h * 64 + c4 * 4;
            const uint32_t soff = (st * KVST + row * AST + c4 * 4) * 4;
            CP_ASYNC16_CA(smk + soff, kg + gsrc);
            CP_ASYNC16_CA(smv + soff, vg + gsrc);
        }
    };

    float s[2][8][4];
    float o[2][8][4];
#pragma unroll
    for (int mt = 0; mt < 2; mt++)
#pragma unroll
        for (int n = 0; n < 8; n++)
#pragma unroll
            for (int i = 0; i < 4; i++) o[mt][n][i] = 0.f;
    float mrow[4] = {-1e30f, -1e30f, -1e30f, -1e30f};
    float lrow[4] = {0.f, 0.f, 0.f, 0.f};

    const int ntiles = 2 * qt + 2;
    issueKV(0, 0);
    CP_COMMIT();

    for (int t64 = 0; t64 < ntiles; t64++) {
        const int st = t64 & 1;
        __syncthreads();
        if (t64 + 1 < ntiles) {
            issueKV(t64 + 1, st ^ 1);
            CP_COMMIT();
            CP_WAIT1();
        } else {
            CP_WAIT0();
        }
        __syncthreads();

        const float* Kst = Ks + st * KVST;
        const float* Vst = Vs + st * KVST;
        const int j0 = t64 * 64;

#pragma unroll
        for (int mt = 0; mt < 2; mt++)
#pragma unroll
            for (int n = 0; n < 8; n++)
#pragma unroll
                for (int i = 0; i < 4; i++) s[mt][n][i] = 0.f;

#pragma unroll
        for (int kk = 0; kk < 8; kk++) {
            uint32_t qa[2][4];
#pragma unroll
            for (int mt = 0; mt < 2; mt++) {
                const float* qp = Qs + (warp * 32 + mt * 16 + g) * AST + kk * 8 + l4;
                qa[mt][0] = fau(qp[0]);
                qa[mt][2] = fau(qp[4]);
                qa[mt][1] = fau(qp[8 * AST]);
                qa[mt][3] = fau(qp[8 * AST + 4]);
            }
#pragma unroll
            for (int n = 0; n < 8; n++) {
                uint32_t kb[2];
                const float* kp = Kst + (n * 8 + g) * AST + kk * 8 + l4;
                kb[0] = fau(kp[0]);
                kb[1] = fau(kp[4]);
                mma_tf32(s[0][n], qa[0], kb);
                mma_tf32(s[1][n], qa[1], kb);
            }
        }

        if (t64 >= 2 * qt) {
#pragma unroll
            for (int mt = 0; mt < 2; mt++) {
                const int rg = qbase + warp * 32 + mt * 16 + g;
#pragma unroll
                for (int n = 0; n < 8; n++) {
                    const int c0 = j0 + n * 8 + 2 * l4;
                    if (c0     > rg)     s[mt][n][0] = -1e30f;
                    if (c0 + 1 > rg)     s[mt][n][1] = -1e30f;
                    if (c0     > rg + 8) s[mt][n][2] = -1e30f;
                    if (c0 + 1 > rg + 8) s[mt][n][3] = -1e30f;
                }
            }
        }

#pragma unroll
        for (int mt = 0; mt < 2; mt++) {
            float r0 = -1e30f, r1 = -1e30f;
#pragma unroll
            for (int n = 0; n < 8; n++) {
                r0 = fmaxf(r0, fmaxf(s[mt][n][0], s[mt][n][1]));
                r1 = fmaxf(r1, fmaxf(s[mt][n][2], s[mt][n][3]));
            }
            r0 = fmaxf(r0, __shfl_xor_sync(0xffffffffu, r0, 1));
            r0 = fmaxf(r0, __shfl_xor_sync(0xffffffffu, r0, 2));
            r1 = fmaxf(r1, __shfl_xor_sync(0xffffffffu, r1, 1));
            r1 = fmaxf(r1, __shfl_xor_sync(0xffffffffu, r1, 2));
            const float m0 = fmaxf(mrow[2*mt],   r0);
            const float m1 = fmaxf(mrow[2*mt+1], r1);
            const float c0 = __expf(mrow[2*mt]   - m0);
            const float c1 = __expf(mrow[2*mt+1] - m1);
            mrow[2*mt] = m0; mrow[2*mt+1] = m1;
            float ps0 = 0.f, ps1 = 0.f;
#pragma unroll
            for (int n = 0; n < 8; n++) {
                float e0 = __expf(s[mt][n][0] - m0);
                float e1 = __expf(s[mt][n][1] - m0);
                float e2 = __expf(s[mt][n][2] - m1);
                float e3 = __expf(s[mt][n][3] - m1);
                ps0 += e0 + e1; ps1 += e2 + e3;
                uint32_t t0, t1, t2, t3;
                CVT_TF32(t0, e0); CVT_TF32(t1, e1);
                CVT_TF32(t2, e2); CVT_TF32(t3, e3);
                s[mt][n][0] = uaf(t0); s[mt][n][1] = uaf(t1);
                s[mt][n][2] = uaf(t2); s[mt][n][3] = uaf(t3);
                o[mt][n][0] *= c0; o[mt][n][1] *= c0;
                o[mt][n][2] *= c1; o[mt][n][3] *= c1;
            }
            lrow[2*mt]   = lrow[2*mt]   * c0 + ps0;
            lrow[2*mt+1] = lrow[2*mt+1] * c1 + ps1;
        }

        const int srcA = (lane & ~3) | (l4 >> 1);
        const int srcB = srcA + 2;
#pragma unroll
        for (int kk = 0; kk < 8; kk++) {
            uint32_t pa[2][4];
#pragma unroll
            for (int mt = 0; mt < 2; mt++) {
                float c0 = s[mt][kk][0], c1 = s[mt][kk][1];
                float c2 = s[mt][kk][2], c3 = s[mt][kk][3];
                float x0 = __shfl_sync(0xffffffffu, c0, srcA);
                float x1 = __shfl_sync(0xffffffffu, c1, srcA);
                float y0 = __shfl_sync(0xffffffffu, c0, srcB);
                float y1 = __shfl_sync(0xffffffffu, c1, srcB);
                pa[mt][0] = fau((l4 & 1) ? x1 : x0);
                pa[mt][2] = fau((l4 & 1) ? y1 : y0);
                x0 = __shfl_sync(0xffffffffu, c2, srcA);
                x1 = __shfl_sync(0xffffffffu, c3, srcA);
                y0 = __shfl_sync(0xffffffffu, c2, srcB);
                y1 = __shfl_sync(0xffffffffu, c3, srcB);
                pa[mt][1] = fau((l4 & 1) ? x1 : x0);
                pa[mt][3] = fau((l4 & 1) ? y1 : y0);
            }
#pragma unroll
            for (int n = 0; n < 8; n++) {
                uint32_t vb[2];
                const float* vp = Vst + (kk * 8 + l4) * AST + n * 8 + g;
                vb[0] = fau(vp[0]);
                vb[1] = fau(vp[4 * AST]);
                mma_tf32(o[0][n], pa[0], vb);
                mma_tf32(o[1][n], pa[1], vb);
            }
        }
    }

#pragma unroll
    for (int i = 0; i < 4; i++) {
        lrow[i] += __shfl_xor_sync(0xffffffffu, lrow[i], 1);
        lrow[i] += __shfl_xor_sync(0xffffffffu, lrow[i], 2);
        lrow[i] = 1.0f / lrow[i];
    }
#pragma unroll
    for (int mt = 0; mt < 2; mt++) {
        const int rg = b * LL + qbase + warp * 32 + mt * 16 + g;
#pragma unroll
        for (int n = 0; n < 8; n++) {
            const size_t a0 = (size_t)rg * 1024 + h * 64 + n * 8 + 2 * l4;
            uint32_t p0, p1;
            PACK_BF16X2(p0, o[mt][n][0] * lrow[2*mt],   o[mt][n][1] * lrow[2*mt]);
            PACK_BF16X2(p1, o[mt][n][2] * lrow[2*mt+1], o[mt][n][3] * lrow[2*mt+1]);
            *(uint32_t*)((char*)og + a0 * 2)              = p0;
            *(uint32_t*)((char*)og + (a0 + 8 * 1024) * 2) = p1;
        }
    }
}

// ---------------------------------------------------------------------------
// Launch
// ---------------------------------------------------------------------------
extern "C" void kernel_launch(void* const* d_in, const int* in_sizes, int n_in,
                              void* d_out, int out_size) {
    const float* x     = (const float*)d_in[0];
    const float* gamma = (const float*)d_in[1];
    const float* beta  = (const float*)d_in[2];
    const float* Wq    = (const float*)d_in[3];
    const float* bq    = (const float*)d_in[4];
    const float* Wk    = (const float*)d_in[5];
    const float* bk    = (const float*)d_in[6];
    const float* Wv    = (const float*)d_in[7];
    const float* bv    = (const float*)d_in[8];
    const float* Wo    = (const float*)d_in[9];
    const float* bo    = (const float*)d_in[10];
    float* out = (float*)d_out;

    float* sc = nullptr;
    cudaGetSymbolAddress((void**)&sc, g_scratch);
    __nv_bfloat16* xn = (__nv_bfloat16*)sc;
    float* qb   = sc + 1 * (size_t)ELEMS;
    float* kb   = sc + 2 * (size_t)ELEMS;
    float* vb   = sc + 3 * (size_t)ELEMS;
    __nv_bfloat16* attn = (__nv_bfloat16*)(sc + 4 * (size_t)ELEMS);
    __nv_bfloat16* Wqt = (__nv_bfloat16*)(sc + 5 * (size_t)ELEMS);  // contig
    __nv_bfloat16* Wkt = Wqt + (size_t)WELEMS;
    __nv_bfloat16* Wvt = Wkt + (size_t)WELEMS;
    __nv_bfloat16* Wot = Wvt + (size_t)WELEMS;
    float2* rtab = (float2*)(sc + 5 * (size_t)ELEMS + 2 * (size_t)WELEMS);

    const int attn_smem = (128 + 4 * 64) * AST * sizeof(float);  // 104448
    cudaFuncSetAttribute(attn_tc_kernel,
                         cudaFuncAttributeMaxDynamicSharedMemorySize, attn_smem);
    cudaFuncSetAttribute(qkv_gemm,
                         cudaFuncAttributeMaxDynamicSharedMemorySize, GSMEM);
    cudaFuncSetAttribute(o_gemm,
                         cudaFuncAttributeMaxDynamicSharedMemorySize, GSMEM);

    rope_table_kernel<<<65536 / 256, 256>>>(rtab);
    dim3 tgrid(32, 32), tblk(32, 8);
    cvtwt_kernel<<<tgrid, tblk>>>(Wq, Wqt);
    cvtwt_kernel<<<tgrid, tblk>>>(Wk, Wkt);
    cvtwt_kernel<<<tgrid, tblk>>>(Wv, Wvt);
    cvtwt_kernel<<<tgrid, tblk>>>(Wo, Wot);

    ln_kernel<<<MM, 256>>>(x, gamma, beta, xn);

    dim3 qkvgrid(24, 64);
    qkv_gemm<<<qkvgrid, 256, GSMEM>>>(xn, Wqt, bq, bk, bv, rtab, qb);

    dim3 agrid(LL / 128, BB * NH);
    attn_tc_kernel<<<agrid, 128, attn_smem>>>(qb, kb, vb, attn);

    dim3 ogrid(8, 64);
    o_gemm<<<ogrid, 256, GSMEM>>>(attn, Wot, bo, x, out);
}

// round 13
// speedup vs baseline: 2.2608x; 1.2762x over previous
#include <cuda_runtime.h>
#include <cuda_bf16.h>
#include <math.h>
#include <stdint.h>

// Problem constants
#define BB 4
#define LL 2048
#define DM 1024
#define NH 16
#define DH 64
#define MM (BB*LL)          // 8192 rows
#define ELEMS (MM*DM)       // 8388608
#define WELEMS (DM*DM)      // 1048576

// Scratch (float units): xn bf16 @0, q bf16 @1E, k bf16 @2E, vt bf16 @3E,
// attn bf16 @4E, weights bf16 @5E (2*WELEMS floats), rope table after.
__device__ float g_scratch[5 * (size_t)ELEMS + 4 * (size_t)WELEMS + 131072];

#define PACK_BF16X2(r, lo, hi) \
    asm("cvt.rn.bf16x2.f32 %0, %1, %2;" : "=r"(r) : "f"(hi), "f"(lo))
__device__ __forceinline__ uint32_t fau(float f) { return __float_as_uint(f); }
__device__ __forceinline__ float uaf(uint32_t u) { return __uint_as_float(u); }

__device__ __forceinline__ void mma_bf16(float c[4],
                                         const uint32_t a[4],
                                         const uint32_t b[2]) {
    asm volatile(
        "mma.sync.aligned.m16n8k16.row.col.f32.bf16.bf16.f32 "
        "{%0,%1,%2,%3}, {%4,%5,%6,%7}, {%8,%9}, {%0,%1,%2,%3};\n"
        : "+f"(c[0]), "+f"(c[1]), "+f"(c[2]), "+f"(c[3])
        : "r"(a[0]), "r"(a[1]), "r"(a[2]), "r"(a[3]),
          "r"(b[0]), "r"(b[1]));
}

#define CP_ASYNC16(dst, src) \
    asm volatile("cp.async.cg.shared.global [%0], [%1], 16;\n" \
                 :: "r"(dst), "l"(src) : "memory")
#define CP_ASYNC16_CA(dst, src) \
    asm volatile("cp.async.ca.shared.global [%0], [%1], 16;\n" \
                 :: "r"(dst), "l"(src) : "memory")
#define CP_COMMIT() asm volatile("cp.async.commit_group;\n" ::: "memory")
#define CP_WAIT1()  asm volatile("cp.async.wait_group 1;\n" ::: "memory")
#define CP_WAIT0()  asm volatile("cp.async.wait_group 0;\n" ::: "memory")

// ---------------------------------------------------------------------------
// Weight prep: fp32 [k][n] -> bf16 transposed [n][k]
// ---------------------------------------------------------------------------
__global__ __launch_bounds__(256) void cvtwt_kernel(const float* __restrict__ src,
                                                    __nv_bfloat16* __restrict__ dst) {
    __shared__ float tile[32][33];
    const int tx = threadIdx.x, ty = threadIdx.y;
    const int bx = blockIdx.x, by = blockIdx.y;
#pragma unroll
    for (int i = 0; i < 4; i++) {
        const int k = by * 32 + ty + i * 8;
        tile[ty + i * 8][tx] = src[(size_t)k * DM + bx * 32 + tx];
    }
    __syncthreads();
#pragma unroll
    for (int i = 0; i < 4; i++) {
        const int n = bx * 32 + ty + i * 8;
        dst[(size_t)n * DM + by * 32 + tx] = __float2bfloat16_rn(tile[tx][ty + i * 8]);
    }
}

// ---------------------------------------------------------------------------
// RoPE cos/sin table
// ---------------------------------------------------------------------------
__global__ __launch_bounds__(256) void rope_table_kernel(float2* __restrict__ t) {
    const int idx = blockIdx.x * 256 + threadIdx.x;   // 65536
    const int l = idx >> 5, p = idx & 31;
    const float inv = exp2f((float)p * (-2.0f / 64.0f) * 13.2877123795494f);
    float s, c;
    sincosf((float)l * inv, &s, &c);
    t[idx] = make_float2(c, s);
}

// ---------------------------------------------------------------------------
// LayerNorm -> bf16
// ---------------------------------------------------------------------------
__global__ __launch_bounds__(256) void ln_kernel(const float* __restrict__ x,
                                                 const float* __restrict__ gamma,
                                                 const float* __restrict__ beta,
                                                 __nv_bfloat16* __restrict__ xn) {
    const int row = blockIdx.x;
    const int t = threadIdx.x;
    const float4 v = ((const float4*)(x + (size_t)row * DM))[t];
    __shared__ float red[8];

    float s = v.x + v.y + v.z + v.w;
#pragma unroll
    for (int o = 16; o > 0; o >>= 1) s += __shfl_xor_sync(0xffffffffu, s, o);
    if ((t & 31) == 0) red[t >> 5] = s;
    __syncthreads();
    float mean = (red[0]+red[1]+red[2]+red[3]+red[4]+red[5]+red[6]+red[7]) * (1.0f/DM);

    float dx = v.x-mean, dy = v.y-mean, dz = v.z-mean, dw = v.w-mean;
    float q = dx*dx + dy*dy + dz*dz + dw*dw;
#pragma unroll
    for (int o = 16; o > 0; o >>= 1) q += __shfl_xor_sync(0xffffffffu, q, o);
    __syncthreads();
    if ((t & 31) == 0) red[t >> 5] = q;
    __syncthreads();
    float var = (red[0]+red[1]+red[2]+red[3]+red[4]+red[5]+red[6]+red[7]) * (1.0f/DM);
    float rs = rsqrtf(var + 1e-5f);

    const float4 g4 = ((const float4*)gamma)[t];
    const float4 b4 = ((const float4*)beta)[t];
    uint32_t p0, p1;
    PACK_BF16X2(p0, dx*rs*g4.x + b4.x, dy*rs*g4.y + b4.y);
    PACK_BF16X2(p1, dz*rs*g4.z + b4.z, dw*rs*g4.w + b4.w);
    *(uint2*)((char*)xn + ((size_t)row * DM + 4 * t) * 2) = make_uint2(p0, p1);
}

// ---------------------------------------------------------------------------
// bf16 GEMM core (R12, validated): 128x128x16, 8 warps, 3-stage cp.async.
// ---------------------------------------------------------------------------
#define GSTG 6144
#define GB_BASE 18432
#define GSMEM 36864

struct GemmCore {
    int tid, lane, warp, warpM, warpN, g, l4;
    uint32_t smbase;
    char* smc;
    const __nv_bfloat16* Ab;
    const __nv_bfloat16* Bb;
    float acc[16][4];

    __device__ __forceinline__ void init(char* sm, const __nv_bfloat16* A_,
                                         const __nv_bfloat16* B_) {
        smc = sm;
        tid = threadIdx.x; lane = tid & 31; warp = tid >> 5;
        warpM = warp >> 2; warpN = warp & 3;
        g = lane >> 2; l4 = lane & 3;
        smbase = (uint32_t)__cvta_generic_to_shared(sm);
        Ab = A_; Bb = B_;
#pragma unroll
        for (int i = 0; i < 16; i++)
#pragma unroll
            for (int j = 0; j < 4; j++) acc[i][j] = 0.f;
    }

    __device__ __forceinline__ void issue(int stage, int k0) {
        const int row = tid >> 1, half = tid & 1;
        CP_ASYNC16(smbase + stage * GSTG + row * 48 + half * 16,
                   Ab + (size_t)row * 1024 + k0 + half * 8);
        CP_ASYNC16(smbase + GB_BASE + stage * GSTG + row * 48 + half * 16,
                   Bb + (size_t)row * 1024 + k0 + half * 8);
    }

    __device__ __forceinline__ void compute(int stage) {
        const char* Ast = smc + stage * GSTG;
        const char* Bst = smc + GB_BASE + stage * GSTG;
        uint32_t af[4][4];
        uint32_t bf[4][2];
#pragma unroll
        for (int i = 0; i < 4; i++) {
            const int m = warpM * 64 + i * 16 + g;
            af[i][0] = *(const uint32_t*)(Ast + m * 48 + l4 * 4);
            af[i][1] = *(const uint32_t*)(Ast + (m + 8) * 48 + l4 * 4);
            af[i][2] = *(const uint32_t*)(Ast + m * 48 + 16 + l4 * 4);
            af[i][3] = *(const uint32_t*)(Ast + (m + 8) * 48 + 16 + l4 * 4);
        }
#pragma unroll
        for (int j = 0; j < 4; j++) {
            const int n = warpN * 32 + j * 8 + g;
            bf[j][0] = *(const uint32_t*)(Bst + n * 48 + l4 * 4);
            bf[j][1] = *(const uint32_t*)(Bst + n * 48 + 16 + l4 * 4);
        }
#pragma unroll
        for (int i = 0; i < 4; i++)
#pragma unroll
            for (int j = 0; j < 4; j++)
                mma_bf16(acc[i * 4 + j], af[i], bf[j]);
    }

    __device__ __forceinline__ void mainloop() {
        issue(0, 0);  CP_COMMIT();
        issue(1, 16); CP_COMMIT();
        for (int kt = 0; kt < 64; kt++) {
            CP_WAIT1();
            __syncthreads();
            if (kt + 2 < 64) issue((kt + 2) % 3, (kt + 2) * 16);
            CP_COMMIT();
            compute(kt % 3);
        }
    }
};

// ---------------------------------------------------------------------------
// Merged QKV GEMM: outputs q,k bf16 [seq][1024] (roped, q scaled 1/8);
// v bf16 TRANSPOSED [bh][d][seq].
// ---------------------------------------------------------------------------
__global__ __launch_bounds__(256) void qkv_gemm(const __nv_bfloat16* __restrict__ xn,
                                                const __nv_bfloat16* __restrict__ Wcat,
                                                const float* __restrict__ bq,
                                                const float* __restrict__ bk,
                                                const float* __restrict__ bv,
                                                const float2* __restrict__ rtab,
                                                __nv_bfloat16* __restrict__ qb,
                                                __nv_bfloat16* __restrict__ kb,
                                                __nv_bfloat16* __restrict__ vt) {
    extern __shared__ char sm[];
    const int brow = blockIdx.y;
    const int bcol = blockIdx.x;
    const int tsel = bcol >> 3;          // 0=q 1=k 2=v
    const int bcl  = bcol & 7;

    GemmCore core;
    core.init(sm,
              xn + (size_t)brow * 128 * 1024,
              Wcat + (size_t)tsel * WELEMS + (size_t)bcl * 128 * 1024);
    core.mainloop();

    const float* bias = (tsel == 0) ? bq : (tsel == 1) ? bk : bv;
    const float oscale = (tsel == 0) ? 0.125f : 1.0f;

#pragma unroll
    for (int i = 0; i < 4; i++) {
        const int r0 = brow * 128 + core.warpM * 64 + i * 16 + core.g;
        const int l0 = r0 & (LL - 1);
        const int bidx = r0 >> 11;
#pragma unroll
        for (int j = 0; j < 4; j++) {
            const int cc = bcl * 128 + core.warpN * 32 + j * 8 + (core.l4 << 1);
            const float bx = bias[cc], by = bias[cc + 1];
            float v0x = core.acc[i * 4 + j][0] + bx;
            float v0y = core.acc[i * 4 + j][1] + by;
            float v1x = core.acc[i * 4 + j][2] + bx;
            float v1y = core.acc[i * 4 + j][3] + by;
            if (tsel < 2) {
                const int p = (cc & 63) >> 1;
                const float2 cs0 = rtab[l0 * 32 + p];
                const float2 cs1 = rtab[(l0 + 8) * 32 + p];
                float t;
                t   = v0x * cs0.x - v0y * cs0.y;
                v0y = v0x * cs0.y + v0y * cs0.x;
                v0x = t;
                t   = v1x * cs1.x - v1y * cs1.y;
                v1y = v1x * cs1.y + v1y * cs1.x;
                v1x = t;
                uint32_t p0, p1;
                PACK_BF16X2(p0, v0x * oscale, v0y * oscale);
                PACK_BF16X2(p1, v1x * oscale, v1y * oscale);
                __nv_bfloat16* C = (tsel == 0) ? qb : kb;
                *(uint32_t*)((char*)C + ((size_t)r0 * 1024 + cc) * 2)       = p0;
                *(uint32_t*)((char*)C + ((size_t)(r0 + 8) * 1024 + cc) * 2) = p1;
            } else {
                // transpose scatter: vt[(b*16+h)*64 + d][seq]
                const int h = cc >> 6, d = cc & 63;
                __nv_bfloat16* row0 = vt + ((size_t)(bidx * 16 + h) * 64 + d) * LL;
                __nv_bfloat16* row1 = row0 + LL;   // d+1
                row0[l0]     = __float2bfloat16_rn(v0x);
                row1[l0]     = __float2bfloat16_rn(v0y);
                row0[l0 + 8] = __float2bfloat16_rn(v1x);
                row1[l0 + 8] = __float2bfloat16_rn(v1y);
            }
        }
    }
}

// ---------------------------------------------------------------------------
// Output projection GEMM: out = attn(bf16) @ Wot^T + bo + x   (fp32 out)
// ---------------------------------------------------------------------------
__global__ __launch_bounds__(256) void o_gemm(const __nv_bfloat16* __restrict__ A,
                                              const __nv_bfloat16* __restrict__ Wt,
                                              const float* __restrict__ bias,
                                              const float* __restrict__ resid,
                                              float* __restrict__ C) {
    extern __shared__ char sm[];
    const int brow = blockIdx.y;
    const int bcol = blockIdx.x;

    GemmCore core;
    core.init(sm, A + (size_t)brow * 128 * 1024, Wt + (size_t)bcol * 128 * 1024);
    core.mainloop();

#pragma unroll
    for (int i = 0; i < 4; i++) {
        const int r0 = brow * 128 + core.warpM * 64 + i * 16 + core.g;
#pragma unroll
        for (int j = 0; j < 4; j++) {
            const int cc = bcol * 128 + core.warpN * 32 + j * 8 + (core.l4 << 1);
            const float bx = bias[cc], by = bias[cc + 1];
            const float2 r0v = *(const float2*)(resid + (size_t)r0 * 1024 + cc);
            const float2 r1v = *(const float2*)(resid + (size_t)(r0 + 8) * 1024 + cc);
            *(float2*)(C + (size_t)r0 * 1024 + cc) =
                make_float2(core.acc[i*4+j][0] + bx + r0v.x,
                            core.acc[i*4+j][1] + by + r0v.y);
            *(float2*)(C + (size_t)(r0 + 8) * 1024 + cc) =
                make_float2(core.acc[i*4+j][2] + bx + r1v.x,
                            core.acc[i*4+j][3] + by + r1v.y);
        }
    }
}

// ---------------------------------------------------------------------------
// bf16 tensor-core flash attention (causal). Q/K [seq][d] bf16, V [d][seq] bf16.
// Smem rows 144B stride (bank 4g+l4: conflict-free). Double-buffered KV.
// ---------------------------------------------------------------------------
#define QROW 144
#define KV_STG (64 * QROW)        // 9216 bytes per stage
#define SK_BASE 18432             // after Q (128*144)
#define SV_BASE (SK_BASE + 2 * KV_STG)
#define ASMEM (SV_BASE + 2 * KV_STG)   // 55296

__global__ __launch_bounds__(128) void attn_tc_kernel(const __nv_bfloat16* __restrict__ qg,
                                                      const __nv_bfloat16* __restrict__ kg,
                                                      const __nv_bfloat16* __restrict__ vt,
                                                      __nv_bfloat16* __restrict__ og) {
    extern __shared__ char sma[];
    const uint32_t smbase = (uint32_t)__cvta_generic_to_shared(sma);

    const int bh = blockIdx.y;
    const int b = bh >> 4, h = bh & 15;
    const int qt = (int)gridDim.x - 1 - (int)blockIdx.x;
    const int qbase = qt * 128;
    const int tid  = threadIdx.x;
    const int lane = tid & 31;
    const int warp = tid >> 5;
    const int g  = lane >> 2;
    const int l4 = lane & 3;

    // ---- Q tile: 128 rows x 64 bf16 (8 chunks/row) ----
#pragma unroll
    for (int it = 0; it < 8; it++) {
        const int i = tid + it * 128;
        const int row = i >> 3, c = i & 7;
        CP_ASYNC16_CA(smbase + row * QROW + c * 16,
                      qg + (size_t)(b * LL + qbase + row) * 1024 + h * 64 + c * 8);
    }

    auto issueKV = [&](int t64, int st) {
#pragma unroll
        for (int it = 0; it < 4; it++) {
            const int i = tid + it * 128;
            const int row = i >> 3, c = i & 7;
            CP_ASYNC16_CA(smbase + SK_BASE + st * KV_STG + row * QROW + c * 16,
                          kg + (size_t)(b * LL + t64 * 64 + row) * 1024 + h * 64 + c * 8);
            CP_ASYNC16_CA(smbase + SV_BASE + st * KV_STG + row * QROW + c * 16,
                          vt + ((size_t)(bh * 64 + row)) * LL + t64 * 64 + c * 8);
        }
    };

    float s[2][8][4];
    float o[2][8][4];
#pragma unroll
    for (int mt = 0; mt < 2; mt++)
#pragma unroll
        for (int n = 0; n < 8; n++)
#pragma unroll
            for (int i = 0; i < 4; i++) o[mt][n][i] = 0.f;
    float mrow[4] = {-1e30f, -1e30f, -1e30f, -1e30f};
    float lrow[4] = {0.f, 0.f, 0.f, 0.f};

    const int ntiles = 2 * qt + 2;
    issueKV(0, 0);
    CP_COMMIT();

    for (int t64 = 0; t64 < ntiles; t64++) {
        const int st = t64 & 1;
        __syncthreads();
        if (t64 + 1 < ntiles) {
            issueKV(t64 + 1, st ^ 1);
            CP_COMMIT();
            CP_WAIT1();
        } else {
            CP_WAIT0();
        }
        __syncthreads();

        const char* Kst = sma + SK_BASE + st * KV_STG;
        const char* Vst = sma + SV_BASE + st * KV_STG;
        const int j0 = t64 * 64;

        // ---- S = Q @ K^T (bf16 k16) ----
#pragma unroll
        for (int mt = 0; mt < 2; mt++)
#pragma unroll
            for (int n = 0; n < 8; n++)
#pragma unroll
                for (int i = 0; i < 4; i++) s[mt][n][i] = 0.f;

#pragma unroll
        for (int kk = 0; kk < 4; kk++) {
            uint32_t qa[2][4];
#pragma unroll
            for (int mt = 0; mt < 2; mt++) {
                const char* qp = sma + (warp * 32 + mt * 16 + g) * QROW + kk * 32 + l4 * 4;
                qa[mt][0] = *(const uint32_t*)(qp);
                qa[mt][1] = *(const uint32_t*)(qp + 8 * QROW);
                qa[mt][2] = *(const uint32_t*)(qp + 16);
                qa[mt][3] = *(const uint32_t*)(qp + 8 * QROW + 16);
            }
#pragma unroll
            for (int n = 0; n < 8; n++) {
                uint32_t kb[2];
                const char* kp = Kst + (n * 8 + g) * QROW + kk * 32 + l4 * 4;
                kb[0] = *(const uint32_t*)(kp);
                kb[1] = *(const uint32_t*)(kp + 16);
                mma_bf16(s[0][n], qa[0], kb);
                mma_bf16(s[1][n], qa[1], kb);
            }
        }

        // ---- causal mask ----
        if (t64 >= 2 * qt) {
#pragma unroll
            for (int mt = 0; mt < 2; mt++) {
                const int rg = qbase + warp * 32 + mt * 16 + g;
#pragma unroll
                for (int n = 0; n < 8; n++) {
                    const int c0 = j0 + n * 8 + 2 * l4;
                    if (c0     > rg)     s[mt][n][0] = -1e30f;
                    if (c0 + 1 > rg)     s[mt][n][1] = -1e30f;
                    if (c0     > rg + 8) s[mt][n][2] = -1e30f;
                    if (c0 + 1 > rg + 8) s[mt][n][3] = -1e30f;
                }
            }
        }

        // ---- online softmax ----
#pragma unroll
        for (int mt = 0; mt < 2; mt++) {
            float r0 = -1e30f, r1 = -1e30f;
#pragma unroll
            for (int n = 0; n < 8; n++) {
                r0 = fmaxf(r0, fmaxf(s[mt][n][0], s[mt][n][1]));
                r1 = fmaxf(r1, fmaxf(s[mt][n][2], s[mt][n][3]));
            }
            r0 = fmaxf(r0, __shfl_xor_sync(0xffffffffu, r0, 1));
            r0 = fmaxf(r0, __shfl_xor_sync(0xffffffffu, r0, 2));
            r1 = fmaxf(r1, __shfl_xor_sync(0xffffffffu, r1, 1));
            r1 = fmaxf(r1, __shfl_xor_sync(0xffffffffu, r1, 2));
            const float m0 = fmaxf(mrow[2*mt],   r0);
            const float m1 = fmaxf(mrow[2*mt+1], r1);
            const float c0 = __expf(mrow[2*mt]   - m0);
            const float c1 = __expf(mrow[2*mt+1] - m1);
            mrow[2*mt] = m0; mrow[2*mt+1] = m1;
            float ps0 = 0.f, ps1 = 0.f;
#pragma unroll
            for (int n = 0; n < 8; n++) {
                s[mt][n][0] = __expf(s[mt][n][0] - m0);
                s[mt][n][1] = __expf(s[mt][n][1] - m0);
                s[mt][n][2] = __expf(s[mt][n][2] - m1);
                s[mt][n][3] = __expf(s[mt][n][3] - m1);
                ps0 += s[mt][n][0] + s[mt][n][1];
                ps1 += s[mt][n][2] + s[mt][n][3];
                o[mt][n][0] *= c0; o[mt][n][1] *= c0;
                o[mt][n][2] *= c1; o[mt][n][3] *= c1;
            }
            lrow[2*mt]   = lrow[2*mt]   * c0 + ps0;
            lrow[2*mt+1] = lrow[2*mt+1] * c1 + ps1;
        }

        // ---- O += P @ V (P packs directly into A-fragments; Vt rows = d) ----
#pragma unroll
        for (int kk = 0; kk < 4; kk++) {
            uint32_t pa[2][4];
#pragma unroll
            for (int mt = 0; mt < 2; mt++) {
                PACK_BF16X2(pa[mt][0], s[mt][2*kk][0],     s[mt][2*kk][1]);
                PACK_BF16X2(pa[mt][1], s[mt][2*kk][2],     s[mt][2*kk][3]);
                PACK_BF16X2(pa[mt][2], s[mt][2*kk+1][0],   s[mt][2*kk+1][1]);
                PACK_BF16X2(pa[mt][3], s[mt][2*kk+1][2],   s[mt][2*kk+1][3]);
            }
#pragma unroll
            for (int nd = 0; nd < 8; nd++) {
                uint32_t vb[2];
                const char* vp = Vst + (nd * 8 + g) * QROW + kk * 32 + l4 * 4;
                vb[0] = *(const uint32_t*)(vp);
                vb[1] = *(const uint32_t*)(vp + 16);
                mma_bf16(o[0][nd], pa[0], vb);
                mma_bf16(o[1][nd], pa[1], vb);
            }
        }
    }

    // ---- finalize ----
#pragma unroll
    for (int i = 0; i < 4; i++) {
        lrow[i] += __shfl_xor_sync(0xffffffffu, lrow[i], 1);
        lrow[i] += __shfl_xor_sync(0xffffffffu, lrow[i], 2);
        lrow[i] = 1.0f / lrow[i];
    }
#pragma unroll
    for (int mt = 0; mt < 2; mt++) {
        const int rg = b * LL + qbase + warp * 32 + mt * 16 + g;
#pragma unroll
        for (int n = 0; n < 8; n++) {
            const size_t a0 = (size_t)rg * 1024 + h * 64 + n * 8 + 2 * l4;
            uint32_t p0, p1;
            PACK_BF16X2(p0, o[mt][n][0] * lrow[2*mt],   o[mt][n][1] * lrow[2*mt]);
            PACK_BF16X2(p1, o[mt][n][2] * lrow[2*mt+1], o[mt][n][3] * lrow[2*mt+1]);
            *(uint32_t*)((char*)og + a0 * 2)              = p0;
            *(uint32_t*)((char*)og + (a0 + 8 * 1024) * 2) = p1;
        }
    }
}

// ---------------------------------------------------------------------------
// Launch
// ---------------------------------------------------------------------------
extern "C" void kernel_launch(void* const* d_in, const int* in_sizes, int n_in,
                              void* d_out, int out_size) {
    const float* x     = (const float*)d_in[0];
    const float* gamma = (const float*)d_in[1];
    const float* beta  = (const float*)d_in[2];
    const float* Wq    = (const float*)d_in[3];
    const float* bq    = (const float*)d_in[4];
    const float* Wk    = (const float*)d_in[5];
    const float* bk    = (const float*)d_in[6];
    const float* Wv    = (const float*)d_in[7];
    const float* bv    = (const float*)d_in[8];
    const float* Wo    = (const float*)d_in[9];
    const float* bo    = (const float*)d_in[10];
    float* out = (float*)d_out;

    float* sc = nullptr;
    cudaGetSymbolAddress((void**)&sc, g_scratch);
    __nv_bfloat16* xn   = (__nv_bfloat16*)sc;
    __nv_bfloat16* qb   = (__nv_bfloat16*)(sc + 1 * (size_t)ELEMS);
    __nv_bfloat16* kb   = (__nv_bfloat16*)(sc + 2 * (size_t)ELEMS);
    __nv_bfloat16* vt   = (__nv_bfloat16*)(sc + 3 * (size_t)ELEMS);
    __nv_bfloat16* attn = (__nv_bfloat16*)(sc + 4 * (size_t)ELEMS);
    __nv_bfloat16* Wqt  = (__nv_bfloat16*)(sc + 5 * (size_t)ELEMS);  // contig x4
    __nv_bfloat16* Wkt  = Wqt + (size_t)WELEMS;
    __nv_bfloat16* Wvt  = Wkt + (size_t)WELEMS;
    __nv_bfloat16* Wot  = Wvt + (size_t)WELEMS;
    float2* rtab = (float2*)(sc + 5 * (size_t)ELEMS + 2 * (size_t)WELEMS);

    cudaFuncSetAttribute(attn_tc_kernel,
                         cudaFuncAttributeMaxDynamicSharedMemorySize, ASMEM);
    cudaFuncSetAttribute(qkv_gemm,
                         cudaFuncAttributeMaxDynamicSharedMemorySize, GSMEM);
    cudaFuncSetAttribute(o_gemm,
                         cudaFuncAttributeMaxDynamicSharedMemorySize, GSMEM);

    rope_table_kernel<<<65536 / 256, 256>>>(rtab);
    dim3 tgrid(32, 32), tblk(32, 8);
    cvtwt_kernel<<<tgrid, tblk>>>(Wq, Wqt);
    cvtwt_kernel<<<tgrid, tblk>>>(Wk, Wkt);
    cvtwt_kernel<<<tgrid, tblk>>>(Wv, Wvt);
    cvtwt_kernel<<<tgrid, tblk>>>(Wo, Wot);

    ln_kernel<<<MM, 256>>>(x, gamma, beta, xn);

    dim3 qkvgrid(24, 64);
    qkv_gemm<<<qkvgrid, 256, GSMEM>>>(xn, Wqt, bq, bk, bv, rtab, qb, kb, vt);

    dim3 agrid(LL / 128, BB * NH);
    attn_tc_kernel<<<agrid, 128, ASMEM>>>(qb, kb, vt, attn);

    dim3 ogrid(8, 64);
    o_gemm<<<ogrid, 256, GSMEM>>>(attn, Wot, bo, x, out);
}

// round 14
// speedup vs baseline: 2.3373x; 1.0339x over previous
#include <cuda_runtime.h>
#include <cuda_bf16.h>
#include <math.h>
#include <stdint.h>

// Problem constants
#define BB 4
#define LL 2048
#define DM 1024
#define NH 16
#define DH 64
#define MM (BB*LL)          // 8192 rows
#define ELEMS (MM*DM)       // 8388608
#define WELEMS (DM*DM)      // 1048576

// Scratch (float units): xn bf16 @0, q bf16 @1E, k bf16 @2E, vt bf16 @3E,
// attn bf16 @4E, weights bf16 @5E (2*WELEMS floats), rope table after.
__device__ float g_scratch[5 * (size_t)ELEMS + 4 * (size_t)WELEMS + 131072];

#define PACK_BF16X2(r, lo, hi) \
    asm("cvt.rn.bf16x2.f32 %0, %1, %2;" : "=r"(r) : "f"(hi), "f"(lo))
__device__ __forceinline__ uint32_t fau(float f) { return __float_as_uint(f); }
__device__ __forceinline__ float uaf(uint32_t u) { return __uint_as_float(u); }

__device__ __forceinline__ void mma_bf16(float c[4],
                                         const uint32_t a[4],
                                         const uint32_t b[2]) {
    asm volatile(
        "mma.sync.aligned.m16n8k16.row.col.f32.bf16.bf16.f32 "
        "{%0,%1,%2,%3}, {%4,%5,%6,%7}, {%8,%9}, {%0,%1,%2,%3};\n"
        : "+f"(c[0]), "+f"(c[1]), "+f"(c[2]), "+f"(c[3])
        : "r"(a[0]), "r"(a[1]), "r"(a[2]), "r"(a[3]),
          "r"(b[0]), "r"(b[1]));
}

#define CP_ASYNC16(dst, src) \
    asm volatile("cp.async.cg.shared.global [%0], [%1], 16;\n" \
                 :: "r"(dst), "l"(src) : "memory")
#define CP_ASYNC16_CA(dst, src) \
    asm volatile("cp.async.ca.shared.global [%0], [%1], 16;\n" \
                 :: "r"(dst), "l"(src) : "memory")
#define CP_COMMIT() asm volatile("cp.async.commit_group;\n" ::: "memory")
#define CP_WAIT1()  asm volatile("cp.async.wait_group 1;\n" ::: "memory")
#define CP_WAIT0()  asm volatile("cp.async.wait_group 0;\n" ::: "memory")

// ---------------------------------------------------------------------------
// Weight prep (merged): fp32 [k][n] -> bf16 transposed [n][k], 4 matrices
// ---------------------------------------------------------------------------
__global__ __launch_bounds__(256) void cvtwt4_kernel(const float* __restrict__ W0,
                                                     const float* __restrict__ W1,
                                                     const float* __restrict__ W2,
                                                     const float* __restrict__ W3,
                                                     __nv_bfloat16* __restrict__ dstc) {
    __shared__ float tile[32][33];
    const int tx = threadIdx.x, ty = threadIdx.y;
    const int bx = blockIdx.x, by = blockIdx.y, bz = blockIdx.z;
    const float* src = (bz == 0) ? W0 : (bz == 1) ? W1 : (bz == 2) ? W2 : W3;
    __nv_bfloat16* dst = dstc + (size_t)bz * WELEMS;
#pragma unroll
    for (int i = 0; i < 4; i++) {
        const int k = by * 32 + ty + i * 8;
        tile[ty + i * 8][tx] = src[(size_t)k * DM + bx * 32 + tx];
    }
    __syncthreads();
#pragma unroll
    for (int i = 0; i < 4; i++) {
        const int n = bx * 32 + ty + i * 8;
        dst[(size_t)n * DM + by * 32 + tx] = __float2bfloat16_rn(tile[tx][ty + i * 8]);
    }
}

// ---------------------------------------------------------------------------
// RoPE cos/sin table
// ---------------------------------------------------------------------------
__global__ __launch_bounds__(256) void rope_table_kernel(float2* __restrict__ t) {
    const int idx = blockIdx.x * 256 + threadIdx.x;   // 65536
    const int l = idx >> 5, p = idx & 31;
    const float inv = exp2f((float)p * (-2.0f / 64.0f) * 13.2877123795494f);
    float s, c;
    sincosf((float)l * inv, &s, &c);
    t[idx] = make_float2(c, s);
}

// ---------------------------------------------------------------------------
// LayerNorm -> bf16
// ---------------------------------------------------------------------------
__global__ __launch_bounds__(256) void ln_kernel(const float* __restrict__ x,
                                                 const float* __restrict__ gamma,
                                                 const float* __restrict__ beta,
                                                 __nv_bfloat16* __restrict__ xn) {
    const int row = blockIdx.x;
    const int t = threadIdx.x;
    const float4 v = ((const float4*)(x + (size_t)row * DM))[t];
    __shared__ float red[8];

    float s = v.x + v.y + v.z + v.w;
#pragma unroll
    for (int o = 16; o > 0; o >>= 1) s += __shfl_xor_sync(0xffffffffu, s, o);
    if ((t & 31) == 0) red[t >> 5] = s;
    __syncthreads();
    float mean = (red[0]+red[1]+red[2]+red[3]+red[4]+red[5]+red[6]+red[7]) * (1.0f/DM);

    float dx = v.x-mean, dy = v.y-mean, dz = v.z-mean, dw = v.w-mean;
    float q = dx*dx + dy*dy + dz*dz + dw*dw;
#pragma unroll
    for (int o = 16; o > 0; o >>= 1) q += __shfl_xor_sync(0xffffffffu, q, o);
    __syncthreads();
    if ((t & 31) == 0) red[t >> 5] = q;
    __syncthreads();
    float var = (red[0]+red[1]+red[2]+red[3]+red[4]+red[5]+red[6]+red[7]) * (1.0f/DM);
    float rs = rsqrtf(var + 1e-5f);

    const float4 g4 = ((const float4*)gamma)[t];
    const float4 b4 = ((const float4*)beta)[t];
    uint32_t p0, p1;
    PACK_BF16X2(p0, dx*rs*g4.x + b4.x, dy*rs*g4.y + b4.y);
    PACK_BF16X2(p1, dz*rs*g4.z + b4.z, dw*rs*g4.w + b4.w);
    *(uint2*)((char*)xn + ((size_t)row * DM + 4 * t) * 2) = make_uint2(p0, p1);
}

// ---------------------------------------------------------------------------
// bf16 GEMM core: 128x128x32 tile, 8 warps (2Mx4N), 3-stage cp.async.
// Smem: rows 80B stride (32 bf16 + pad); banks 20g+l4 conflict-free.
// Stage 10240B; A x3 @0, B x3 @30720. Total 61440B.
// ---------------------------------------------------------------------------
#define GSTG 10240
#define GB_BASE 30720
#define GSMEM 61440

struct GemmCore {
    int tid, lane, warp, warpM, warpN, g, l4;
    uint32_t smbase;
    char* smc;
    const __nv_bfloat16* Ab;
    const __nv_bfloat16* Bb;
    float acc[16][4];

    __device__ __forceinline__ void init(char* sm, const __nv_bfloat16* A_,
                                         const __nv_bfloat16* B_) {
        smc = sm;
        tid = threadIdx.x; lane = tid & 31; warp = tid >> 5;
        warpM = warp >> 2; warpN = warp & 3;
        g = lane >> 2; l4 = lane & 3;
        smbase = (uint32_t)__cvta_generic_to_shared(sm);
        Ab = A_; Bb = B_;
#pragma unroll
        for (int i = 0; i < 16; i++)
#pragma unroll
            for (int j = 0; j < 4; j++) acc[i][j] = 0.f;
    }

    __device__ __forceinline__ void issue(int stage, int k0) {
        const int row = tid >> 1;
        const int c2 = (tid & 1) * 2;
#pragma unroll
        for (int c = c2; c < c2 + 2; c++) {
            CP_ASYNC16(smbase + stage * GSTG + row * 80 + c * 16,
                       Ab + (size_t)row * 1024 + k0 + c * 8);
            CP_ASYNC16(smbase + GB_BASE + stage * GSTG + row * 80 + c * 16,
                       Bb + (size_t)row * 1024 + k0 + c * 8);
        }
    }

    __device__ __forceinline__ void compute(int stage) {
        const char* Ast = smc + stage * GSTG;
        const char* Bst = smc + GB_BASE + stage * GSTG;
#pragma unroll
        for (int kh = 0; kh < 2; kh++) {
            const int ko = kh * 32;
            uint32_t af[4][4];
            uint32_t bf[4][2];
#pragma unroll
            for (int i = 0; i < 4; i++) {
                const int m = warpM * 64 + i * 16 + g;
                af[i][0] = *(const uint32_t*)(Ast + m * 80 + ko + l4 * 4);
                af[i][1] = *(const uint32_t*)(Ast + (m + 8) * 80 + ko + l4 * 4);
                af[i][2] = *(const uint32_t*)(Ast + m * 80 + ko + 16 + l4 * 4);
                af[i][3] = *(const uint32_t*)(Ast + (m + 8) * 80 + ko + 16 + l4 * 4);
            }
#pragma unroll
            for (int j = 0; j < 4; j++) {
                const int n = warpN * 32 + j * 8 + g;
                bf[j][0] = *(const uint32_t*)(Bst + n * 80 + ko + l4 * 4);
                bf[j][1] = *(const uint32_t*)(Bst + n * 80 + ko + 16 + l4 * 4);
            }
#pragma unroll
            for (int i = 0; i < 4; i++)
#pragma unroll
                for (int j = 0; j < 4; j++)
                    mma_bf16(acc[i * 4 + j], af[i], bf[j]);
        }
    }

    __device__ __forceinline__ void mainloop() {
        issue(0, 0);  CP_COMMIT();
        issue(1, 32); CP_COMMIT();
        for (int kt = 0; kt < 32; kt++) {
            CP_WAIT1();
            __syncthreads();
            if (kt + 2 < 32) issue((kt + 2) % 3, (kt + 2) * 32);
            CP_COMMIT();
            compute(kt % 3);
        }
    }
};

// ---------------------------------------------------------------------------
// Merged QKV GEMM: outputs q,k bf16 [seq][1024] (roped, q scaled 1/8);
// v bf16 TRANSPOSED [bh][d][seq].
// ---------------------------------------------------------------------------
__global__ __launch_bounds__(256) void qkv_gemm(const __nv_bfloat16* __restrict__ xn,
                                                const __nv_bfloat16* __restrict__ Wcat,
                                                const float* __restrict__ bq,
                                                const float* __restrict__ bk,
                                                const float* __restrict__ bv,
                                                const float2* __restrict__ rtab,
                                                __nv_bfloat16* __restrict__ qb,
                                                __nv_bfloat16* __restrict__ kb,
                                                __nv_bfloat16* __restrict__ vt) {
    extern __shared__ char sm[];
    const int brow = blockIdx.y;
    const int bcol = blockIdx.x;
    const int tsel = bcol >> 3;          // 0=q 1=k 2=v
    const int bcl  = bcol & 7;

    GemmCore core;
    core.init(sm,
              xn + (size_t)brow * 128 * 1024,
              Wcat + (size_t)tsel * WELEMS + (size_t)bcl * 128 * 1024);
    core.mainloop();

    const float* bias = (tsel == 0) ? bq : (tsel == 1) ? bk : bv;
    const float oscale = (tsel == 0) ? 0.125f : 1.0f;

#pragma unroll
    for (int i = 0; i < 4; i++) {
        const int r0 = brow * 128 + core.warpM * 64 + i * 16 + core.g;
        const int l0 = r0 & (LL - 1);
        const int bidx = r0 >> 11;
#pragma unroll
        for (int j = 0; j < 4; j++) {
            const int cc = bcl * 128 + core.warpN * 32 + j * 8 + (core.l4 << 1);
            const float bx = bias[cc], by = bias[cc + 1];
            float v0x = core.acc[i * 4 + j][0] + bx;
            float v0y = core.acc[i * 4 + j][1] + by;
            float v1x = core.acc[i * 4 + j][2] + bx;
            float v1y = core.acc[i * 4 + j][3] + by;
            if (tsel < 2) {
                const int p = (cc & 63) >> 1;
                const float2 cs0 = rtab[l0 * 32 + p];
                const float2 cs1 = rtab[(l0 + 8) * 32 + p];
                float t;
                t   = v0x * cs0.x - v0y * cs0.y;
                v0y = v0x * cs0.y + v0y * cs0.x;
                v0x = t;
                t   = v1x * cs1.x - v1y * cs1.y;
                v1y = v1x * cs1.y + v1y * cs1.x;
                v1x = t;
                uint32_t p0, p1;
                PACK_BF16X2(p0, v0x * oscale, v0y * oscale);
                PACK_BF16X2(p1, v1x * oscale, v1y * oscale);
                __nv_bfloat16* C = (tsel == 0) ? qb : kb;
                *(uint32_t*)((char*)C + ((size_t)r0 * 1024 + cc) * 2)       = p0;
                *(uint32_t*)((char*)C + ((size_t)(r0 + 8) * 1024 + cc) * 2) = p1;
            } else {
                const int h = cc >> 6, d = cc & 63;
                __nv_bfloat16* row0 = vt + ((size_t)(bidx * 16 + h) * 64 + d) * LL;
                __nv_bfloat16* row1 = row0 + LL;
                row0[l0]     = __float2bfloat16_rn(v0x);
                row1[l0]     = __float2bfloat16_rn(v0y);
                row0[l0 + 8] = __float2bfloat16_rn(v1x);
                row1[l0 + 8] = __float2bfloat16_rn(v1y);
            }
        }
    }
}

// ---------------------------------------------------------------------------
// Output projection GEMM: out = attn(bf16) @ Wot^T + bo + x   (fp32 out)
// ---------------------------------------------------------------------------
__global__ __launch_bounds__(256) void o_gemm(const __nv_bfloat16* __restrict__ A,
                                              const __nv_bfloat16* __restrict__ Wt,
                                              const float* __restrict__ bias,
                                              const float* __restrict__ resid,
                                              float* __restrict__ C) {
    extern __shared__ char sm[];
    const int brow = blockIdx.y;
    const int bcol = blockIdx.x;

    GemmCore core;
    core.init(sm, A + (size_t)brow * 128 * 1024, Wt + (size_t)bcol * 128 * 1024);
    core.mainloop();

#pragma unroll
    for (int i = 0; i < 4; i++) {
        const int r0 = brow * 128 + core.warpM * 64 + i * 16 + core.g;
#pragma unroll
        for (int j = 0; j < 4; j++) {
            const int cc = bcol * 128 + core.warpN * 32 + j * 8 + (core.l4 << 1);
            const float bx = bias[cc], by = bias[cc + 1];
            const float2 r0v = *(const float2*)(resid + (size_t)r0 * 1024 + cc);
            const float2 r1v = *(const float2*)(resid + (size_t)(r0 + 8) * 1024 + cc);
            *(float2*)(C + (size_t)r0 * 1024 + cc) =
                make_float2(core.acc[i*4+j][0] + bx + r0v.x,
                            core.acc[i*4+j][1] + by + r0v.y);
            *(float2*)(C + (size_t)(r0 + 8) * 1024 + cc) =
                make_float2(core.acc[i*4+j][2] + bx + r1v.x,
                            core.acc[i*4+j][3] + by + r1v.y);
        }
    }
}

// ---------------------------------------------------------------------------
// bf16 flash attention (causal) — unchanged from R13 best.
// ---------------------------------------------------------------------------
#define QROW 144
#define KV_STG (64 * QROW)
#define SK_BASE 18432
#define SV_BASE (SK_BASE + 2 * KV_STG)
#define ASMEM (SV_BASE + 2 * KV_STG)   // 55296

__global__ __launch_bounds__(128) void attn_tc_kernel(const __nv_bfloat16* __restrict__ qg,
                                                      const __nv_bfloat16* __restrict__ kg,
                                                      const __nv_bfloat16* __restrict__ vt,
                                                      __nv_bfloat16* __restrict__ og) {
    extern __shared__ char sma[];
    const uint32_t smbase = (uint32_t)__cvta_generic_to_shared(sma);

    const int bh = blockIdx.y;
    const int b = bh >> 4, h = bh & 15;
    const int qt = (int)gridDim.x - 1 - (int)blockIdx.x;
    const int qbase = qt * 128;
    const int tid  = threadIdx.x;
    const int lane = tid & 31;
    const int warp = tid >> 5;
    const int g  = lane >> 2;
    const int l4 = lane & 3;

#pragma unroll
    for (int it = 0; it < 8; it++) {
        const int i = tid + it * 128;
        const int row = i >> 3, c = i & 7;
        CP_ASYNC16_CA(smbase + row * QROW + c * 16,
                      qg + (size_t)(b * LL + qbase + row) * 1024 + h * 64 + c * 8);
    }

    auto issueKV = [&](int t64, int st) {
#pragma unroll
        for (int it = 0; it < 4; it++) {
            const int i = tid + it * 128;
            const int row = i >> 3, c = i & 7;
            CP_ASYNC16_CA(smbase + SK_BASE + st * KV_STG + row * QROW + c * 16,
                          kg + (size_t)(b * LL + t64 * 64 + row) * 1024 + h * 64 + c * 8);
            CP_ASYNC16_CA(smbase + SV_BASE + st * KV_STG + row * QROW + c * 16,
                          vt + ((size_t)(bh * 64 + row)) * LL + t64 * 64 + c * 8);
        }
    };

    float s[2][8][4];
    float o[2][8][4];
#pragma unroll
    for (int mt = 0; mt < 2; mt++)
#pragma unroll
        for (int n = 0; n < 8; n++)
#pragma unroll
            for (int i = 0; i < 4; i++) o[mt][n][i] = 0.f;
    float mrow[4] = {-1e30f, -1e30f, -1e30f, -1e30f};
    float lrow[4] = {0.f, 0.f, 0.f, 0.f};

    const int ntiles = 2 * qt + 2;
    issueKV(0, 0);
    CP_COMMIT();

    for (int t64 = 0; t64 < ntiles; t64++) {
        const int st = t64 & 1;
        __syncthreads();
        if (t64 + 1 < ntiles) {
            issueKV(t64 + 1, st ^ 1);
            CP_COMMIT();
            CP_WAIT1();
        } else {
            CP_WAIT0();
        }
        __syncthreads();

        const char* Kst = sma + SK_BASE + st * KV_STG;
        const char* Vst = sma + SV_BASE + st * KV_STG;
        const int j0 = t64 * 64;

#pragma unroll
        for (int mt = 0; mt < 2; mt++)
#pragma unroll
            for (int n = 0; n < 8; n++)
#pragma unroll
                for (int i = 0; i < 4; i++) s[mt][n][i] = 0.f;

#pragma unroll
        for (int kk = 0; kk < 4; kk++) {
            uint32_t qa[2][4];
#pragma unroll
            for (int mt = 0; mt < 2; mt++) {
                const char* qp = sma + (warp * 32 + mt * 16 + g) * QROW + kk * 32 + l4 * 4;
                qa[mt][0] = *(const uint32_t*)(qp);
                qa[mt][1] = *(const uint32_t*)(qp + 8 * QROW);
                qa[mt][2] = *(const uint32_t*)(qp + 16);
                qa[mt][3] = *(const uint32_t*)(qp + 8 * QROW + 16);
            }
#pragma unroll
            for (int n = 0; n < 8; n++) {
                uint32_t kb[2];
                const char* kp = Kst + (n * 8 + g) * QROW + kk * 32 + l4 * 4;
                kb[0] = *(const uint32_t*)(kp);
                kb[1] = *(const uint32_t*)(kp + 16);
                mma_bf16(s[0][n], qa[0], kb);
                mma_bf16(s[1][n], qa[1], kb);
            }
        }

        if (t64 >= 2 * qt) {
#pragma unroll
            for (int mt = 0; mt < 2; mt++) {
                const int rg = qbase + warp * 32 + mt * 16 + g;
#pragma unroll
                for (int n = 0; n < 8; n++) {
                    const int c0 = j0 + n * 8 + 2 * l4;
                    if (c0     > rg)     s[mt][n][0] = -1e30f;
                    if (c0 + 1 > rg)     s[mt][n][1] = -1e30f;
                    if (c0     > rg + 8) s[mt][n][2] = -1e30f;
                    if (c0 + 1 > rg + 8) s[mt][n][3] = -1e30f;
                }
            }
        }

#pragma unroll
        for (int mt = 0; mt < 2; mt++) {
            float r0 = -1e30f, r1 = -1e30f;
#pragma unroll
            for (int n = 0; n < 8; n++) {
                r0 = fmaxf(r0, fmaxf(s[mt][n][0], s[mt][n][1]));
                r1 = fmaxf(r1, fmaxf(s[mt][n][2], s[mt][n][3]));
            }
            r0 = fmaxf(r0, __shfl_xor_sync(0xffffffffu, r0, 1));
            r0 = fmaxf(r0, __shfl_xor_sync(0xffffffffu, r0, 2));
            r1 = fmaxf(r1, __shfl_xor_sync(0xffffffffu, r1, 1));
            r1 = fmaxf(r1, __shfl_xor_sync(0xffffffffu, r1, 2));
            const float m0 = fmaxf(mrow[2*mt],   r0);
            const float m1 = fmaxf(mrow[2*mt+1], r1);
            const float c0 = __expf(mrow[2*mt]   - m0);
            const float c1 = __expf(mrow[2*mt+1] - m1);
            mrow[2*mt] = m0; mrow[2*mt+1] = m1;
            float ps0 = 0.f, ps1 = 0.f;
#pragma unroll
            for (int n = 0; n < 8; n++) {
                s[mt][n][0] = __expf(s[mt][n][0] - m0);
                s[mt][n][1] = __expf(s[mt][n][1] - m0);
                s[mt][n][2] = __expf(s[mt][n][2] - m1);
                s[mt][n][3] = __expf(s[mt][n][3] - m1);
                ps0 += s[mt][n][0] + s[mt][n][1];
                ps1 += s[mt][n][2] + s[mt][n][3];
                o[mt][n][0] *= c0; o[mt][n][1] *= c0;
                o[mt][n][2] *= c1; o[mt][n][3] *= c1;
            }
            lrow[2*mt]   = lrow[2*mt]   * c0 + ps0;
            lrow[2*mt+1] = lrow[2*mt+1] * c1 + ps1;
        }

#pragma unroll
        for (int kk = 0; kk < 4; kk++) {
            uint32_t pa[2][4];
#pragma unroll
            for (int mt = 0; mt < 2; mt++) {
                PACK_BF16X2(pa[mt][0], s[mt][2*kk][0],   s[mt][2*kk][1]);
                PACK_BF16X2(pa[mt][1], s[mt][2*kk][2],   s[mt][2*kk][3]);
                PACK_BF16X2(pa[mt][2], s[mt][2*kk+1][0], s[mt][2*kk+1][1]);
                PACK_BF16X2(pa[mt][3], s[mt][2*kk+1][2], s[mt][2*kk+1][3]);
            }
#pragma unroll
            for (int nd = 0; nd < 8; nd++) {
                uint32_t vb[2];
                const char* vp = Vst + (nd * 8 + g) * QROW + kk * 32 + l4 * 4;
                vb[0] = *(const uint32_t*)(vp);
                vb[1] = *(const uint32_t*)(vp + 16);
                mma_bf16(o[0][nd], pa[0], vb);
                mma_bf16(o[1][nd], pa[1], vb);
            }
        }
    }

#pragma unroll
    for (int i = 0; i < 4; i++) {
        lrow[i] += __shfl_xor_sync(0xffffffffu, lrow[i], 1);
        lrow[i] += __shfl_xor_sync(0xffffffffu, lrow[i], 2);
        lrow[i] = 1.0f / lrow[i];
    }
#pragma unroll
    for (int mt = 0; mt < 2; mt++) {
        const int rg = b * LL + qbase + warp * 32 + mt * 16 + g;
#pragma unroll
        for (int n = 0; n < 8; n++) {
            const size_t a0 = (size_t)rg * 1024 + h * 64 + n * 8 + 2 * l4;
            uint32_t p0, p1;
            PACK_BF16X2(p0, o[mt][n][0] * lrow[2*mt],   o[mt][n][1] * lrow[2*mt]);
            PACK_BF16X2(p1, o[mt][n][2] * lrow[2*mt+1], o[mt][n][3] * lrow[2*mt+1]);
            *(uint32_t*)((char*)og + a0 * 2)              = p0;
            *(uint32_t*)((char*)og + (a0 + 8 * 1024) * 2) = p1;
        }
    }
}

// ---------------------------------------------------------------------------
// Launch
// ---------------------------------------------------------------------------
extern "C" void kernel_launch(void* const* d_in, const int* in_sizes, int n_in,
                              void* d_out, int out_size) {
    const float* x     = (const float*)d_in[0];
    const float* gamma = (const float*)d_in[1];
    const float* beta  = (const float*)d_in[2];
    const float* Wq    = (const float*)d_in[3];
    const float* bq    = (const float*)d_in[4];
    const float* Wk    = (const float*)d_in[5];
    const float* bk    = (const float*)d_in[6];
    const float* Wv    = (const float*)d_in[7];
    const float* bv    = (const float*)d_in[8];
    const float* Wo    = (const float*)d_in[9];
    const float* bo    = (const float*)d_in[10];
    float* out = (float*)d_out;

    float* sc = nullptr;
    cudaGetSymbolAddress((void**)&sc, g_scratch);
    __nv_bfloat16* xn   = (__nv_bfloat16*)sc;
    __nv_bfloat16* qb   = (__nv_bfloat16*)(sc + 1 * (size_t)ELEMS);
    __nv_bfloat16* kb   = (__nv_bfloat16*)(sc + 2 * (size_t)ELEMS);
    __nv_bfloat16* vt   = (__nv_bfloat16*)(sc + 3 * (size_t)ELEMS);
    __nv_bfloat16* attn = (__nv_bfloat16*)(sc + 4 * (size_t)ELEMS);
    __nv_bfloat16* Wcat = (__nv_bfloat16*)(sc + 5 * (size_t)ELEMS);  // q,k,v,o
    __nv_bfloat16* Wot  = Wcat + 3 * (size_t)WELEMS;
    float2* rtab = (float2*)(sc + 5 * (size_t)ELEMS + 2 * (size_t)WELEMS);

    cudaFuncSetAttribute(attn_tc_kernel,
                         cudaFuncAttributeMaxDynamicSharedMemorySize, ASMEM);
    cudaFuncSetAttribute(qkv_gemm,
                         cudaFuncAttributeMaxDynamicSharedMemorySize, GSMEM);
    cudaFuncSetAttribute(o_gemm,
                         cudaFuncAttributeMaxDynamicSharedMemorySize, GSMEM);

    rope_table_kernel<<<65536 / 256, 256>>>(rtab);
    dim3 tgrid(32, 32, 4), tblk(32, 8);
    cvtwt4_kernel<<<tgrid, tblk>>>(Wq, Wk, Wv, Wo, Wcat);

    ln_kernel<<<MM, 256>>>(x, gamma, beta, xn);

    dim3 qkvgrid(24, 64);
    qkv_gemm<<<qkvgrid, 256, GSMEM>>>(xn, Wcat, bq, bk, bv, rtab, qb, kb, vt);

    dim3 agrid(LL / 128, BB * NH);
    attn_tc_kernel<<<agrid, 128, ASMEM>>>(qb, kb, vt, attn);

    dim3 ogrid(8, 64);
    o_gemm<<<ogrid, 256, GSMEM>>>(attn, Wot, bo, x, out);
}

// round 15
// speedup vs baseline: 2.5442x; 1.0885x over previous
#include <cuda_runtime.h>
#include <cuda_bf16.h>
#include <math.h>
#include <stdint.h>

// Problem constants
#define BB 4
#define LL 2048
#define DM 1024
#define NH 16
#define DH 64
#define MM (BB*LL)          // 8192 rows
#define ELEMS (MM*DM)       // 8388608
#define WELEMS (DM*DM)      // 1048576

// Scratch (float units): xn bf16 @0, q bf16 @1E, k bf16 @2E, vt bf16 @3E,
// attn bf16 @4E, weights bf16 @5E (2*WELEMS floats), rope table after.
__device__ float g_scratch[5 * (size_t)ELEMS + 4 * (size_t)WELEMS + 131072];

#define PACK_BF16X2(r, lo, hi) \
    asm("cvt.rn.bf16x2.f32 %0, %1, %2;" : "=r"(r) : "f"(hi), "f"(lo))
__device__ __forceinline__ uint32_t fau(float f) { return __float_as_uint(f); }
__device__ __forceinline__ float uaf(uint32_t u) { return __uint_as_float(u); }

__device__ __forceinline__ void mma_bf16(float c[4],
                                         const uint32_t a[4],
                                         const uint32_t b[2]) {
    asm volatile(
        "mma.sync.aligned.m16n8k16.row.col.f32.bf16.bf16.f32 "
        "{%0,%1,%2,%3}, {%4,%5,%6,%7}, {%8,%9}, {%0,%1,%2,%3};\n"
        : "+f"(c[0]), "+f"(c[1]), "+f"(c[2]), "+f"(c[3])
        : "r"(a[0]), "r"(a[1]), "r"(a[2]), "r"(a[3]),
          "r"(b[0]), "r"(b[1]));
}

__device__ __forceinline__ void ldmx4(uint32_t& r0, uint32_t& r1,
                                      uint32_t& r2, uint32_t& r3,
                                      uint32_t addr) {
    asm volatile("ldmatrix.sync.aligned.m8n8.x4.shared.b16 {%0,%1,%2,%3}, [%4];"
                 : "=r"(r0), "=r"(r1), "=r"(r2), "=r"(r3) : "r"(addr));
}

#define CP_ASYNC16(dst, src) \
    asm volatile("cp.async.cg.shared.global [%0], [%1], 16;\n" \
                 :: "r"(dst), "l"(src) : "memory")
#define CP_ASYNC16_CA(dst, src) \
    asm volatile("cp.async.ca.shared.global [%0], [%1], 16;\n" \
                 :: "r"(dst), "l"(src) : "memory")
#define CP_COMMIT() asm volatile("cp.async.commit_group;\n" ::: "memory")
#define CP_WAIT2()  asm volatile("cp.async.wait_group 2;\n" ::: "memory")
#define CP_WAIT1()  asm volatile("cp.async.wait_group 1;\n" ::: "memory")
#define CP_WAIT0()  asm volatile("cp.async.wait_group 0;\n" ::: "memory")

// ---------------------------------------------------------------------------
// Weight prep (merged): fp32 [k][n] -> bf16 transposed [n][k], 4 matrices
// ---------------------------------------------------------------------------
__global__ __launch_bounds__(256) void cvtwt4_kernel(const float* __restrict__ W0,
                                                     const float* __restrict__ W1,
                                                     const float* __restrict__ W2,
                                                     const float* __restrict__ W3,
                                                     __nv_bfloat16* __restrict__ dstc) {
    __shared__ float tile[32][33];
    const int tx = threadIdx.x, ty = threadIdx.y;
    const int bx = blockIdx.x, by = blockIdx.y, bz = blockIdx.z;
    const float* src = (bz == 0) ? W0 : (bz == 1) ? W1 : (bz == 2) ? W2 : W3;
    __nv_bfloat16* dst = dstc + (size_t)bz * WELEMS;
#pragma unroll
    for (int i = 0; i < 4; i++) {
        const int k = by * 32 + ty + i * 8;
        tile[ty + i * 8][tx] = src[(size_t)k * DM + bx * 32 + tx];
    }
    __syncthreads();
#pragma unroll
    for (int i = 0; i < 4; i++) {
        const int n = bx * 32 + ty + i * 8;
        dst[(size_t)n * DM + by * 32 + tx] = __float2bfloat16_rn(tile[tx][ty + i * 8]);
    }
}

// ---------------------------------------------------------------------------
// RoPE cos/sin table
// ---------------------------------------------------------------------------
__global__ __launch_bounds__(256) void rope_table_kernel(float2* __restrict__ t) {
    const int idx = blockIdx.x * 256 + threadIdx.x;   // 65536
    const int l = idx >> 5, p = idx & 31;
    const float inv = exp2f((float)p * (-2.0f / 64.0f) * 13.2877123795494f);
    float s, c;
    sincosf((float)l * inv, &s, &c);
    t[idx] = make_float2(c, s);
}

// ---------------------------------------------------------------------------
// LayerNorm -> bf16
// ---------------------------------------------------------------------------
__global__ __launch_bounds__(256) void ln_kernel(const float* __restrict__ x,
                                                 const float* __restrict__ gamma,
                                                 const float* __restrict__ beta,
                                                 __nv_bfloat16* __restrict__ xn) {
    const int row = blockIdx.x;
    const int t = threadIdx.x;
    const float4 v = ((const float4*)(x + (size_t)row * DM))[t];
    __shared__ float red[8];

    float s = v.x + v.y + v.z + v.w;
#pragma unroll
    for (int o = 16; o > 0; o >>= 1) s += __shfl_xor_sync(0xffffffffu, s, o);
    if ((t & 31) == 0) red[t >> 5] = s;
    __syncthreads();
    float mean = (red[0]+red[1]+red[2]+red[3]+red[4]+red[5]+red[6]+red[7]) * (1.0f/DM);

    float dx = v.x-mean, dy = v.y-mean, dz = v.z-mean, dw = v.w-mean;
    float q = dx*dx + dy*dy + dz*dz + dw*dw;
#pragma unroll
    for (int o = 16; o > 0; o >>= 1) q += __shfl_xor_sync(0xffffffffu, q, o);
    __syncthreads();
    if ((t & 31) == 0) red[t >> 5] = q;
    __syncthreads();
    float var = (red[0]+red[1]+red[2]+red[3]+red[4]+red[5]+red[6]+red[7]) * (1.0f/DM);
    float rs = rsqrtf(var + 1e-5f);

    const float4 g4 = ((const float4*)gamma)[t];
    const float4 b4 = ((const float4*)beta)[t];
    uint32_t p0, p1;
    PACK_BF16X2(p0, dx*rs*g4.x + b4.x, dy*rs*g4.y + b4.y);
    PACK_BF16X2(p1, dz*rs*g4.z + b4.z, dw*rs*g4.w + b4.w);
    *(uint2*)((char*)xn + ((size_t)row * DM + 4 * t) * 2) = make_uint2(p0, p1);
}

// ---------------------------------------------------------------------------
// bf16 GEMM core: 128x128x32 tile, 8 warps (2Mx4N), 4-stage cp.async,
// ldmatrix.x4 fragment loads. Rows 80B stride (conflict-free for LDS & LDSM).
// Stage 10240B; A x4 @0, B x4 @40960. Total 81920B.
// ---------------------------------------------------------------------------
#define GSTG 10240
#define GB_BASE 40960
#define GSMEM 81920

struct GemmCore {
    int tid, lane, warp, warpM, warpN, g, l4;
    uint32_t smbase;
    const __nv_bfloat16* Ab;
    const __nv_bfloat16* Bb;
    uint32_t aoff, boff;   // lane-dependent ldmatrix offsets (within stage)
    float acc[16][4];

    __device__ __forceinline__ void init(char* sm, const __nv_bfloat16* A_,
                                         const __nv_bfloat16* B_) {
        tid = threadIdx.x; lane = tid & 31; warp = tid >> 5;
        warpM = warp >> 2; warpN = warp & 3;
        g = lane >> 2; l4 = lane & 3;
        smbase = (uint32_t)__cvta_generic_to_shared(sm);
        Ab = A_; Bb = B_;
        // A: lanes 0-15 -> rows m0..15 (k-chunk 0), lanes 16-31 -> same rows +16B
        aoff = (uint32_t)(warpM * 64 + (lane & 15)) * 80 + (lane >> 4) * 16;
        // B: matrices (tile,k0),(tile,k8),(tile+1,k0),(tile+1,k8)
        boff = (uint32_t)(warpN * 32 + ((lane >> 4) << 3) + (lane & 7)) * 80
             + ((lane >> 3) & 1) * 16;
#pragma unroll
        for (int i = 0; i < 16; i++)
#pragma unroll
            for (int j = 0; j < 4; j++) acc[i][j] = 0.f;
    }

    __device__ __forceinline__ void issue(int stage, int k0) {
        const int row = tid >> 1;
        const int c2 = (tid & 1) * 2;
#pragma unroll
        for (int c = c2; c < c2 + 2; c++) {
            CP_ASYNC16(smbase + stage * GSTG + row * 80 + c * 16,
                       Ab + (size_t)row * 1024 + k0 + c * 8);
            CP_ASYNC16(smbase + GB_BASE + stage * GSTG + row * 80 + c * 16,
                       Bb + (size_t)row * 1024 + k0 + c * 8);
        }
    }

    __device__ __forceinline__ void compute(int stage) {
        const uint32_t Asb = smbase + stage * GSTG + aoff;
        const uint32_t Bsb = smbase + GB_BASE + stage * GSTG + boff;
#pragma unroll
        for (int kh = 0; kh < 2; kh++) {
            const int ko = kh * 32;
            uint32_t af[4][4];
            uint32_t bf[4][2];
#pragma unroll
            for (int i = 0; i < 4; i++)
                ldmx4(af[i][0], af[i][1], af[i][2], af[i][3],
                      Asb + i * (16 * 80) + ko);
#pragma unroll
            for (int jj = 0; jj < 2; jj++)
                ldmx4(bf[2*jj][0], bf[2*jj][1], bf[2*jj+1][0], bf[2*jj+1][1],
                      Bsb + jj * (16 * 80) + ko);
#pragma unroll
            for (int i = 0; i < 4; i++)
#pragma unroll
                for (int j = 0; j < 4; j++)
                    mma_bf16(acc[i * 4 + j], af[i], bf[j]);
        }
    }

    __device__ __forceinline__ void mainloop() {
        issue(0, 0);   CP_COMMIT();
        issue(1, 32);  CP_COMMIT();
        issue(2, 64);  CP_COMMIT();
        for (int kt = 0; kt < 32; kt++) {
            CP_WAIT2();
            __syncthreads();
            if (kt + 3 < 32) issue((kt + 3) & 3, (kt + 3) * 32);
            CP_COMMIT();
            compute(kt & 3);
        }
    }
};

// ---------------------------------------------------------------------------
// Merged QKV GEMM: outputs q,k bf16 [seq][1024] (roped, q scaled 1/8);
// v bf16 TRANSPOSED [bh][d][seq].
// ---------------------------------------------------------------------------
__global__ __launch_bounds__(256) void qkv_gemm(const __nv_bfloat16* __restrict__ xn,
                                                const __nv_bfloat16* __restrict__ Wcat,
                                                const float* __restrict__ bq,
                                                const float* __restrict__ bk,
                                                const float* __restrict__ bv,
                                                const float2* __restrict__ rtab,
                                                __nv_bfloat16* __restrict__ qb,
                                                __nv_bfloat16* __restrict__ kb,
                                                __nv_bfloat16* __restrict__ vt) {
    extern __shared__ char sm[];
    const int brow = blockIdx.y;
    const int bcol = blockIdx.x;
    const int tsel = bcol >> 3;          // 0=q 1=k 2=v
    const int bcl  = bcol & 7;

    GemmCore core;
    core.init(sm,
              xn + (size_t)brow * 128 * 1024,
              Wcat + (size_t)tsel * WELEMS + (size_t)bcl * 128 * 1024);
    core.mainloop();

    const float* bias = (tsel == 0) ? bq : (tsel == 1) ? bk : bv;
    const float oscale = (tsel == 0) ? 0.125f : 1.0f;

#pragma unroll
    for (int i = 0; i < 4; i++) {
        const int r0 = brow * 128 + core.warpM * 64 + i * 16 + core.g;
        const int l0 = r0 & (LL - 1);
        const int bidx = r0 >> 11;
#pragma unroll
        for (int j = 0; j < 4; j++) {
            const int cc = bcl * 128 + core.warpN * 32 + j * 8 + (core.l4 << 1);
            const float bx = bias[cc], by = bias[cc + 1];
            float v0x = core.acc[i * 4 + j][0] + bx;
            float v0y = core.acc[i * 4 + j][1] + by;
            float v1x = core.acc[i * 4 + j][2] + bx;
            float v1y = core.acc[i * 4 + j][3] + by;
            if (tsel < 2) {
                const int p = (cc & 63) >> 1;
                const float2 cs0 = rtab[l0 * 32 + p];
                const float2 cs1 = rtab[(l0 + 8) * 32 + p];
                float t;
                t   = v0x * cs0.x - v0y * cs0.y;
                v0y = v0x * cs0.y + v0y * cs0.x;
                v0x = t;
                t   = v1x * cs1.x - v1y * cs1.y;
                v1y = v1x * cs1.y + v1y * cs1.x;
                v1x = t;
                uint32_t p0, p1;
                PACK_BF16X2(p0, v0x * oscale, v0y * oscale);
                PACK_BF16X2(p1, v1x * oscale, v1y * oscale);
                __nv_bfloat16* C = (tsel == 0) ? qb : kb;
                *(uint32_t*)((char*)C + ((size_t)r0 * 1024 + cc) * 2)       = p0;
                *(uint32_t*)((char*)C + ((size_t)(r0 + 8) * 1024 + cc) * 2) = p1;
            } else {
                const int h = cc >> 6, d = cc & 63;
                __nv_bfloat16* row0 = vt + ((size_t)(bidx * 16 + h) * 64 + d) * LL;
                __nv_bfloat16* row1 = row0 + LL;
                row0[l0]     = __float2bfloat16_rn(v0x);
                row1[l0]     = __float2bfloat16_rn(v0y);
                row0[l0 + 8] = __float2bfloat16_rn(v1x);
                row1[l0 + 8] = __float2bfloat16_rn(v1y);
            }
        }
    }
}

// ---------------------------------------------------------------------------
// Output projection GEMM: out = attn(bf16) @ Wot^T + bo + x   (fp32 out)
// ---------------------------------------------------------------------------
__global__ __launch_bounds__(256) void o_gemm(const __nv_bfloat16* __restrict__ A,
                                              const __nv_bfloat16* __restrict__ Wt,
                                              const float* __restrict__ bias,
                                              const float* __restrict__ resid,
                                              float* __restrict__ C) {
    extern __shared__ char sm[];
    const int brow = blockIdx.y;
    const int bcol = blockIdx.x;

    GemmCore core;
    core.init(sm, A + (size_t)brow * 128 * 1024, Wt + (size_t)bcol * 128 * 1024);
    core.mainloop();

#pragma unroll
    for (int i = 0; i < 4; i++) {
        const int r0 = brow * 128 + core.warpM * 64 + i * 16 + core.g;
#pragma unroll
        for (int j = 0; j < 4; j++) {
            const int cc = bcol * 128 + core.warpN * 32 + j * 8 + (core.l4 << 1);
            const float bx = bias[cc], by = bias[cc + 1];
            const float2 r0v = *(const float2*)(resid + (size_t)r0 * 1024 + cc);
            const float2 r1v = *(const float2*)(resid + (size_t)(r0 + 8) * 1024 + cc);
            *(float2*)(C + (size_t)r0 * 1024 + cc) =
                make_float2(core.acc[i*4+j][0] + bx + r0v.x,
                            core.acc[i*4+j][1] + by + r0v.y);
            *(float2*)(C + (size_t)(r0 + 8) * 1024 + cc) =
                make_float2(core.acc[i*4+j][2] + bx + r1v.x,
                            core.acc[i*4+j][3] + by + r1v.y);
        }
    }
}

// ---------------------------------------------------------------------------
// bf16 flash attention (causal) — unchanged from R13/R14 best.
// ---------------------------------------------------------------------------
#define QROW 144
#define KV_STG (64 * QROW)
#define SK_BASE 18432
#define SV_BASE (SK_BASE + 2 * KV_STG)
#define ASMEM (SV_BASE + 2 * KV_STG)   // 55296

__global__ __launch_bounds__(128) void attn_tc_kernel(const __nv_bfloat16* __restrict__ qg,
                                                      const __nv_bfloat16* __restrict__ kg,
                                                      const __nv_bfloat16* __restrict__ vt,
                                                      __nv_bfloat16* __restrict__ og) {
    extern __shared__ char sma[];
    const uint32_t smbase = (uint32_t)__cvta_generic_to_shared(sma);

    const int bh = blockIdx.y;
    const int b = bh >> 4, h = bh & 15;
    const int qt = (int)gridDim.x - 1 - (int)blockIdx.x;
    const int qbase = qt * 128;
    const int tid  = threadIdx.x;
    const int lane = tid & 31;
    const int warp = tid >> 5;
    const int g  = lane >> 2;
    const int l4 = lane & 3;

#pragma unroll
    for (int it = 0; it < 8; it++) {
        const int i = tid + it * 128;
        const int row = i >> 3, c = i & 7;
        CP_ASYNC16_CA(smbase + row * QROW + c * 16,
                      qg + (size_t)(b * LL + qbase + row) * 1024 + h * 64 + c * 8);
    }

    auto issueKV = [&](int t64, int st) {
#pragma unroll
        for (int it = 0; it < 4; it++) {
            const int i = tid + it * 128;
            const int row = i >> 3, c = i & 7;
            CP_ASYNC16_CA(smbase + SK_BASE + st * KV_STG + row * QROW + c * 16,
                          kg + (size_t)(b * LL + t64 * 64 + row) * 1024 + h * 64 + c * 8);
            CP_ASYNC16_CA(smbase + SV_BASE + st * KV_STG + row * QROW + c * 16,
                          vt + ((size_t)(bh * 64 + row)) * LL + t64 * 64 + c * 8);
        }
    };

    float s[2][8][4];
    float o[2][8][4];
#pragma unroll
    for (int mt = 0; mt < 2; mt++)
#pragma unroll
        for (int n = 0; n < 8; n++)
#pragma unroll
            for (int i = 0; i < 4; i++) o[mt][n][i] = 0.f;
    float mrow[4] = {-1e30f, -1e30f, -1e30f, -1e30f};
    float lrow[4] = {0.f, 0.f, 0.f, 0.f};

    const int ntiles = 2 * qt + 2;
    issueKV(0, 0);
    CP_COMMIT();

    for (int t64 = 0; t64 < ntiles; t64++) {
        const int st = t64 & 1;
        __syncthreads();
        if (t64 + 1 < ntiles) {
            issueKV(t64 + 1, st ^ 1);
            CP_COMMIT();
            CP_WAIT1();
        } else {
            CP_WAIT0();
        }
        __syncthreads();

        const char* Kst = sma + SK_BASE + st * KV_STG;
        const char* Vst = sma + SV_BASE + st * KV_STG;
        const int j0 = t64 * 64;

#pragma unroll
        for (int mt = 0; mt < 2; mt++)
#pragma unroll
            for (int n = 0; n < 8; n++)
#pragma unroll
                for (int i = 0; i < 4; i++) s[mt][n][i] = 0.f;

#pragma unroll
        for (int kk = 0; kk < 4; kk++) {
            uint32_t qa[2][4];
#pragma unroll
            for (int mt = 0; mt < 2; mt++) {
                const char* qp = sma + (warp * 32 + mt * 16 + g) * QROW + kk * 32 + l4 * 4;
                qa[mt][0] = *(const uint32_t*)(qp);
                qa[mt][1] = *(const uint32_t*)(qp + 8 * QROW);
                qa[mt][2] = *(const uint32_t*)(qp + 16);
                qa[mt][3] = *(const uint32_t*)(qp + 8 * QROW + 16);
            }
#pragma unroll
            for (int n = 0; n < 8; n++) {
                uint32_t kb[2];
                const char* kp = Kst + (n * 8 + g) * QROW + kk * 32 + l4 * 4;
                kb[0] = *(const uint32_t*)(kp);
                kb[1] = *(const uint32_t*)(kp + 16);
                mma_bf16(s[0][n], qa[0], kb);
                mma_bf16(s[1][n], qa[1], kb);
            }
        }

        if (t64 >= 2 * qt) {
#pragma unroll
            for (int mt = 0; mt < 2; mt++) {
                const int rg = qbase + warp * 32 + mt * 16 + g;
#pragma unroll
                for (int n = 0; n < 8; n++) {
                    const int c0 = j0 + n * 8 + 2 * l4;
                    if (c0     > rg)     s[mt][n][0] = -1e30f;
                    if (c0 + 1 > rg)     s[mt][n][1] = -1e30f;
                    if (c0     > rg + 8) s[mt][n][2] = -1e30f;
                    if (c0 + 1 > rg + 8) s[mt][n][3] = -1e30f;
                }
            }
        }

#pragma unroll
        for (int mt = 0; mt < 2; mt++) {
            float r0 = -1e30f, r1 = -1e30f;
#pragma unroll
            for (int n = 0; n < 8; n++) {
                r0 = fmaxf(r0, fmaxf(s[mt][n][0], s[mt][n][1]));
                r1 = fmaxf(r1, fmaxf(s[mt][n][2], s[mt][n][3]));
            }
            r0 = fmaxf(r0, __shfl_xor_sync(0xffffffffu, r0, 1));
            r0 = fmaxf(r0, __shfl_xor_sync(0xffffffffu, r0, 2));
            r1 = fmaxf(r1, __shfl_xor_sync(0xffffffffu, r1, 1));
            r1 = fmaxf(r1, __shfl_xor_sync(0xffffffffu, r1, 2));
            const float m0 = fmaxf(mrow[2*mt],   r0);
            const float m1 = fmaxf(mrow[2*mt+1], r1);
            const float c0 = __expf(mrow[2*mt]   - m0);
            const float c1 = __expf(mrow[2*mt+1] - m1);
            mrow[2*mt] = m0; mrow[2*mt+1] = m1;
            float ps0 = 0.f, ps1 = 0.f;
#pragma unroll
            for (int n = 0; n < 8; n++) {
                s[mt][n][0] = __expf(s[mt][n][0] - m0);
                s[mt][n][1] = __expf(s[mt][n][1] - m0);
                s[mt][n][2] = __expf(s[mt][n][2] - m1);
                s[mt][n][3] = __expf(s[mt][n][3] - m1);
                ps0 += s[mt][n][0] + s[mt][n][1];
                ps1 += s[mt][n][2] + s[mt][n][3];
                o[mt][n][0] *= c0; o[mt][n][1] *= c0;
                o[mt][n][2] *= c1; o[mt][n][3] *= c1;
            }
            lrow[2*mt]   = lrow[2*mt]   * c0 + ps0;
            lrow[2*mt+1] = lrow[2*mt+1] * c1 + ps1;
        }

#pragma unroll
        for (int kk = 0; kk < 4; kk++) {
            uint32_t pa[2][4];
#pragma unroll
            for (int mt = 0; mt < 2; mt++) {
                PACK_BF16X2(pa[mt][0], s[mt][2*kk][0],   s[mt][2*kk][1]);
                PACK_BF16X2(pa[mt][1], s[mt][2*kk][2],   s[mt][2*kk][3]);
                PACK_BF16X2(pa[mt][2], s[mt][2*kk+1][0], s[mt][2*kk+1][1]);
                PACK_BF16X2(pa[mt][3], s[mt][2*kk+1][2], s[mt][2*kk+1][3]);
            }
#pragma unroll
            for (int nd = 0; nd < 8; nd++) {
                uint32_t vb[2];
                const char* vp = Vst + (nd * 8 + g) * QROW + kk * 32 + l4 * 4;
                vb[0] = *(const uint32_t*)(vp);
                vb[1] = *(const uint32_t*)(vp + 16);
                mma_bf16(o[0][nd], pa[0], vb);
                mma_bf16(o[1][nd], pa[1], vb);
            }
        }
    }

#pragma unroll
    for (int i = 0; i < 4; i++) {
        lrow[i] += __shfl_xor_sync(0xffffffffu, lrow[i], 1);
        lrow[i] += __shfl_xor_sync(0xffffffffu, lrow[i], 2);
        lrow[i] = 1.0f / lrow[i];
    }
#pragma unroll
    for (int mt = 0; mt < 2; mt++) {
        const int rg = b * LL + qbase + warp * 32 + mt * 16 + g;
#pragma unroll
        for (int n = 0; n < 8; n++) {
            const size_t a0 = (size_t)rg * 1024 + h * 64 + n * 8 + 2 * l4;
            uint32_t p0, p1;
            PACK_BF16X2(p0, o[mt][n][0] * lrow[2*mt],   o[mt][n][1] * lrow[2*mt]);
            PACK_BF16X2(p1, o[mt][n][2] * lrow[2*mt+1], o[mt][n][3] * lrow[2*mt+1]);
            *(uint32_t*)((char*)og + a0 * 2)              = p0;
            *(uint32_t*)((char*)og + (a0 + 8 * 1024) * 2) = p1;
        }
    }
}

// ---------------------------------------------------------------------------
// Launch
// ---------------------------------------------------------------------------
extern "C" void kernel_launch(void* const* d_in, const int* in_sizes, int n_in,
                              void* d_out, int out_size) {
    const float* x     = (const float*)d_in[0];
    const float* gamma = (const float*)d_in[1];
    const float* beta  = (const float*)d_in[2];
    const float* Wq    = (const float*)d_in[3];
    const float* bq    = (const float*)d_in[4];
    const float* Wk    = (const float*)d_in[5];
    const float* bk    = (const float*)d_in[6];
    const float* Wv    = (const float*)d_in[7];
    const float* bv    = (const float*)d_in[8];
    const float* Wo    = (const float*)d_in[9];
    const float* bo    = (const float*)d_in[10];
    float* out = (float*)d_out;

    float* sc = nullptr;
    cudaGetSymbolAddress((void**)&sc, g_scratch);
    __nv_bfloat16* xn   = (__nv_bfloat16*)sc;
    __nv_bfloat16* qb   = (__nv_bfloat16*)(sc + 1 * (size_t)ELEMS);
    __nv_bfloat16* kb   = (__nv_bfloat16*)(sc + 2 * (size_t)ELEMS);
    __nv_bfloat16* vt   = (__nv_bfloat16*)(sc + 3 * (size_t)ELEMS);
    __nv_bfloat16* attn = (__nv_bfloat16*)(sc + 4 * (size_t)ELEMS);
    __nv_bfloat16* Wcat = (__nv_bfloat16*)(sc + 5 * (size_t)ELEMS);  // q,k,v,o
    __nv_bfloat16* Wot  = Wcat + 3 * (size_t)WELEMS;
    float2* rtab = (float2*)(sc + 5 * (size_t)ELEMS + 2 * (size_t)WELEMS);

    cudaFuncSetAttribute(attn_tc_kernel,
                         cudaFuncAttributeMaxDynamicSharedMemorySize, ASMEM);
    cudaFuncSetAttribute(qkv_gemm,
                         cudaFuncAttributeMaxDynamicSharedMemorySize, GSMEM);
    cudaFuncSetAttribute(o_gemm,
                         cudaFuncAttributeMaxDynamicSharedMemorySize, GSMEM);

    rope_table_kernel<<<65536 / 256, 256>>>(rtab);
    dim3 tgrid(32, 32, 4), tblk(32, 8);
    cvtwt4_kernel<<<tgrid, tblk>>>(Wq, Wk, Wv, Wo, Wcat);

    ln_kernel<<<MM, 256>>>(x, gamma, beta, xn);

    dim3 qkvgrid(24, 64);
    qkv_gemm<<<qkvgrid, 256, GSMEM>>>(xn, Wcat, bq, bk, bv, rtab, qb, kb, vt);

    dim3 agrid(LL / 128, BB * NH);
    attn_tc_kernel<<<agrid, 128, ASMEM>>>(qb, kb, vt, attn);

    dim3 ogrid(8, 64);
    o_gemm<<<ogrid, 256, GSMEM>>>(attn, Wot, bo, x, out);
}

// round 16
// speedup vs baseline: 2.6955x; 1.0595x over previous
#include <cuda_runtime.h>
#include <cuda_bf16.h>
#include <math.h>
#include <stdint.h>

// Problem constants
#define BB 4
#define LL 2048
#define DM 1024
#define NH 16
#define DH 64
#define MM (BB*LL)          // 8192 rows
#define ELEMS (MM*DM)       // 8388608
#define WELEMS (DM*DM)      // 1048576

// Scratch (float units): xn bf16 @0, q bf16 @1E, k bf16 @2E, vt bf16 @3E,
// attn bf16 @4E, weights bf16 @5E (2*WELEMS floats), rope table after.
__device__ float g_scratch[5 * (size_t)ELEMS + 4 * (size_t)WELEMS + 131072];

#define PACK_BF16X2(r, lo, hi) \
    asm("cvt.rn.bf16x2.f32 %0, %1, %2;" : "=r"(r) : "f"(hi), "f"(lo))
__device__ __forceinline__ uint32_t fau(float f) { return __float_as_uint(f); }
__device__ __forceinline__ float uaf(uint32_t u) { return __uint_as_float(u); }

__device__ __forceinline__ void mma_bf16(float c[4],
                                         const uint32_t a[4],
                                         const uint32_t b[2]) {
    asm volatile(
        "mma.sync.aligned.m16n8k16.row.col.f32.bf16.bf16.f32 "
        "{%0,%1,%2,%3}, {%4,%5,%6,%7}, {%8,%9}, {%0,%1,%2,%3};\n"
        : "+f"(c[0]), "+f"(c[1]), "+f"(c[2]), "+f"(c[3])
        : "r"(a[0]), "r"(a[1]), "r"(a[2]), "r"(a[3]),
          "r"(b[0]), "r"(b[1]));
}

__device__ __forceinline__ void ldmx4(uint32_t& r0, uint32_t& r1,
                                      uint32_t& r2, uint32_t& r3,
                                      uint32_t addr) {
    asm volatile("ldmatrix.sync.aligned.m8n8.x4.shared.b16 {%0,%1,%2,%3}, [%4];"
                 : "=r"(r0), "=r"(r1), "=r"(r2), "=r"(r3) : "r"(addr));
}

#define CP_ASYNC16(dst, src) \
    asm volatile("cp.async.cg.shared.global [%0], [%1], 16;\n" \
                 :: "r"(dst), "l"(src) : "memory")
#define CP_ASYNC16_CA(dst, src) \
    asm volatile("cp.async.ca.shared.global [%0], [%1], 16;\n" \
                 :: "r"(dst), "l"(src) : "memory")
#define CP_COMMIT() asm volatile("cp.async.commit_group;\n" ::: "memory")
#define CP_WAIT2()  asm volatile("cp.async.wait_group 2;\n" ::: "memory")
#define CP_WAIT1()  asm volatile("cp.async.wait_group 1;\n" ::: "memory")
#define CP_WAIT0()  asm volatile("cp.async.wait_group 0;\n" ::: "memory")

// ---------------------------------------------------------------------------
// Weight prep (merged): fp32 [k][n] -> bf16 transposed [n][k], 4 matrices
// ---------------------------------------------------------------------------
__global__ __launch_bounds__(256) void cvtwt4_kernel(const float* __restrict__ W0,
                                                     const float* __restrict__ W1,
                                                     const float* __restrict__ W2,
                                                     const float* __restrict__ W3,
                                                     __nv_bfloat16* __restrict__ dstc) {
    __shared__ float tile[32][33];
    const int tx = threadIdx.x, ty = threadIdx.y;
    const int bx = blockIdx.x, by = blockIdx.y, bz = blockIdx.z;
    const float* src = (bz == 0) ? W0 : (bz == 1) ? W1 : (bz == 2) ? W2 : W3;
    __nv_bfloat16* dst = dstc + (size_t)bz * WELEMS;
#pragma unroll
    for (int i = 0; i < 4; i++) {
        const int k = by * 32 + ty + i * 8;
        tile[ty + i * 8][tx] = src[(size_t)k * DM + bx * 32 + tx];
    }
    __syncthreads();
#pragma unroll
    for (int i = 0; i < 4; i++) {
        const int n = bx * 32 + ty + i * 8;
        dst[(size_t)n * DM + by * 32 + tx] = __float2bfloat16_rn(tile[tx][ty + i * 8]);
    }
}

// ---------------------------------------------------------------------------
// RoPE cos/sin table
// ---------------------------------------------------------------------------
__global__ __launch_bounds__(256) void rope_table_kernel(float2* __restrict__ t) {
    const int idx = blockIdx.x * 256 + threadIdx.x;   // 65536
    const int l = idx >> 5, p = idx & 31;
    const float inv = exp2f((float)p * (-2.0f / 64.0f) * 13.2877123795494f);
    float s, c;
    sincosf((float)l * inv, &s, &c);
    t[idx] = make_float2(c, s);
}

// ---------------------------------------------------------------------------
// LayerNorm -> bf16
// ---------------------------------------------------------------------------
__global__ __launch_bounds__(256) void ln_kernel(const float* __restrict__ x,
                                                 const float* __restrict__ gamma,
                                                 const float* __restrict__ beta,
                                                 __nv_bfloat16* __restrict__ xn) {
    const int row = blockIdx.x;
    const int t = threadIdx.x;
    const float4 v = ((const float4*)(x + (size_t)row * DM))[t];
    __shared__ float red[8];

    float s = v.x + v.y + v.z + v.w;
#pragma unroll
    for (int o = 16; o > 0; o >>= 1) s += __shfl_xor_sync(0xffffffffu, s, o);
    if ((t & 31) == 0) red[t >> 5] = s;
    __syncthreads();
    float mean = (red[0]+red[1]+red[2]+red[3]+red[4]+red[5]+red[6]+red[7]) * (1.0f/DM);

    float dx = v.x-mean, dy = v.y-mean, dz = v.z-mean, dw = v.w-mean;
    float q = dx*dx + dy*dy + dz*dz + dw*dw;
#pragma unroll
    for (int o = 16; o > 0; o >>= 1) q += __shfl_xor_sync(0xffffffffu, q, o);
    __syncthreads();
    if ((t & 31) == 0) red[t >> 5] = q;
    __syncthreads();
    float var = (red[0]+red[1]+red[2]+red[3]+red[4]+red[5]+red[6]+red[7]) * (1.0f/DM);
    float rs = rsqrtf(var + 1e-5f);

    const float4 g4 = ((const float4*)gamma)[t];
    const float4 b4 = ((const float4*)beta)[t];
    uint32_t p0, p1;
    PACK_BF16X2(p0, dx*rs*g4.x + b4.x, dy*rs*g4.y + b4.y);
    PACK_BF16X2(p1, dz*rs*g4.z + b4.z, dw*rs*g4.w + b4.w);
    *(uint2*)((char*)xn + ((size_t)row * DM + 4 * t) * 2) = make_uint2(p0, p1);
}

// ---------------------------------------------------------------------------
// bf16 GEMM core: 128x128x32 tile, 8 warps (2Mx4N), 4-stage cp.async,
// ldmatrix.x4 with FULL fragment preload (both kh halves), then 64-mma burst.
// Rows 80B stride. Stage 10240B; A x4 @0, B x4 @40960. Total 81920B.
// ---------------------------------------------------------------------------
#define GSTG 10240
#define GB_BASE 40960
#define GSMEM 81920

struct GemmCore {
    int tid, lane, warp, warpM, warpN, g, l4;
    uint32_t smbase;
    const __nv_bfloat16* Ab;
    const __nv_bfloat16* Bb;
    uint32_t aoff, boff;
    float acc[16][4];

    __device__ __forceinline__ void init(char* sm, const __nv_bfloat16* A_,
                                         const __nv_bfloat16* B_) {
        tid = threadIdx.x; lane = tid & 31; warp = tid >> 5;
        warpM = warp >> 2; warpN = warp & 3;
        g = lane >> 2; l4 = lane & 3;
        smbase = (uint32_t)__cvta_generic_to_shared(sm);
        Ab = A_; Bb = B_;
        aoff = (uint32_t)(warpM * 64 + (lane & 15)) * 80 + (lane >> 4) * 16;
        boff = (uint32_t)(warpN * 32 + ((lane >> 4) << 3) + (lane & 7)) * 80
             + ((lane >> 3) & 1) * 16;
#pragma unroll
        for (int i = 0; i < 16; i++)
#pragma unroll
            for (int j = 0; j < 4; j++) acc[i][j] = 0.f;
    }

    __device__ __forceinline__ void issue(int stage, int k0) {
        const int row = tid >> 1;
        const int c2 = (tid & 1) * 2;
#pragma unroll
        for (int c = c2; c < c2 + 2; c++) {
            CP_ASYNC16(smbase + stage * GSTG + row * 80 + c * 16,
                       Ab + (size_t)row * 1024 + k0 + c * 8);
            CP_ASYNC16(smbase + GB_BASE + stage * GSTG + row * 80 + c * 16,
                       Bb + (size_t)row * 1024 + k0 + c * 8);
        }
    }

    __device__ __forceinline__ void compute(int stage) {
        const uint32_t Asb = smbase + stage * GSTG + aoff;
        const uint32_t Bsb = smbase + GB_BASE + stage * GSTG + boff;
        uint32_t af[2][4][4];
        uint32_t bf[2][4][2];
        // ---- preload ALL fragments for both kh halves ----
#pragma unroll
        for (int kh = 0; kh < 2; kh++) {
            const int ko = kh * 32;
#pragma unroll
            for (int i = 0; i < 4; i++)
                ldmx4(af[kh][i][0], af[kh][i][1], af[kh][i][2], af[kh][i][3],
                      Asb + i * (16 * 80) + ko);
#pragma unroll
            for (int jj = 0; jj < 2; jj++)
                ldmx4(bf[kh][2*jj][0], bf[kh][2*jj][1],
                      bf[kh][2*jj+1][0], bf[kh][2*jj+1][1],
                      Bsb + jj * (16 * 80) + ko);
        }
        // ---- 64 back-to-back mma ----
#pragma unroll
        for (int kh = 0; kh < 2; kh++)
#pragma unroll
            for (int i = 0; i < 4; i++)
#pragma unroll
                for (int j = 0; j < 4; j++)
                    mma_bf16(acc[i * 4 + j], af[kh][i], bf[kh][j]);
    }

    __device__ __forceinline__ void mainloop() {
        issue(0, 0);   CP_COMMIT();
        issue(1, 32);  CP_COMMIT();
        issue(2, 64);  CP_COMMIT();
        for (int kt = 0; kt < 32; kt++) {
            CP_WAIT2();
            __syncthreads();
            if (kt + 3 < 32) issue((kt + 3) & 3, (kt + 3) * 32);
            CP_COMMIT();
            compute(kt & 3);
        }
    }
};

// ---------------------------------------------------------------------------
// Merged QKV GEMM: outputs q,k bf16 [seq][1024] (roped, q scaled 1/8);
// v bf16 TRANSPOSED [bh][d][seq].
// ---------------------------------------------------------------------------
__global__ __launch_bounds__(256, 2) void qkv_gemm(const __nv_bfloat16* __restrict__ xn,
                                                   const __nv_bfloat16* __restrict__ Wcat,
                                                   const float* __restrict__ bq,
                                                   const float* __restrict__ bk,
                                                   const float* __restrict__ bv,
                                                   const float2* __restrict__ rtab,
                                                   __nv_bfloat16* __restrict__ qb,
                                                   __nv_bfloat16* __restrict__ kb,
                                                   __nv_bfloat16* __restrict__ vt) {
    extern __shared__ char sm[];
    const int brow = blockIdx.y;
    const int bcol = blockIdx.x;
    const int tsel = bcol >> 3;          // 0=q 1=k 2=v
    const int bcl  = bcol & 7;

    GemmCore core;
    core.init(sm,
              xn + (size_t)brow * 128 * 1024,
              Wcat + (size_t)tsel * WELEMS + (size_t)bcl * 128 * 1024);
    core.mainloop();

    const float* bias = (tsel == 0) ? bq : (tsel == 1) ? bk : bv;
    const float oscale = (tsel == 0) ? 0.125f : 1.0f;

#pragma unroll
    for (int i = 0; i < 4; i++) {
        const int r0 = brow * 128 + core.warpM * 64 + i * 16 + core.g;
        const int l0 = r0 & (LL - 1);
        const int bidx = r0 >> 11;
#pragma unroll
        for (int j = 0; j < 4; j++) {
            const int cc = bcl * 128 + core.warpN * 32 + j * 8 + (core.l4 << 1);
            const float bx = bias[cc], by = bias[cc + 1];
            float v0x = core.acc[i * 4 + j][0] + bx;
            float v0y = core.acc[i * 4 + j][1] + by;
            float v1x = core.acc[i * 4 + j][2] + bx;
            float v1y = core.acc[i * 4 + j][3] + by;
            if (tsel < 2) {
                const int p = (cc & 63) >> 1;
                const float2 cs0 = rtab[l0 * 32 + p];
                const float2 cs1 = rtab[(l0 + 8) * 32 + p];
                float t;
                t   = v0x * cs0.x - v0y * cs0.y;
                v0y = v0x * cs0.y + v0y * cs0.x;
                v0x = t;
                t   = v1x * cs1.x - v1y * cs1.y;
                v1y = v1x * cs1.y + v1y * cs1.x;
                v1x = t;
                uint32_t p0, p1;
                PACK_BF16X2(p0, v0x * oscale, v0y * oscale);
                PACK_BF16X2(p1, v1x * oscale, v1y * oscale);
                __nv_bfloat16* C = (tsel == 0) ? qb : kb;
                *(uint32_t*)((char*)C + ((size_t)r0 * 1024 + cc) * 2)       = p0;
                *(uint32_t*)((char*)C + ((size_t)(r0 + 8) * 1024 + cc) * 2) = p1;
            } else {
                const int h = cc >> 6, d = cc & 63;
                __nv_bfloat16* row0 = vt + ((size_t)(bidx * 16 + h) * 64 + d) * LL;
                __nv_bfloat16* row1 = row0 + LL;
                row0[l0]     = __float2bfloat16_rn(v0x);
                row1[l0]     = __float2bfloat16_rn(v0y);
                row0[l0 + 8] = __float2bfloat16_rn(v1x);
                row1[l0 + 8] = __float2bfloat16_rn(v1y);
            }
        }
    }
}

// ---------------------------------------------------------------------------
// Output projection GEMM: out = attn(bf16) @ Wot^T + bo + x   (fp32 out)
// ---------------------------------------------------------------------------
__global__ __launch_bounds__(256, 2) void o_gemm(const __nv_bfloat16* __restrict__ A,
                                                 const __nv_bfloat16* __restrict__ Wt,
                                                 const float* __restrict__ bias,
                                                 const float* __restrict__ resid,
                                                 float* __restrict__ C) {
    extern __shared__ char sm[];
    const int brow = blockIdx.y;
    const int bcol = blockIdx.x;

    GemmCore core;
    core.init(sm, A + (size_t)brow * 128 * 1024, Wt + (size_t)bcol * 128 * 1024);
    core.mainloop();

#pragma unroll
    for (int i = 0; i < 4; i++) {
        const int r0 = brow * 128 + core.warpM * 64 + i * 16 + core.g;
#pragma unroll
        for (int j = 0; j < 4; j++) {
            const int cc = bcol * 128 + core.warpN * 32 + j * 8 + (core.l4 << 1);
            const float bx = bias[cc], by = bias[cc + 1];
            const float2 r0v = *(const float2*)(resid + (size_t)r0 * 1024 + cc);
            const float2 r1v = *(const float2*)(resid + (size_t)(r0 + 8) * 1024 + cc);
            *(float2*)(C + (size_t)r0 * 1024 + cc) =
                make_float2(core.acc[i*4+j][0] + bx + r0v.x,
                            core.acc[i*4+j][1] + by + r0v.y);
            *(float2*)(C + (size_t)(r0 + 8) * 1024 + cc) =
                make_float2(core.acc[i*4+j][2] + bx + r1v.x,
                            core.acc[i*4+j][3] + by + r1v.y);
        }
    }
}

// ---------------------------------------------------------------------------
// bf16 flash attention (causal) — unchanged from R13/R14 best.
// ---------------------------------------------------------------------------
#define QROW 144
#define KV_STG (64 * QROW)
#define SK_BASE 18432
#define SV_BASE (SK_BASE + 2 * KV_STG)
#define ASMEM (SV_BASE + 2 * KV_STG)   // 55296

__global__ __launch_bounds__(128) void attn_tc_kernel(const __nv_bfloat16* __restrict__ qg,
                                                      const __nv_bfloat16* __restrict__ kg,
                                                      const __nv_bfloat16* __restrict__ vt,
                                                      __nv_bfloat16* __restrict__ og) {
    extern __shared__ char sma[];
    const uint32_t smbase = (uint32_t)__cvta_generic_to_shared(sma);

    const int bh = blockIdx.y;
    const int b = bh >> 4, h = bh & 15;
    const int qt = (int)gridDim.x - 1 - (int)blockIdx.x;
    const int qbase = qt * 128;
    const int tid  = threadIdx.x;
    const int lane = tid & 31;
    const int warp = tid >> 5;
    const int g  = lane >> 2;
    const int l4 = lane & 3;

#pragma unroll
    for (int it = 0; it < 8; it++) {
        const int i = tid + it * 128;
        const int row = i >> 3, c = i & 7;
        CP_ASYNC16_CA(smbase + row * QROW + c * 16,
                      qg + (size_t)(b * LL + qbase + row) * 1024 + h * 64 + c * 8);
    }

    auto issueKV = [&](int t64, int st) {
#pragma unroll
        for (int it = 0; it < 4; it++) {
            const int i = tid + it * 128;
            const int row = i >> 3, c = i & 7;
            CP_ASYNC16_CA(smbase + SK_BASE + st * KV_STG + row * QROW + c * 16,
                          kg + (size_t)(b * LL + t64 * 64 + row) * 1024 + h * 64 + c * 8);
            CP_ASYNC16_CA(smbase + SV_BASE + st * KV_STG + row * QROW + c * 16,
                          vt + ((size_t)(bh * 64 + row)) * LL + t64 * 64 + c * 8);
        }
    };

    float s[2][8][4];
    float o[2][8][4];
#pragma unroll
    for (int mt = 0; mt < 2; mt++)
#pragma unroll
        for (int n = 0; n < 8; n++)
#pragma unroll
            for (int i = 0; i < 4; i++) o[mt][n][i] = 0.f;
    float mrow[4] = {-1e30f, -1e30f, -1e30f, -1e30f};
    float lrow[4] = {0.f, 0.f, 0.f, 0.f};

    const int ntiles = 2 * qt + 2;
    issueKV(0, 0);
    CP_COMMIT();

    for (int t64 = 0; t64 < ntiles; t64++) {
        const int st = t64 & 1;
        __syncthreads();
        if (t64 + 1 < ntiles) {
            issueKV(t64 + 1, st ^ 1);
            CP_COMMIT();
            CP_WAIT1();
        } else {
            CP_WAIT0();
        }
        __syncthreads();

        const char* Kst = sma + SK_BASE + st * KV_STG;
        const char* Vst = sma + SV_BASE + st * KV_STG;
        const int j0 = t64 * 64;

#pragma unroll
        for (int mt = 0; mt < 2; mt++)
#pragma unroll
            for (int n = 0; n < 8; n++)
#pragma unroll
                for (int i = 0; i < 4; i++) s[mt][n][i] = 0.f;

#pragma unroll
        for (int kk = 0; kk < 4; kk++) {
            uint32_t qa[2][4];
#pragma unroll
            for (int mt = 0; mt < 2; mt++) {
                const char* qp = sma + (warp * 32 + mt * 16 + g) * QROW + kk * 32 + l4 * 4;
                qa[mt][0] = *(const uint32_t*)(qp);
                qa[mt][1] = *(const uint32_t*)(qp + 8 * QROW);
                qa[mt][2] = *(const uint32_t*)(qp + 16);
                qa[mt][3] = *(const uint32_t*)(qp + 8 * QROW + 16);
            }
#pragma unroll
            for (int n = 0; n < 8; n++) {
                uint32_t kb[2];
                const char* kp = Kst + (n * 8 + g) * QROW + kk * 32 + l4 * 4;
                kb[0] = *(const uint32_t*)(kp);
                kb[1] = *(const uint32_t*)(kp + 16);
                mma_bf16(s[0][n], qa[0], kb);
                mma_bf16(s[1][n], qa[1], kb);
            }
        }

        if (t64 >= 2 * qt) {
#pragma unroll
            for (int mt = 0; mt < 2; mt++) {
                const int rg = qbase + warp * 32 + mt * 16 + g;
#pragma unroll
                for (int n = 0; n < 8; n++) {
                    const int c0 = j0 + n * 8 + 2 * l4;
                    if (c0     > rg)     s[mt][n][0] = -1e30f;
                    if (c0 + 1 > rg)     s[mt][n][1] = -1e30f;
                    if (c0     > rg + 8) s[mt][n][2] = -1e30f;
                    if (c0 + 1 > rg + 8) s[mt][n][3] = -1e30f;
                }
            }
        }

#pragma unroll
        for (int mt = 0; mt < 2; mt++) {
            float r0 = -1e30f, r1 = -1e30f;
#pragma unroll
            for (int n = 0; n < 8; n++) {
                r0 = fmaxf(r0, fmaxf(s[mt][n][0], s[mt][n][1]));
                r1 = fmaxf(r1, fmaxf(s[mt][n][2], s[mt][n][3]));
            }
            r0 = fmaxf(r0, __shfl_xor_sync(0xffffffffu, r0, 1));
            r0 = fmaxf(r0, __shfl_xor_sync(0xffffffffu, r0, 2));
            r1 = fmaxf(r1, __shfl_xor_sync(0xffffffffu, r1, 1));
            r1 = fmaxf(r1, __shfl_xor_sync(0xffffffffu, r1, 2));
            const float m0 = fmaxf(mrow[2*mt],   r0);
            const float m1 = fmaxf(mrow[2*mt+1], r1);
            const float c0 = __expf(mrow[2*mt]   - m0);
            const float c1 = __expf(mrow[2*mt+1] - m1);
            mrow[2*mt] = m0; mrow[2*mt+1] = m1;
            float ps0 = 0.f, ps1 = 0.f;
#pragma unroll
            for (int n = 0; n < 8; n++) {
                s[mt][n][0] = __expf(s[mt][n][0] - m0);
                s[mt][n][1] = __expf(s[mt][n][1] - m0);
                s[mt][n][2] = __expf(s[mt][n][2] - m1);
                s[mt][n][3] = __expf(s[mt][n][3] - m1);
                ps0 += s[mt][n][0] + s[mt][n][1];
                ps1 += s[mt][n][2] + s[mt][n][3];
                o[mt][n][0] *= c0; o[mt][n][1] *= c0;
                o[mt][n][2] *= c1; o[mt][n][3] *= c1;
            }
            lrow[2*mt]   = lrow[2*mt]   * c0 + ps0;
            lrow[2*mt+1] = lrow[2*mt+1] * c1 + ps1;
        }

#pragma unroll
        for (int kk = 0; kk < 4; kk++) {
            uint32_t pa[2][4];
#pragma unroll
            for (int mt = 0; mt < 2; mt++) {
                PACK_BF16X2(pa[mt][0], s[mt][2*kk][0],   s[mt][2*kk][1]);
                PACK_BF16X2(pa[mt][1], s[mt][2*kk][2],   s[mt][2*kk][3]);
                PACK_BF16X2(pa[mt][2], s[mt][2*kk+1][0], s[mt][2*kk+1][1]);
                PACK_BF16X2(pa[mt][3], s[mt][2*kk+1][2], s[mt][2*kk+1][3]);
            }
#pragma unroll
            for (int nd = 0; nd < 8; nd++) {
                uint32_t vb[2];
                const char* vp = Vst + (nd * 8 + g) * QROW + kk * 32 + l4 * 4;
                vb[0] = *(const uint32_t*)(vp);
                vb[1] = *(const uint32_t*)(vp + 16);
                mma_bf16(o[0][nd], pa[0], vb);
                mma_bf16(o[1][nd], pa[1], vb);
            }
        }
    }

#pragma unroll
    for (int i = 0; i < 4; i++) {
        lrow[i] += __shfl_xor_sync(0xffffffffu, lrow[i], 1);
        lrow[i] += __shfl_xor_sync(0xffffffffu, lrow[i], 2);
        lrow[i] = 1.0f / lrow[i];
    }
#pragma unroll
    for (int mt = 0; mt < 2; mt++) {
        const int rg = b * LL + qbase + warp * 32 + mt * 16 + g;
#pragma unroll
        for (int n = 0; n < 8; n++) {
            const size_t a0 = (size_t)rg * 1024 + h * 64 + n * 8 + 2 * l4;
            uint32_t p0, p1;
            PACK_BF16X2(p0, o[mt][n][0] * lrow[2*mt],   o[mt][n][1] * lrow[2*mt]);
            PACK_BF16X2(p1, o[mt][n][2] * lrow[2*mt+1], o[mt][n][3] * lrow[2*mt+1]);
            *(uint32_t*)((char*)og + a0 * 2)              = p0;
            *(uint32_t*)((char*)og + (a0 + 8 * 1024) * 2) = p1;
        }
    }
}

// ---------------------------------------------------------------------------
// Launch
// ---------------------------------------------------------------------------
extern "C" void kernel_launch(void* const* d_in, const int* in_sizes, int n_in,
                              void* d_out, int out_size) {
    const float* x     = (const float*)d_in[0];
    const float* gamma = (const float*)d_in[1];
    const float* beta  = (const float*)d_in[2];
    const float* Wq    = (const float*)d_in[3];
    const float* bq    = (const float*)d_in[4];
    const float* Wk    = (const float*)d_in[5];
    const float* bk    = (const float*)d_in[6];
    const float* Wv    = (const float*)d_in[7];
    const float* bv    = (const float*)d_in[8];
    const float* Wo    = (const float*)d_in[9];
    const float* bo    = (const float*)d_in[10];
    float* out = (float*)d_out;

    float* sc = nullptr;
    cudaGetSymbolAddress((void**)&sc, g_scratch);
    __nv_bfloat16* xn   = (__nv_bfloat16*)sc;
    __nv_bfloat16* qb   = (__nv_bfloat16*)(sc + 1 * (size_t)ELEMS);
    __nv_bfloat16* kb   = (__nv_bfloat16*)(sc + 2 * (size_t)ELEMS);
    __nv_bfloat16* vt   = (__nv_bfloat16*)(sc + 3 * (size_t)ELEMS);
    __nv_bfloat16* attn = (__nv_bfloat16*)(sc + 4 * (size_t)ELEMS);
    __nv_bfloat16* Wcat = (__nv_bfloat16*)(sc + 5 * (size_t)ELEMS);  // q,k,v,o
    __nv_bfloat16* Wot  = Wcat + 3 * (size_t)WELEMS;
    float2* rtab = (float2*)(sc + 5 * (size_t)ELEMS + 2 * (size_t)WELEMS);

    cudaFuncSetAttribute(attn_tc_kernel,
                         cudaFuncAttributeMaxDynamicSharedMemorySize, ASMEM);
    cudaFuncSetAttribute(qkv_gemm,
                         cudaFuncAttributeMaxDynamicSharedMemorySize, GSMEM);
    cudaFuncSetAttribute(o_gemm,
                         cudaFuncAttributeMaxDynamicSharedMemorySize, GSMEM);

    rope_table_kernel<<<65536 / 256, 256>>>(rtab);
    dim3 tgrid(32, 32, 4), tblk(32, 8);
    cvtwt4_kernel<<<tgrid, tblk>>>(Wq, Wk, Wv, Wo, Wcat);

    ln_kernel<<<MM, 256>>>(x, gamma, beta, xn);

    dim3 qkvgrid(24, 64);
    qkv_gemm<<<qkvgrid, 256, GSMEM>>>(xn, Wcat, bq, bk, bv, rtab, qb, kb, vt);

    dim3 agrid(LL / 128, BB * NH);
    attn_tc_kernel<<<agrid, 128, ASMEM>>>(qb, kb, vt, attn);

    dim3 ogrid(8, 64);
    o_gemm<<<ogrid, 256, GSMEM>>>(attn, Wot, bo, x, out);
}